// round 6
// baseline (speedup 1.0000x reference)
#include <cuda_runtime.h>
#include <cuda_bf16.h>
#include <math.h>
#include <cstdint>

#define B_  2
#define T_  2048
#define E_  768
#define H_  12
#define D_  64
#define M_  (B_*T_)    // 4096
#define FF_ (4*E_)     // 3072
#define BH_ (B_*H_)    // 24
#define QKVN (3*E_)    // 2304

typedef __nv_bfloat16 bf16;

// ---------------- scratch ----------------
__device__ float g_x2[M_*E_];
__device__ bf16 g_h1h[M_*E_],  g_h1l[M_*E_];
__device__ bf16 g_qh[M_*E_],  g_ql[M_*E_];     // [B,H,T,D]
__device__ bf16 g_kh[M_*E_],  g_kl[M_*E_];     // [B,H,T,D]
__device__ bf16 g_vth[M_*E_], g_vtl[M_*E_];    // [B,H,D,T]
__device__ bf16 g_ctxh[M_*E_], g_ctxl[M_*E_];
__device__ bf16 g_h2h[M_*E_],  g_h2l[M_*E_];
__device__ bf16 g_midh[(size_t)M_*FF_], g_midl[(size_t)M_*FF_];
__device__ bf16 g_wqkvTh[(size_t)QKVN*E_], g_wqkvTl[(size_t)QKVN*E_];
__device__ bf16 g_woTh[E_*E_], g_woTl[E_*E_];
__device__ bf16 g_w1Th[(size_t)E_*FF_], g_w1Tl[(size_t)E_*FF_];
__device__ bf16 g_w2Th[(size_t)E_*FF_], g_w2Tl[(size_t)E_*FF_];

// ---------------- helpers ----------------
__device__ __forceinline__ uint32_t smem_u32(const void* p) {
    uint32_t a;
    asm("{ .reg .u64 t; cvta.to.shared.u64 t, %1; cvt.u32.u64 %0, t; }" : "=r"(a) : "l"(p));
    return a;
}
__device__ __forceinline__ void cpasync16(uint32_t dst, const void* src) {
    asm volatile("cp.async.ca.shared.global [%0], [%1], 16;" :: "r"(dst), "l"(src));
}
__device__ __forceinline__ void ldsm4(uint32_t* r, uint32_t addr) {
    asm volatile("ldmatrix.sync.aligned.m8n8.x4.shared.b16 {%0,%1,%2,%3}, [%4];"
        : "=r"(r[0]), "=r"(r[1]), "=r"(r[2]), "=r"(r[3]) : "r"(addr));
}
__device__ __forceinline__ void mma_bf16(float* c, const uint32_t* a, uint32_t b0, uint32_t b1) {
    asm volatile("mma.sync.aligned.m16n8k16.row.col.f32.bf16.bf16.f32 "
        "{%0,%1,%2,%3}, {%4,%5,%6,%7}, {%8,%9}, {%0,%1,%2,%3};"
        : "+f"(c[0]), "+f"(c[1]), "+f"(c[2]), "+f"(c[3])
        : "r"(a[0]), "r"(a[1]), "r"(a[2]), "r"(a[3]), "r"(b0), "r"(b1));
}
__device__ __forceinline__ void split_bf16(float v, bf16& h, bf16& l) {
    h = __float2bfloat16(v);
    l = __float2bfloat16(v - __bfloat162float(h));
}
__device__ __forceinline__ uint32_t packbf(float a, float b) {
    __nv_bfloat162 t = __floats2bfloat162_rn(a, b);
    return *(uint32_t*)&t;
}

// ---------------- weight transpose + split ----------------
__global__ void __launch_bounds__(256)
wsplitT(const float* __restrict__ w, bf16* __restrict__ hi, bf16* __restrict__ lo, int K, int N)
{
    __shared__ float t[32][33];
    const int tx = threadIdx.x & 31, ty = threadIdx.x >> 5;
    const int n0 = blockIdx.x * 32, k0 = blockIdx.y * 32;
    #pragma unroll
    for (int i = 0; i < 32; i += 8)
        t[ty + i][tx] = w[(size_t)(k0 + ty + i) * N + n0 + tx];
    __syncthreads();
    #pragma unroll
    for (int i = 0; i < 32; i += 8) {
        float v = t[tx][ty + i];
        bf16 h, l; split_bf16(v, h, l);
        size_t o = (size_t)(n0 + ty + i) * K + k0 + tx;
        hi[o] = h; lo[o] = l;
    }
}

// four E x E weights in one launch (z selects wq/wk/wv/wo)
__global__ void __launch_bounds__(256)
wsplitT4(const float* __restrict__ wqp, const float* __restrict__ wkp,
         const float* __restrict__ wvp, const float* __restrict__ wop,
         bf16* __restrict__ hqkv, bf16* __restrict__ lqkv,
         bf16* __restrict__ hwo, bf16* __restrict__ lwo)
{
    const int z = blockIdx.z;
    const float* w = (z == 0) ? wqp : (z == 1) ? wkp : (z == 2) ? wvp : wop;
    bf16* hi = (z < 3) ? hqkv + (size_t)z * E_ * E_ : hwo;
    bf16* lo = (z < 3) ? lqkv + (size_t)z * E_ * E_ : lwo;
    __shared__ float t[32][33];
    const int tx = threadIdx.x & 31, ty = threadIdx.x >> 5;
    const int n0 = blockIdx.x * 32, k0 = blockIdx.y * 32;
    #pragma unroll
    for (int i = 0; i < 32; i += 8)
        t[ty + i][tx] = w[(size_t)(k0 + ty + i) * E_ + n0 + tx];
    __syncthreads();
    #pragma unroll
    for (int i = 0; i < 32; i += 8) {
        float v = t[tx][ty + i];
        bf16 h, l; split_bf16(v, h, l);
        size_t o = (size_t)(n0 + ty + i) * E_ + k0 + tx;
        hi[o] = h; lo[o] = l;
    }
}

// ---------------- LayerNorm (ddof=1) -> bf16 hi/lo ----------------
__global__ void __launch_bounds__(256)
ln_kernel(const float* __restrict__ x, const float* __restrict__ sc,
          const float* __restrict__ sh, bf16* __restrict__ ohi, bf16* __restrict__ olo)
{
    int row = blockIdx.x;
    const float* xr = x + (size_t)row * E_;
    float s = 0.f, s2 = 0.f;
    for (int i = threadIdx.x; i < E_; i += 256) { float v = xr[i]; s += v; s2 += v * v; }
    __shared__ float rs[8], rs2[8];
    #pragma unroll
    for (int o = 16; o; o >>= 1) {
        s  += __shfl_xor_sync(0xffffffffu, s,  o);
        s2 += __shfl_xor_sync(0xffffffffu, s2, o);
    }
    if ((threadIdx.x & 31) == 0) { rs[threadIdx.x >> 5] = s; rs2[threadIdx.x >> 5] = s2; }
    __syncthreads();
    float ts = 0.f, ts2 = 0.f;
    #pragma unroll
    for (int i = 0; i < 8; i++) { ts += rs[i]; ts2 += rs2[i]; }
    float mean = ts * (1.f / E_);
    float var  = (ts2 - ts * mean) * (1.f / (E_ - 1));
    float rstd = rsqrtf(var + 1e-5f);
    for (int i = threadIdx.x; i < E_; i += 256) {
        float v = sc[i] * (xr[i] - mean) * rstd + sh[i];
        bf16 h, l; split_bf16(v, h, l);
        ohi[(size_t)row * E_ + i] = h;
        olo[(size_t)row * E_ + i] = l;
    }
}

// ---------------- warp-MMA GEMM: 3-stage cp.async pipeline ----------------
enum { EPI_QKV = 0, EPI_BIAS_RESID = 1, EPI_BIAS_GELU_SPLIT = 2 };

#define KCH     64
#define ROWB    144
#define TILE_B  (128*ROWB)      // 18432
#define STAGE_B (4*TILE_B)      // 73728
#define NSTG    3
#define GEMM_SMEM (NSTG*STAGE_B) // 221184
#define VROW    272
#define VPLANE  (128*VROW)      // 34816

template<int EPI>
__global__ void __launch_bounds__(256, 1)
mma_gemm(const bf16* __restrict__ Ahi, const bf16* __restrict__ Alo,
         const bf16* __restrict__ Bhi, const bf16* __restrict__ Blo,
         const float* __restrict__ bias, const float* __restrict__ resid,
         float* __restrict__ C,
         bf16* __restrict__ Qh, bf16* __restrict__ Ql,
         bf16* __restrict__ Kh, bf16* __restrict__ Kl,
         bf16* __restrict__ Vth, bf16* __restrict__ Vtl,
         bf16* __restrict__ Chi, bf16* __restrict__ Clo,
         int N, int K)
{
    extern __shared__ char sm[];
    const uint32_t sbase = smem_u32(sm);
    const int tid = threadIdx.x, wid = tid >> 5, lid = tid & 31;
    const int m0 = blockIdx.y * 128, n0 = blockIdx.x * 128;
    const int wm = wid >> 2, wn = wid & 3;

    const int lrow = tid >> 3;
    const int lcb  = (tid & 7) * 16;

    float acc[4][4][4] = {};

    const bf16* gs[4] = {Ahi, Alo, Bhi, Blo};
    const int   r0s[4] = {m0, m0, n0, n0};

    auto issue = [&](int c) {
        const int k0 = c * KCH;
        const uint32_t sb = sbase + (uint32_t)(c % NSTG) * STAGE_B;
        #pragma unroll
        for (int t = 0; t < 4; t++) {
            const char* g = (const char*)(gs[t] + (size_t)(r0s[t] + lrow) * K + k0) + lcb;
            uint32_t d = sb + t * TILE_B + lrow * ROWB + lcb;
            #pragma unroll
            for (int i = 0; i < 4; i++)
                cpasync16(d + i * 32 * ROWB, g + (size_t)i * 32 * K * 2);
        }
        asm volatile("cp.async.commit_group;");
    };

    const int NC = K / KCH;
    issue(0);
    issue(1);

    const int am = (lid >> 3);
    const uint32_t aRow = wm * 64 + (am & 1) * 8 + (lid & 7);
    const uint32_t aColH = (am >> 1) * 16;
    const uint32_t bRowBase = wn * 32 + (lid & 7);
    const uint32_t bNt = (am >> 1);
    const uint32_t bColH = (am & 1) * 16;

    for (int c = 0; c < NC; c++) {
        if (c + 2 < NC)      { issue(c + 2); asm volatile("cp.async.wait_group 2;"); }
        else if (c + 1 < NC) { asm volatile("cp.async.wait_group 1;"); }
        else                 { asm volatile("cp.async.wait_group 0;"); }
        __syncthreads();

        const uint32_t sb = sbase + (uint32_t)(c % NSTG) * STAGE_B;
        const uint32_t aHiB = sb,               aLoB = sb + TILE_B;
        const uint32_t bHiB = sb + 2 * TILE_B,  bLoB = sb + 3 * TILE_B;

        #pragma unroll
        for (int ks = 0; ks < 4; ks++) {
            uint32_t bh[2][4], bl[2][4];
            #pragma unroll
            for (int p = 0; p < 2; p++) {
                uint32_t row = bRowBase + (p * 2 + bNt) * 8;
                uint32_t off = row * ROWB + ks * 32 + bColH;
                ldsm4(bh[p], bHiB + off);
                ldsm4(bl[p], bLoB + off);
            }
            #pragma unroll
            for (int mt = 0; mt < 4; mt++) {
                uint32_t ah[4], al[4];
                uint32_t off = (aRow + mt * 16) * ROWB + ks * 32 + aColH;
                ldsm4(ah, aHiB + off);
                ldsm4(al, aLoB + off);
                #pragma unroll
                for (int nt = 0; nt < 4; nt++) {
                    const int p = nt >> 1, q = (nt & 1) * 2;
                    mma_bf16(acc[mt][nt], ah, bh[p][q], bh[p][q + 1]);
                    mma_bf16(acc[mt][nt], ah, bl[p][q], bl[p][q + 1]);
                    mma_bf16(acc[mt][nt], al, bh[p][q], bh[p][q + 1]);
                }
            }
        }
        __syncthreads();
    }

    const bool isV = (EPI == EPI_QKV) && (n0 >= 2 * E_);

    #pragma unroll
    for (int mt = 0; mt < 4; mt++) {
        #pragma unroll
        for (int nt = 0; nt < 4; nt++) {
            const int r0 = m0 + wm * 64 + mt * 16 + (lid >> 2);
            const int cc = n0 + wn * 32 + nt * 8 + (lid & 3) * 2;
            #pragma unroll
            for (int hh = 0; hh < 2; hh++) {
                const int r = r0 + hh * 8;
                float v0 = acc[mt][nt][hh * 2], v1 = acc[mt][nt][hh * 2 + 1];
                if (EPI == EPI_QKV) {
                    bf16 h0, l0, h1, l1;
                    split_bf16(v0, h0, l0);
                    split_bf16(v1, h1, l1);
                    if (isV) {
                        // stage transposed in smem (coalesced writeout below)
                        const int rl = r - m0;
                        const int cl = cc - n0;
                        *(bf16*)(sm + cl * VROW + rl * 2)             = h0;
                        *(bf16*)(sm + (cl + 1) * VROW + rl * 2)       = h1;
                        *(bf16*)(sm + VPLANE + cl * VROW + rl * 2)    = l0;
                        *(bf16*)(sm + VPLANE + (cl + 1) * VROW + rl * 2) = l1;
                    } else {
                        const int bb = r >> 11, tt = r & (T_ - 1);
                        int which = (cc >= E_) ? 1 : 0;
                        int nn = cc - which * E_;
                        int hx = nn >> 6, d = nn & 63;
                        size_t o = ((size_t)(bb * H_ + hx) * T_ + tt) * D_ + d;
                        bf16* dh = (which == 0) ? Qh : Kh;
                        bf16* dl = (which == 0) ? Ql : Kl;
                        *(__nv_bfloat162*)&dh[o] = __nv_bfloat162(h0, h1);
                        *(__nv_bfloat162*)&dl[o] = __nv_bfloat162(l0, l1);
                    }
                } else if (EPI == EPI_BIAS_RESID) {
                    size_t o = (size_t)r * N + cc;
                    float2 bs = *(const float2*)&bias[cc];
                    float2 rs = *(const float2*)&resid[o];
                    *(float2*)&C[o] = make_float2(v0 + bs.x + rs.x, v1 + bs.y + rs.y);
                } else {
                    size_t o = (size_t)r * N + cc;
                    float2 bs = *(const float2*)&bias[cc];
                    float vv[2] = {v0 + bs.x, v1 + bs.y};
                    bf16 ph[2], pl[2];
                    #pragma unroll
                    for (int j = 0; j < 2; j++) {
                        float v = vv[j];
                        float u = 0.7978845608028654f * (v + 0.044715f * v * v * v);
                        v = 0.5f * v * (1.f + tanhf(u));
                        split_bf16(v, ph[j], pl[j]);
                    }
                    *(__nv_bfloat162*)&Chi[o] = __nv_bfloat162(ph[0], ph[1]);
                    *(__nv_bfloat162*)&Clo[o] = __nv_bfloat162(pl[0], pl[1]);
                }
            }
        }
    }

    if (isV) {
        __syncthreads();
        const int bb = m0 >> 11, tt0 = m0 & (T_ - 1);
        const int nh = n0 - 2 * E_;
        #pragma unroll
        for (int it = 0; it < 16; it++) {
            const int R = it * 16 + (tid >> 4);       // 0..255
            const int plane = R >> 7, nl = R & 127;
            const int hx = (nh + nl) >> 6, d = (nh + nl) & 63;
            const uint4 v = *(const uint4*)(sm + plane * VPLANE + nl * VROW + (tid & 15) * 16);
            bf16* dst = plane ? Vtl : Vth;
            *(uint4*)&dst[((size_t)(bb * H_ + hx) * D_ + d) * T_ + tt0 + (tid & 15) * 8] = v;
        }
    }
}

// ---------------- tensor-core flash attention (unchanged from R5) ----------------
#define FROWK 144
#define FROWV 272
#define FQH   0
#define FQL   18432
#define FSTG0 36864
#define FSTGB 71680
#define FA2_SMEM (36864 + 2*FSTGB)   // 180224

__global__ void __launch_bounds__(256, 1)
flash_attn2(const bf16* __restrict__ Qh_g, const bf16* __restrict__ Ql_g,
            const bf16* __restrict__ Kh_g, const bf16* __restrict__ Kl_g,
            const bf16* __restrict__ Vth_g, const bf16* __restrict__ Vtl_g,
            bf16* __restrict__ ctxh, bf16* __restrict__ ctxl)
{
    extern __shared__ char sm[];
    const uint32_t sb = smem_u32(sm);
    const int tid = threadIdx.x, wid = tid >> 5, lid = tid & 31;
    const int bh = blockIdx.y;
    const int mtile = (gridDim.x - 1) - blockIdx.x;
    const int q0 = mtile * 128;

    const bf16* Qhb = Qh_g + (size_t)bh * T_ * D_;
    const bf16* Qlb = Ql_g + (size_t)bh * T_ * D_;
    const bf16* Khb = Kh_g + (size_t)bh * T_ * D_;
    const bf16* Klb = Kl_g + (size_t)bh * T_ * D_;
    const bf16* Vhb = Vth_g + (size_t)bh * D_ * T_;
    const bf16* Vlb = Vtl_g + (size_t)bh * D_ * T_;

    {
        const int row = tid >> 1, half = tid & 1;
        const char* gh = (const char*)(Qhb + (size_t)(q0 + row) * D_ + half * 32);
        const char* gl = (const char*)(Qlb + (size_t)(q0 + row) * D_ + half * 32);
        uint32_t dh = sb + FQH + row * FROWK + half * 64;
        uint32_t dl = sb + FQL + row * FROWK + half * 64;
        #pragma unroll
        for (int i = 0; i < 4; i++) { cpasync16(dh + i * 16, gh + i * 16); cpasync16(dl + i * 16, gl + i * 16); }
    }

    auto issueKV = [&](int stage, int kvt) {
        const int kv0 = kvt * 128;
        const uint32_t s0 = sb + FSTG0 + (uint32_t)stage * FSTGB;
        {
            const int row = tid >> 1, half = tid & 1;
            const char* gh = (const char*)(Khb + (size_t)(kv0 + row) * D_ + half * 32);
            const char* gl = (const char*)(Klb + (size_t)(kv0 + row) * D_ + half * 32);
            uint32_t dh = s0 + row * FROWK + half * 64;
            uint32_t dl = s0 + 18432 + row * FROWK + half * 64;
            #pragma unroll
            for (int i = 0; i < 4; i++) { cpasync16(dh + i * 16, gh + i * 16); cpasync16(dl + i * 16, gl + i * 16); }
        }
        {
            const int row = tid >> 2, qt = tid & 3;
            const char* gh = (const char*)(Vhb + (size_t)row * T_ + kv0 + qt * 32);
            const char* gl = (const char*)(Vlb + (size_t)row * T_ + kv0 + qt * 32);
            uint32_t dh = s0 + 36864 + row * FROWV + qt * 64;
            uint32_t dl = s0 + 54272 + row * FROWV + qt * 64;
            #pragma unroll
            for (int i = 0; i < 4; i++) { cpasync16(dh + i * 16, gh + i * 16); cpasync16(dl + i * 16, gl + i * 16); }
        }
        asm volatile("cp.async.commit_group;");
    };

    issueKV(0, 0);

    const int am = lid >> 3;
    uint32_t qhf[4][4], qlf[4][4];
    float m_[2] = {-1e30f, -1e30f}, l_[2] = {0.f, 0.f};
    float oacc[8][4] = {};

    const int r0g = q0 + wid * 16 + (lid >> 2);
    const int c0l = (lid & 3) * 2;

    for (int kt = 0; kt <= mtile; kt++) {
        if (kt + 1 <= mtile) { issueKV((kt + 1) & 1, kt + 1); asm volatile("cp.async.wait_group 1;"); }
        else                 { asm volatile("cp.async.wait_group 0;"); }
        __syncthreads();

        if (kt == 0) {
            const uint32_t rowq = wid * 16 + (am & 1) * 8 + (lid & 7);
            #pragma unroll
            for (int ks = 0; ks < 4; ks++) {
                uint32_t off = rowq * FROWK + ks * 32 + (am >> 1) * 16;
                ldsm4(qhf[ks], sb + FQH + off);
                ldsm4(qlf[ks], sb + FQL + off);
            }
        }

        const uint32_t stg = sb + FSTG0 + (uint32_t)(kt & 1) * FSTGB;

        float sacc[16][4] = {};
        #pragma unroll
        for (int ks = 0; ks < 4; ks++) {
            #pragma unroll
            for (int ntp = 0; ntp < 8; ntp++) {
                uint32_t kh4[4], kl4[4];
                uint32_t off = (uint32_t)(ntp * 16 + ((lid >> 4) * 8) + (lid & 7)) * FROWK
                             + ks * 32 + ((lid >> 3) & 1) * 16;
                ldsm4(kh4, stg + off);
                ldsm4(kl4, stg + 18432 + off);
                mma_bf16(sacc[2 * ntp],     qhf[ks], kh4[0], kh4[1]);
                mma_bf16(sacc[2 * ntp],     qhf[ks], kl4[0], kl4[1]);
                mma_bf16(sacc[2 * ntp],     qlf[ks], kh4[0], kh4[1]);
                mma_bf16(sacc[2 * ntp + 1], qhf[ks], kh4[2], kh4[3]);
                mma_bf16(sacc[2 * ntp + 1], qhf[ks], kl4[2], kl4[3]);
                mma_bf16(sacc[2 * ntp + 1], qlf[ks], kh4[2], kh4[3]);
            }
        }

        const bool diag = (kt == mtile);
        float mx0 = -1e30f, mx1 = -1e30f;
        #pragma unroll
        for (int nt = 0; nt < 16; nt++) {
            #pragma unroll
            for (int j = 0; j < 2; j++) {
                float s = sacc[nt][j] * 0.125f;
                if (diag && (kt * 128 + nt * 8 + c0l + j) > r0g) s = -1e30f;
                sacc[nt][j] = s; mx0 = fmaxf(mx0, s);
            }
            #pragma unroll
            for (int j = 2; j < 4; j++) {
                float s = sacc[nt][j] * 0.125f;
                if (diag && (kt * 128 + nt * 8 + c0l + j - 2) > r0g + 8) s = -1e30f;
                sacc[nt][j] = s; mx1 = fmaxf(mx1, s);
            }
        }
        #pragma unroll
        for (int o = 1; o < 4; o <<= 1) {
            mx0 = fmaxf(mx0, __shfl_xor_sync(0xffffffffu, mx0, o));
            mx1 = fmaxf(mx1, __shfl_xor_sync(0xffffffffu, mx1, o));
        }
        float mn0 = fmaxf(m_[0], mx0), mn1 = fmaxf(m_[1], mx1);
        float cr0 = __expf(m_[0] - mn0), cr1 = __expf(m_[1] - mn1);
        float sum0 = 0.f, sum1 = 0.f;
        #pragma unroll
        for (int nt = 0; nt < 16; nt++) {
            float p0 = __expf(sacc[nt][0] - mn0), p1 = __expf(sacc[nt][1] - mn0);
            float p2 = __expf(sacc[nt][2] - mn1), p3 = __expf(sacc[nt][3] - mn1);
            sacc[nt][0] = p0; sacc[nt][1] = p1; sacc[nt][2] = p2; sacc[nt][3] = p3;
            sum0 += p0 + p1; sum1 += p2 + p3;
        }
        #pragma unroll
        for (int o = 1; o < 4; o <<= 1) {
            sum0 += __shfl_xor_sync(0xffffffffu, sum0, o);
            sum1 += __shfl_xor_sync(0xffffffffu, sum1, o);
        }
        l_[0] = l_[0] * cr0 + sum0; l_[1] = l_[1] * cr1 + sum1;
        m_[0] = mn0; m_[1] = mn1;
        #pragma unroll
        for (int d = 0; d < 8; d++) {
            oacc[d][0] *= cr0; oacc[d][1] *= cr0;
            oacc[d][2] *= cr1; oacc[d][3] *= cr1;
        }

        #pragma unroll
        for (int kvt = 0; kvt < 8; kvt++) {
            float p00 = sacc[2 * kvt][0],     p01 = sacc[2 * kvt][1];
            float p02 = sacc[2 * kvt][2],     p03 = sacc[2 * kvt][3];
            float p10 = sacc[2 * kvt + 1][0], p11 = sacc[2 * kvt + 1][1];
            float p12 = sacc[2 * kvt + 1][2], p13 = sacc[2 * kvt + 1][3];
            uint32_t pa_h[4], pa_l[4];
            pa_h[0] = packbf(p00, p01); pa_h[1] = packbf(p02, p03);
            pa_h[2] = packbf(p10, p11); pa_h[3] = packbf(p12, p13);
            bf16 b;
            b = __float2bfloat16(p00); float r00 = p00 - __bfloat162float(b);
            b = __float2bfloat16(p01); float r01 = p01 - __bfloat162float(b);
            b = __float2bfloat16(p02); float r02 = p02 - __bfloat162float(b);
            b = __float2bfloat16(p03); float r03 = p03 - __bfloat162float(b);
            b = __float2bfloat16(p10); float r10 = p10 - __bfloat162float(b);
            b = __float2bfloat16(p11); float r11 = p11 - __bfloat162float(b);
            b = __float2bfloat16(p12); float r12 = p12 - __bfloat162float(b);
            b = __float2bfloat16(p13); float r13 = p13 - __bfloat162float(b);
            pa_l[0] = packbf(r00, r01); pa_l[1] = packbf(r02, r03);
            pa_l[2] = packbf(r10, r11); pa_l[3] = packbf(r12, r13);

            #pragma unroll
            for (int ntp = 0; ntp < 4; ntp++) {
                uint32_t vh4[4], vl4[4];
                uint32_t off = (uint32_t)(ntp * 16 + ((lid >> 4) * 8) + (lid & 7)) * FROWV
                             + kvt * 32 + ((lid >> 3) & 1) * 16;
                ldsm4(vh4, stg + 36864 + off);
                ldsm4(vl4, stg + 54272 + off);
                mma_bf16(oacc[2 * ntp],     pa_h, vh4[0], vh4[1]);
                mma_bf16(oacc[2 * ntp],     pa_h, vl4[0], vl4[1]);
                mma_bf16(oacc[2 * ntp],     pa_l, vh4[0], vh4[1]);
                mma_bf16(oacc[2 * ntp + 1], pa_h, vh4[2], vh4[3]);
                mma_bf16(oacc[2 * ntp + 1], pa_h, vl4[2], vl4[3]);
                mma_bf16(oacc[2 * ntp + 1], pa_l, vh4[2], vh4[3]);
            }
        }
        __syncthreads();
    }

    const int b = bh / H_, h = bh - b * H_;
    float inv0 = 1.f / l_[0], inv1 = 1.f / l_[1];
    #pragma unroll
    for (int nt = 0; nt < 8; nt++) {
        const int d = nt * 8 + c0l;
        {
            float v0 = oacc[nt][0] * inv0, v1 = oacc[nt][1] * inv0;
            bf16 h0, l0, h1, l1;
            split_bf16(v0, h0, l0); split_bf16(v1, h1, l1);
            size_t o = ((size_t)(b * T_ + r0g)) * E_ + h * D_ + d;
            *(__nv_bfloat162*)&ctxh[o] = __nv_bfloat162(h0, h1);
            *(__nv_bfloat162*)&ctxl[o] = __nv_bfloat162(l0, l1);
        }
        {
            float v0 = oacc[nt][2] * inv1, v1 = oacc[nt][3] * inv1;
            bf16 h0, l0, h1, l1;
            split_bf16(v0, h0, l0); split_bf16(v1, h1, l1);
            size_t o = ((size_t)(b * T_ + r0g + 8)) * E_ + h * D_ + d;
            *(__nv_bfloat162*)&ctxh[o] = __nv_bfloat162(h0, h1);
            *(__nv_bfloat162*)&ctxl[o] = __nv_bfloat162(l0, l1);
        }
    }
}

// ---------------- launch ----------------
extern "C" void kernel_launch(void* const* d_in, const int* in_sizes, int n_in,
                              void* d_out, int out_size)
{
    const float* x    = (const float*)d_in[0];
    const float* wq   = (const float*)d_in[1];
    const float* wk   = (const float*)d_in[2];
    const float* wv   = (const float*)d_in[3];
    const float* wo   = (const float*)d_in[4];
    const float* bo   = (const float*)d_in[5];
    const float* ln1s = (const float*)d_in[6];
    const float* ln1b = (const float*)d_in[7];
    const float* ln2s = (const float*)d_in[8];
    const float* ln2b = (const float*)d_in[9];
    const float* w1   = (const float*)d_in[10];
    const float* b1   = (const float*)d_in[11];
    const float* w2   = (const float*)d_in[12];
    const float* b2   = (const float*)d_in[13];
    float* out = (float*)d_out;

    float *x2;
    bf16 *h1h, *h1l, *qh, *ql, *kh, *kl, *vth, *vtl, *ctxh, *ctxl, *h2h, *h2l, *midh, *midl;
    bf16 *wqkvTh, *wqkvTl, *woTh, *woTl, *w1Th, *w1Tl, *w2Th, *w2Tl;
    cudaGetSymbolAddress((void**)&x2,  g_x2);
    cudaGetSymbolAddress((void**)&h1h, g_h1h);  cudaGetSymbolAddress((void**)&h1l, g_h1l);
    cudaGetSymbolAddress((void**)&qh,  g_qh);   cudaGetSymbolAddress((void**)&ql,  g_ql);
    cudaGetSymbolAddress((void**)&kh,  g_kh);   cudaGetSymbolAddress((void**)&kl,  g_kl);
    cudaGetSymbolAddress((void**)&vth, g_vth);  cudaGetSymbolAddress((void**)&vtl, g_vtl);
    cudaGetSymbolAddress((void**)&ctxh,g_ctxh); cudaGetSymbolAddress((void**)&ctxl,g_ctxl);
    cudaGetSymbolAddress((void**)&h2h, g_h2h);  cudaGetSymbolAddress((void**)&h2l, g_h2l);
    cudaGetSymbolAddress((void**)&midh,g_midh); cudaGetSymbolAddress((void**)&midl,g_midl);
    cudaGetSymbolAddress((void**)&wqkvTh,g_wqkvTh); cudaGetSymbolAddress((void**)&wqkvTl,g_wqkvTl);
    cudaGetSymbolAddress((void**)&woTh,g_woTh); cudaGetSymbolAddress((void**)&woTl,g_woTl);
    cudaGetSymbolAddress((void**)&w1Th,g_w1Th); cudaGetSymbolAddress((void**)&w1Tl,g_w1Tl);
    cudaGetSymbolAddress((void**)&w2Th,g_w2Th); cudaGetSymbolAddress((void**)&w2Tl,g_w2Tl);

    cudaFuncSetAttribute(flash_attn2, cudaFuncAttributeMaxDynamicSharedMemorySize, FA2_SMEM);
    cudaFuncSetAttribute(mma_gemm<EPI_QKV>,             cudaFuncAttributeMaxDynamicSharedMemorySize, GEMM_SMEM);
    cudaFuncSetAttribute(mma_gemm<EPI_BIAS_RESID>,      cudaFuncAttributeMaxDynamicSharedMemorySize, GEMM_SMEM);
    cudaFuncSetAttribute(mma_gemm<EPI_BIAS_GELU_SPLIT>, cudaFuncAttributeMaxDynamicSharedMemorySize, GEMM_SMEM);

    // weight transpose+split
    wsplitT4<<<dim3(E_/32, E_/32, 4), 256>>>(wq, wk, wv, wo, wqkvTh, wqkvTl, woTh, woTl);
    wsplitT<<<dim3(FF_/32, E_/32), 256>>>(w1, w1Th, w1Tl, E_, FF_);
    wsplitT<<<dim3(E_/32, FF_/32), 256>>>(w2, w2Th, w2Tl, FF_, E_);

    // LN1 -> h1 hi/lo
    ln_kernel<<<M_, 256>>>(x, ln1s, ln1b, h1h, h1l);

    // fused QKV -> Q/K hi/lo [BH,T,D], Vt hi/lo [BH,D,T]
    mma_gemm<EPI_QKV><<<dim3(QKVN/128, M_/128), 256, GEMM_SMEM>>>(
        h1h, h1l, wqkvTh, wqkvTl, nullptr, nullptr, nullptr,
        qh, ql, kh, kl, vth, vtl, nullptr, nullptr, QKVN, E_);

    // tensor-core flash attention -> ctx hi/lo
    flash_attn2<<<dim3(T_/128, BH_), 256, FA2_SMEM>>>(qh, ql, kh, kl, vth, vtl, ctxh, ctxl);

    // proj + bias + resid -> x2
    mma_gemm<EPI_BIAS_RESID><<<dim3(E_/128, M_/128), 256, GEMM_SMEM>>>(
        ctxh, ctxl, woTh, woTl, bo, x, x2,
        nullptr, nullptr, nullptr, nullptr, nullptr, nullptr, nullptr, nullptr, E_, E_);

    // LN2 -> h2 hi/lo
    ln_kernel<<<M_, 256>>>(x2, ln2s, ln2b, h2h, h2l);

    // MLP1 (gelu) -> mid hi/lo
    mma_gemm<EPI_BIAS_GELU_SPLIT><<<dim3(FF_/128, M_/128), 256, GEMM_SMEM>>>(
        h2h, h2l, w1Th, w1Tl, b1, nullptr, nullptr,
        nullptr, nullptr, nullptr, nullptr, nullptr, nullptr, midh, midl, FF_, E_);

    // MLP2 + bias + resid -> out
    mma_gemm<EPI_BIAS_RESID><<<dim3(E_/128, M_/128), 256, GEMM_SMEM>>>(
        midh, midl, w2Th, w2Tl, b2, x2, out,
        nullptr, nullptr, nullptr, nullptr, nullptr, nullptr, nullptr, nullptr, E_, FF_);
}

// round 7
// speedup vs baseline: 1.0327x; 1.0327x over previous
#include <cuda_runtime.h>
#include <cuda_bf16.h>
#include <math.h>
#include <cstdint>

#define B_  2
#define T_  2048
#define E_  768
#define H_  12
#define D_  64
#define M_  (B_*T_)    // 4096
#define FF_ (4*E_)     // 3072
#define BH_ (B_*H_)    // 24
#define QKVN (3*E_)    // 2304

typedef __nv_bfloat16 bf16;

// ---------------- scratch ----------------
__device__ float g_x2[M_*E_];
__device__ bf16 g_h1h[M_*E_],  g_h1l[M_*E_];
__device__ bf16 g_qh[M_*E_],  g_ql[M_*E_];     // [B,H,T,D]
__device__ bf16 g_kh[M_*E_],  g_kl[M_*E_];     // [B,H,T,D]
__device__ bf16 g_vth[M_*E_], g_vtl[M_*E_];    // [B,H,D,T]
__device__ bf16 g_ctxh[M_*E_], g_ctxl[M_*E_];
__device__ bf16 g_h2h[M_*E_],  g_h2l[M_*E_];
__device__ bf16 g_midh[(size_t)M_*FF_], g_midl[(size_t)M_*FF_];
__device__ bf16 g_wqkvTh[(size_t)QKVN*E_], g_wqkvTl[(size_t)QKVN*E_];
__device__ bf16 g_woTh[E_*E_], g_woTl[E_*E_];
__device__ bf16 g_w1Th[(size_t)E_*FF_], g_w1Tl[(size_t)E_*FF_];
__device__ bf16 g_w2Th[(size_t)E_*FF_], g_w2Tl[(size_t)E_*FF_];

// ---------------- helpers ----------------
__device__ __forceinline__ uint32_t smem_u32(const void* p) {
    uint32_t a;
    asm("{ .reg .u64 t; cvta.to.shared.u64 t, %1; cvt.u32.u64 %0, t; }" : "=r"(a) : "l"(p));
    return a;
}
__device__ __forceinline__ void cpasync16(uint32_t dst, const void* src) {
    asm volatile("cp.async.ca.shared.global [%0], [%1], 16;" :: "r"(dst), "l"(src));
}
__device__ __forceinline__ void ldsm4(uint32_t* r, uint32_t addr) {
    asm volatile("ldmatrix.sync.aligned.m8n8.x4.shared.b16 {%0,%1,%2,%3}, [%4];"
        : "=r"(r[0]), "=r"(r[1]), "=r"(r[2]), "=r"(r[3]) : "r"(addr));
}
__device__ __forceinline__ void mma_bf16(float* c, const uint32_t* a, uint32_t b0, uint32_t b1) {
    asm volatile("mma.sync.aligned.m16n8k16.row.col.f32.bf16.bf16.f32 "
        "{%0,%1,%2,%3}, {%4,%5,%6,%7}, {%8,%9}, {%0,%1,%2,%3};"
        : "+f"(c[0]), "+f"(c[1]), "+f"(c[2]), "+f"(c[3])
        : "r"(a[0]), "r"(a[1]), "r"(a[2]), "r"(a[3]), "r"(b0), "r"(b1));
}
__device__ __forceinline__ void split_bf16(float v, bf16& h, bf16& l) {
    h = __float2bfloat16(v);
    l = __float2bfloat16(v - __bfloat162float(h));
}
__device__ __forceinline__ uint32_t packbf(float a, float b) {
    __nv_bfloat162 t = __floats2bfloat162_rn(a, b);
    return *(uint32_t*)&t;
}

// ---------------- weight transpose + split ----------------
__global__ void __launch_bounds__(256)
wsplitT(const float* __restrict__ w, bf16* __restrict__ hi, bf16* __restrict__ lo, int K, int N)
{
    __shared__ float t[32][33];
    const int tx = threadIdx.x & 31, ty = threadIdx.x >> 5;
    const int n0 = blockIdx.x * 32, k0 = blockIdx.y * 32;
    #pragma unroll
    for (int i = 0; i < 32; i += 8)
        t[ty + i][tx] = w[(size_t)(k0 + ty + i) * N + n0 + tx];
    __syncthreads();
    #pragma unroll
    for (int i = 0; i < 32; i += 8) {
        float v = t[tx][ty + i];
        bf16 h, l; split_bf16(v, h, l);
        size_t o = (size_t)(n0 + ty + i) * K + k0 + tx;
        hi[o] = h; lo[o] = l;
    }
}

__global__ void __launch_bounds__(256)
wsplitT4(const float* __restrict__ wqp, const float* __restrict__ wkp,
         const float* __restrict__ wvp, const float* __restrict__ wop,
         bf16* __restrict__ hqkv, bf16* __restrict__ lqkv,
         bf16* __restrict__ hwo, bf16* __restrict__ lwo)
{
    const int z = blockIdx.z;
    const float* w = (z == 0) ? wqp : (z == 1) ? wkp : (z == 2) ? wvp : wop;
    bf16* hi = (z < 3) ? hqkv + (size_t)z * E_ * E_ : hwo;
    bf16* lo = (z < 3) ? lqkv + (size_t)z * E_ * E_ : lwo;
    __shared__ float t[32][33];
    const int tx = threadIdx.x & 31, ty = threadIdx.x >> 5;
    const int n0 = blockIdx.x * 32, k0 = blockIdx.y * 32;
    #pragma unroll
    for (int i = 0; i < 32; i += 8)
        t[ty + i][tx] = w[(size_t)(k0 + ty + i) * E_ + n0 + tx];
    __syncthreads();
    #pragma unroll
    for (int i = 0; i < 32; i += 8) {
        float v = t[tx][ty + i];
        bf16 h, l; split_bf16(v, h, l);
        size_t o = (size_t)(n0 + ty + i) * E_ + k0 + tx;
        hi[o] = h; lo[o] = l;
    }
}

// ---------------- LayerNorm (ddof=1) -> bf16 hi/lo ----------------
__global__ void __launch_bounds__(256)
ln_kernel(const float* __restrict__ x, const float* __restrict__ sc,
          const float* __restrict__ sh, bf16* __restrict__ ohi, bf16* __restrict__ olo)
{
    int row = blockIdx.x;
    const float* xr = x + (size_t)row * E_;
    float s = 0.f, s2 = 0.f;
    for (int i = threadIdx.x; i < E_; i += 256) { float v = xr[i]; s += v; s2 += v * v; }
    __shared__ float rs[8], rs2[8];
    #pragma unroll
    for (int o = 16; o; o >>= 1) {
        s  += __shfl_xor_sync(0xffffffffu, s,  o);
        s2 += __shfl_xor_sync(0xffffffffu, s2, o);
    }
    if ((threadIdx.x & 31) == 0) { rs[threadIdx.x >> 5] = s; rs2[threadIdx.x >> 5] = s2; }
    __syncthreads();
    float ts = 0.f, ts2 = 0.f;
    #pragma unroll
    for (int i = 0; i < 8; i++) { ts += rs[i]; ts2 += rs2[i]; }
    float mean = ts * (1.f / E_);
    float var  = (ts2 - ts * mean) * (1.f / (E_ - 1));
    float rstd = rsqrtf(var + 1e-5f);
    for (int i = threadIdx.x; i < E_; i += 256) {
        float v = sc[i] * (xr[i] - mean) * rstd + sh[i];
        bf16 h, l; split_bf16(v, h, l);
        ohi[(size_t)row * E_ + i] = h;
        olo[(size_t)row * E_ + i] = l;
    }
}

// ---------------- warp-MMA GEMM: 512 threads, 2-stage cp.async ----------------
enum { EPI_QKV = 0, EPI_BIAS_RESID = 1, EPI_BIAS_GELU_SPLIT = 2 };

#define KCH     64
#define ROWB    144
#define TILE_B  (128*ROWB)      // 18432
#define STAGE_B (4*TILE_B)      // 73728
#define GEMM_SMEM (2*STAGE_B)   // 147456
#define VROW    272
#define VPLANE  (128*VROW)      // 34816
#define GT      512

template<int EPI>
__global__ void __launch_bounds__(GT, 1)
mma_gemm(const bf16* __restrict__ Ahi, const bf16* __restrict__ Alo,
         const bf16* __restrict__ Bhi, const bf16* __restrict__ Blo,
         const float* __restrict__ bias, const float* __restrict__ resid,
         float* __restrict__ C,
         bf16* __restrict__ Qh, bf16* __restrict__ Ql,
         bf16* __restrict__ Kh, bf16* __restrict__ Kl,
         bf16* __restrict__ Vth, bf16* __restrict__ Vtl,
         bf16* __restrict__ Chi, bf16* __restrict__ Clo,
         int N, int K)
{
    extern __shared__ char sm[];
    const uint32_t sbase = smem_u32(sm);
    const int tid = threadIdx.x, wid = tid >> 5, lid = tid & 31;
    const int m0 = blockIdx.y * 128, n0 = blockIdx.x * 128;
    const int wm = wid >> 2, wn = wid & 3;      // 4x4 warp grid, 32x32 per warp

    const int lrow = tid >> 2;                  // loader row 0..127
    const int lcb  = (tid & 3) * 32;            // loader col bytes (2x16B)

    float acc[2][4][4] = {};

    const bf16* gs[4] = {Ahi, Alo, Bhi, Blo};
    const int   r0s[4] = {m0, m0, n0, n0};

    auto issue = [&](int c) {
        const int k0 = c * KCH;
        const uint32_t sb = sbase + (uint32_t)(c & 1) * STAGE_B;
        #pragma unroll
        for (int t = 0; t < 4; t++) {
            const char* g = (const char*)(gs[t] + (size_t)(r0s[t] + lrow) * K + k0) + lcb;
            uint32_t d = sb + t * TILE_B + lrow * ROWB + lcb;
            cpasync16(d,      g);
            cpasync16(d + 16, g + 16);
        }
        asm volatile("cp.async.commit_group;");
    };

    const int NC = K / KCH;
    issue(0);

    const int am = (lid >> 3);
    const uint32_t aRow = wm * 32 + (am & 1) * 8 + (lid & 7);
    const uint32_t aColH = (am >> 1) * 16;
    const uint32_t bRowBase = wn * 32 + (lid & 7);
    const uint32_t bNt = (am >> 1);
    const uint32_t bColH = (am & 1) * 16;

    for (int c = 0; c < NC; c++) {
        if (c + 1 < NC) { issue(c + 1); asm volatile("cp.async.wait_group 1;"); }
        else            { asm volatile("cp.async.wait_group 0;"); }
        __syncthreads();

        const uint32_t sb = sbase + (uint32_t)(c & 1) * STAGE_B;
        const uint32_t aHiB = sb,               aLoB = sb + TILE_B;
        const uint32_t bHiB = sb + 2 * TILE_B,  bLoB = sb + 3 * TILE_B;

        #pragma unroll
        for (int ks = 0; ks < 4; ks++) {
            uint32_t bh[2][4], bl[2][4];
            #pragma unroll
            for (int p = 0; p < 2; p++) {
                uint32_t row = bRowBase + (p * 2 + bNt) * 8;
                uint32_t off = row * ROWB + ks * 32 + bColH;
                ldsm4(bh[p], bHiB + off);
                ldsm4(bl[p], bLoB + off);
            }
            #pragma unroll
            for (int mt = 0; mt < 2; mt++) {
                uint32_t ah[4], al[4];
                uint32_t off = (aRow + mt * 16) * ROWB + ks * 32 + aColH;
                ldsm4(ah, aHiB + off);
                ldsm4(al, aLoB + off);
                #pragma unroll
                for (int nt = 0; nt < 4; nt++) {
                    const int p = nt >> 1, q = (nt & 1) * 2;
                    mma_bf16(acc[mt][nt], ah, bh[p][q], bh[p][q + 1]);
                    mma_bf16(acc[mt][nt], ah, bl[p][q], bl[p][q + 1]);
                    mma_bf16(acc[mt][nt], al, bh[p][q], bh[p][q + 1]);
                }
            }
        }
        __syncthreads();
    }

    const bool isV = (EPI == EPI_QKV) && (n0 >= 2 * E_);

    #pragma unroll
    for (int mt = 0; mt < 2; mt++) {
        #pragma unroll
        for (int nt = 0; nt < 4; nt++) {
            const int r0 = m0 + wm * 32 + mt * 16 + (lid >> 2);
            const int cc = n0 + wn * 32 + nt * 8 + (lid & 3) * 2;
            #pragma unroll
            for (int hh = 0; hh < 2; hh++) {
                const int r = r0 + hh * 8;
                float v0 = acc[mt][nt][hh * 2], v1 = acc[mt][nt][hh * 2 + 1];
                if (EPI == EPI_QKV) {
                    bf16 h0, l0, h1, l1;
                    split_bf16(v0, h0, l0);
                    split_bf16(v1, h1, l1);
                    if (isV) {
                        const int rl = r - m0;
                        const int cl = cc - n0;
                        *(bf16*)(sm + cl * VROW + rl * 2)                = h0;
                        *(bf16*)(sm + (cl + 1) * VROW + rl * 2)          = h1;
                        *(bf16*)(sm + VPLANE + cl * VROW + rl * 2)       = l0;
                        *(bf16*)(sm + VPLANE + (cl + 1) * VROW + rl * 2) = l1;
                    } else {
                        const int bb = r >> 11, tt = r & (T_ - 1);
                        int which = (cc >= E_) ? 1 : 0;
                        int nn = cc - which * E_;
                        int hx = nn >> 6, d = nn & 63;
                        size_t o = ((size_t)(bb * H_ + hx) * T_ + tt) * D_ + d;
                        bf16* dh = (which == 0) ? Qh : Kh;
                        bf16* dl = (which == 0) ? Ql : Kl;
                        *(__nv_bfloat162*)&dh[o] = __nv_bfloat162(h0, h1);
                        *(__nv_bfloat162*)&dl[o] = __nv_bfloat162(l0, l1);
                    }
                } else if (EPI == EPI_BIAS_RESID) {
                    size_t o = (size_t)r * N + cc;
                    float2 bs = *(const float2*)&bias[cc];
                    float2 rs = *(const float2*)&resid[o];
                    *(float2*)&C[o] = make_float2(v0 + bs.x + rs.x, v1 + bs.y + rs.y);
                } else {
                    size_t o = (size_t)r * N + cc;
                    float2 bs = *(const float2*)&bias[cc];
                    float vv[2] = {v0 + bs.x, v1 + bs.y};
                    bf16 ph[2], pl[2];
                    #pragma unroll
                    for (int j = 0; j < 2; j++) {
                        float v = vv[j];
                        float u = 0.7978845608028654f * (v + 0.044715f * v * v * v);
                        v = 0.5f * v * (1.f + tanhf(u));
                        split_bf16(v, ph[j], pl[j]);
                    }
                    *(__nv_bfloat162*)&Chi[o] = __nv_bfloat162(ph[0], ph[1]);
                    *(__nv_bfloat162*)&Clo[o] = __nv_bfloat162(pl[0], pl[1]);
                }
            }
        }
    }

    if (isV) {
        __syncthreads();
        const int bb = m0 >> 11, tt0 = m0 & (T_ - 1);
        const int nh = n0 - 2 * E_;
        #pragma unroll
        for (int it = 0; it < 8; it++) {
            const int R = it * 32 + (tid >> 4);       // 0..255
            const int plane = R >> 7, nl = R & 127;
            const int hx = (nh + nl) >> 6, d = (nh + nl) & 63;
            const uint4 v = *(const uint4*)(sm + plane * VPLANE + nl * VROW + (tid & 15) * 16);
            bf16* dst = plane ? Vtl : Vth;
            *(uint4*)&dst[((size_t)(bb * H_ + hx) * D_ + d) * T_ + tt0 + (tid & 15) * 8] = v;
        }
    }
}

// ---------------- tensor-core flash attention (unchanged from R5) ----------------
#define FROWK 144
#define FROWV 272
#define FQH   0
#define FQL   18432
#define FSTG0 36864
#define FSTGB 71680
#define FA2_SMEM (36864 + 2*FSTGB)   // 180224

__global__ void __launch_bounds__(256, 1)
flash_attn2(const bf16* __restrict__ Qh_g, const bf16* __restrict__ Ql_g,
            const bf16* __restrict__ Kh_g, const bf16* __restrict__ Kl_g,
            const bf16* __restrict__ Vth_g, const bf16* __restrict__ Vtl_g,
            bf16* __restrict__ ctxh, bf16* __restrict__ ctxl)
{
    extern __shared__ char sm[];
    const uint32_t sb = smem_u32(sm);
    const int tid = threadIdx.x, wid = tid >> 5, lid = tid & 31;
    const int bh = blockIdx.y;
    const int mtile = (gridDim.x - 1) - blockIdx.x;
    const int q0 = mtile * 128;

    const bf16* Qhb = Qh_g + (size_t)bh * T_ * D_;
    const bf16* Qlb = Ql_g + (size_t)bh * T_ * D_;
    const bf16* Khb = Kh_g + (size_t)bh * T_ * D_;
    const bf16* Klb = Kl_g + (size_t)bh * T_ * D_;
    const bf16* Vhb = Vth_g + (size_t)bh * D_ * T_;
    const bf16* Vlb = Vtl_g + (size_t)bh * D_ * T_;

    {
        const int row = tid >> 1, half = tid & 1;
        const char* gh = (const char*)(Qhb + (size_t)(q0 + row) * D_ + half * 32);
        const char* gl = (const char*)(Qlb + (size_t)(q0 + row) * D_ + half * 32);
        uint32_t dh = sb + FQH + row * FROWK + half * 64;
        uint32_t dl = sb + FQL + row * FROWK + half * 64;
        #pragma unroll
        for (int i = 0; i < 4; i++) { cpasync16(dh + i * 16, gh + i * 16); cpasync16(dl + i * 16, gl + i * 16); }
    }

    auto issueKV = [&](int stage, int kvt) {
        const int kv0 = kvt * 128;
        const uint32_t s0 = sb + FSTG0 + (uint32_t)stage * FSTGB;
        {
            const int row = tid >> 1, half = tid & 1;
            const char* gh = (const char*)(Khb + (size_t)(kv0 + row) * D_ + half * 32);
            const char* gl = (const char*)(Klb + (size_t)(kv0 + row) * D_ + half * 32);
            uint32_t dh = s0 + row * FROWK + half * 64;
            uint32_t dl = s0 + 18432 + row * FROWK + half * 64;
            #pragma unroll
            for (int i = 0; i < 4; i++) { cpasync16(dh + i * 16, gh + i * 16); cpasync16(dl + i * 16, gl + i * 16); }
        }
        {
            const int row = tid >> 2, qt = tid & 3;
            const char* gh = (const char*)(Vhb + (size_t)row * T_ + kv0 + qt * 32);
            const char* gl = (const char*)(Vlb + (size_t)row * T_ + kv0 + qt * 32);
            uint32_t dh = s0 + 36864 + row * FROWV + qt * 64;
            uint32_t dl = s0 + 54272 + row * FROWV + qt * 64;
            #pragma unroll
            for (int i = 0; i < 4; i++) { cpasync16(dh + i * 16, gh + i * 16); cpasync16(dl + i * 16, gl + i * 16); }
        }
        asm volatile("cp.async.commit_group;");
    };

    issueKV(0, 0);

    const int am = lid >> 3;
    uint32_t qhf[4][4], qlf[4][4];
    float m_[2] = {-1e30f, -1e30f}, l_[2] = {0.f, 0.f};
    float oacc[8][4] = {};

    const int r0g = q0 + wid * 16 + (lid >> 2);
    const int c0l = (lid & 3) * 2;

    for (int kt = 0; kt <= mtile; kt++) {
        if (kt + 1 <= mtile) { issueKV((kt + 1) & 1, kt + 1); asm volatile("cp.async.wait_group 1;"); }
        else                 { asm volatile("cp.async.wait_group 0;"); }
        __syncthreads();

        if (kt == 0) {
            const uint32_t rowq = wid * 16 + (am & 1) * 8 + (lid & 7);
            #pragma unroll
            for (int ks = 0; ks < 4; ks++) {
                uint32_t off = rowq * FROWK + ks * 32 + (am >> 1) * 16;
                ldsm4(qhf[ks], sb + FQH + off);
                ldsm4(qlf[ks], sb + FQL + off);
            }
        }

        const uint32_t stg = sb + FSTG0 + (uint32_t)(kt & 1) * FSTGB;

        float sacc[16][4] = {};
        #pragma unroll
        for (int ks = 0; ks < 4; ks++) {
            #pragma unroll
            for (int ntp = 0; ntp < 8; ntp++) {
                uint32_t kh4[4], kl4[4];
                uint32_t off = (uint32_t)(ntp * 16 + ((lid >> 4) * 8) + (lid & 7)) * FROWK
                             + ks * 32 + ((lid >> 3) & 1) * 16;
                ldsm4(kh4, stg + off);
                ldsm4(kl4, stg + 18432 + off);
                mma_bf16(sacc[2 * ntp],     qhf[ks], kh4[0], kh4[1]);
                mma_bf16(sacc[2 * ntp],     qhf[ks], kl4[0], kl4[1]);
                mma_bf16(sacc[2 * ntp],     qlf[ks], kh4[0], kh4[1]);
                mma_bf16(sacc[2 * ntp + 1], qhf[ks], kh4[2], kh4[3]);
                mma_bf16(sacc[2 * ntp + 1], qhf[ks], kl4[2], kl4[3]);
                mma_bf16(sacc[2 * ntp + 1], qlf[ks], kh4[2], kh4[3]);
            }
        }

        const bool diag = (kt == mtile);
        float mx0 = -1e30f, mx1 = -1e30f;
        #pragma unroll
        for (int nt = 0; nt < 16; nt++) {
            #pragma unroll
            for (int j = 0; j < 2; j++) {
                float s = sacc[nt][j] * 0.125f;
                if (diag && (kt * 128 + nt * 8 + c0l + j) > r0g) s = -1e30f;
                sacc[nt][j] = s; mx0 = fmaxf(mx0, s);
            }
            #pragma unroll
            for (int j = 2; j < 4; j++) {
                float s = sacc[nt][j] * 0.125f;
                if (diag && (kt * 128 + nt * 8 + c0l + j - 2) > r0g + 8) s = -1e30f;
                sacc[nt][j] = s; mx1 = fmaxf(mx1, s);
            }
        }
        #pragma unroll
        for (int o = 1; o < 4; o <<= 1) {
            mx0 = fmaxf(mx0, __shfl_xor_sync(0xffffffffu, mx0, o));
            mx1 = fmaxf(mx1, __shfl_xor_sync(0xffffffffu, mx1, o));
        }
        float mn0 = fmaxf(m_[0], mx0), mn1 = fmaxf(m_[1], mx1);
        float cr0 = __expf(m_[0] - mn0), cr1 = __expf(m_[1] - mn1);
        float sum0 = 0.f, sum1 = 0.f;
        #pragma unroll
        for (int nt = 0; nt < 16; nt++) {
            float p0 = __expf(sacc[nt][0] - mn0), p1 = __expf(sacc[nt][1] - mn0);
            float p2 = __expf(sacc[nt][2] - mn1), p3 = __expf(sacc[nt][3] - mn1);
            sacc[nt][0] = p0; sacc[nt][1] = p1; sacc[nt][2] = p2; sacc[nt][3] = p3;
            sum0 += p0 + p1; sum1 += p2 + p3;
        }
        #pragma unroll
        for (int o = 1; o < 4; o <<= 1) {
            sum0 += __shfl_xor_sync(0xffffffffu, sum0, o);
            sum1 += __shfl_xor_sync(0xffffffffu, sum1, o);
        }
        l_[0] = l_[0] * cr0 + sum0; l_[1] = l_[1] * cr1 + sum1;
        m_[0] = mn0; m_[1] = mn1;
        #pragma unroll
        for (int d = 0; d < 8; d++) {
            oacc[d][0] *= cr0; oacc[d][1] *= cr0;
            oacc[d][2] *= cr1; oacc[d][3] *= cr1;
        }

        #pragma unroll
        for (int kvt = 0; kvt < 8; kvt++) {
            float p00 = sacc[2 * kvt][0],     p01 = sacc[2 * kvt][1];
            float p02 = sacc[2 * kvt][2],     p03 = sacc[2 * kvt][3];
            float p10 = sacc[2 * kvt + 1][0], p11 = sacc[2 * kvt + 1][1];
            float p12 = sacc[2 * kvt + 1][2], p13 = sacc[2 * kvt + 1][3];
            uint32_t pa_h[4], pa_l[4];
            pa_h[0] = packbf(p00, p01); pa_h[1] = packbf(p02, p03);
            pa_h[2] = packbf(p10, p11); pa_h[3] = packbf(p12, p13);
            bf16 b;
            b = __float2bfloat16(p00); float r00 = p00 - __bfloat162float(b);
            b = __float2bfloat16(p01); float r01 = p01 - __bfloat162float(b);
            b = __float2bfloat16(p02); float r02 = p02 - __bfloat162float(b);
            b = __float2bfloat16(p03); float r03 = p03 - __bfloat162float(b);
            b = __float2bfloat16(p10); float r10 = p10 - __bfloat162float(b);
            b = __float2bfloat16(p11); float r11 = p11 - __bfloat162float(b);
            b = __float2bfloat16(p12); float r12 = p12 - __bfloat162float(b);
            b = __float2bfloat16(p13); float r13 = p13 - __bfloat162float(b);
            pa_l[0] = packbf(r00, r01); pa_l[1] = packbf(r02, r03);
            pa_l[2] = packbf(r10, r11); pa_l[3] = packbf(r12, r13);

            #pragma unroll
            for (int ntp = 0; ntp < 4; ntp++) {
                uint32_t vh4[4], vl4[4];
                uint32_t off = (uint32_t)(ntp * 16 + ((lid >> 4) * 8) + (lid & 7)) * FROWV
                             + kvt * 32 + ((lid >> 3) & 1) * 16;
                ldsm4(vh4, stg + 36864 + off);
                ldsm4(vl4, stg + 54272 + off);
                mma_bf16(oacc[2 * ntp],     pa_h, vh4[0], vh4[1]);
                mma_bf16(oacc[2 * ntp],     pa_h, vl4[0], vl4[1]);
                mma_bf16(oacc[2 * ntp],     pa_l, vh4[0], vh4[1]);
                mma_bf16(oacc[2 * ntp + 1], pa_h, vh4[2], vh4[3]);
                mma_bf16(oacc[2 * ntp + 1], pa_h, vl4[2], vl4[3]);
                mma_bf16(oacc[2 * ntp + 1], pa_l, vh4[2], vh4[3]);
            }
        }
        __syncthreads();
    }

    const int b = bh / H_, h = bh - b * H_;
    float inv0 = 1.f / l_[0], inv1 = 1.f / l_[1];
    #pragma unroll
    for (int nt = 0; nt < 8; nt++) {
        const int d = nt * 8 + c0l;
        {
            float v0 = oacc[nt][0] * inv0, v1 = oacc[nt][1] * inv0;
            bf16 h0, l0, h1, l1;
            split_bf16(v0, h0, l0); split_bf16(v1, h1, l1);
            size_t o = ((size_t)(b * T_ + r0g)) * E_ + h * D_ + d;
            *(__nv_bfloat162*)&ctxh[o] = __nv_bfloat162(h0, h1);
            *(__nv_bfloat162*)&ctxl[o] = __nv_bfloat162(l0, l1);
        }
        {
            float v0 = oacc[nt][2] * inv1, v1 = oacc[nt][3] * inv1;
            bf16 h0, l0, h1, l1;
            split_bf16(v0, h0, l0); split_bf16(v1, h1, l1);
            size_t o = ((size_t)(b * T_ + r0g + 8)) * E_ + h * D_ + d;
            *(__nv_bfloat162*)&ctxh[o] = __nv_bfloat162(h0, h1);
            *(__nv_bfloat162*)&ctxl[o] = __nv_bfloat162(l0, l1);
        }
    }
}

// ---------------- launch ----------------
extern "C" void kernel_launch(void* const* d_in, const int* in_sizes, int n_in,
                              void* d_out, int out_size)
{
    const float* x    = (const float*)d_in[0];
    const float* wq   = (const float*)d_in[1];
    const float* wk   = (const float*)d_in[2];
    const float* wv   = (const float*)d_in[3];
    const float* wo   = (const float*)d_in[4];
    const float* bo   = (const float*)d_in[5];
    const float* ln1s = (const float*)d_in[6];
    const float* ln1b = (const float*)d_in[7];
    const float* ln2s = (const float*)d_in[8];
    const float* ln2b = (const float*)d_in[9];
    const float* w1   = (const float*)d_in[10];
    const float* b1   = (const float*)d_in[11];
    const float* w2   = (const float*)d_in[12];
    const float* b2   = (const float*)d_in[13];
    float* out = (float*)d_out;

    float *x2;
    bf16 *h1h, *h1l, *qh, *ql, *kh, *kl, *vth, *vtl, *ctxh, *ctxl, *h2h, *h2l, *midh, *midl;
    bf16 *wqkvTh, *wqkvTl, *woTh, *woTl, *w1Th, *w1Tl, *w2Th, *w2Tl;
    cudaGetSymbolAddress((void**)&x2,  g_x2);
    cudaGetSymbolAddress((void**)&h1h, g_h1h);  cudaGetSymbolAddress((void**)&h1l, g_h1l);
    cudaGetSymbolAddress((void**)&qh,  g_qh);   cudaGetSymbolAddress((void**)&ql,  g_ql);
    cudaGetSymbolAddress((void**)&kh,  g_kh);   cudaGetSymbolAddress((void**)&kl,  g_kl);
    cudaGetSymbolAddress((void**)&vth, g_vth);  cudaGetSymbolAddress((void**)&vtl, g_vtl);
    cudaGetSymbolAddress((void**)&ctxh,g_ctxh); cudaGetSymbolAddress((void**)&ctxl,g_ctxl);
    cudaGetSymbolAddress((void**)&h2h, g_h2h);  cudaGetSymbolAddress((void**)&h2l, g_h2l);
    cudaGetSymbolAddress((void**)&midh,g_midh); cudaGetSymbolAddress((void**)&midl,g_midl);
    cudaGetSymbolAddress((void**)&wqkvTh,g_wqkvTh); cudaGetSymbolAddress((void**)&wqkvTl,g_wqkvTl);
    cudaGetSymbolAddress((void**)&woTh,g_woTh); cudaGetSymbolAddress((void**)&woTl,g_woTl);
    cudaGetSymbolAddress((void**)&w1Th,g_w1Th); cudaGetSymbolAddress((void**)&w1Tl,g_w1Tl);
    cudaGetSymbolAddress((void**)&w2Th,g_w2Th); cudaGetSymbolAddress((void**)&w2Tl,g_w2Tl);

    cudaFuncSetAttribute(flash_attn2, cudaFuncAttributeMaxDynamicSharedMemorySize, FA2_SMEM);
    cudaFuncSetAttribute(mma_gemm<EPI_QKV>,             cudaFuncAttributeMaxDynamicSharedMemorySize, GEMM_SMEM);
    cudaFuncSetAttribute(mma_gemm<EPI_BIAS_RESID>,      cudaFuncAttributeMaxDynamicSharedMemorySize, GEMM_SMEM);
    cudaFuncSetAttribute(mma_gemm<EPI_BIAS_GELU_SPLIT>, cudaFuncAttributeMaxDynamicSharedMemorySize, GEMM_SMEM);

    // weight transpose+split
    wsplitT4<<<dim3(E_/32, E_/32, 4), 256>>>(wq, wk, wv, wo, wqkvTh, wqkvTl, woTh, woTl);
    wsplitT<<<dim3(FF_/32, E_/32), 256>>>(w1, w1Th, w1Tl, E_, FF_);
    wsplitT<<<dim3(E_/32, FF_/32), 256>>>(w2, w2Th, w2Tl, FF_, E_);

    // LN1 -> h1 hi/lo
    ln_kernel<<<M_, 256>>>(x, ln1s, ln1b, h1h, h1l);

    // fused QKV -> Q/K hi/lo [BH,T,D], Vt hi/lo [BH,D,T]
    mma_gemm<EPI_QKV><<<dim3(QKVN/128, M_/128), GT, GEMM_SMEM>>>(
        h1h, h1l, wqkvTh, wqkvTl, nullptr, nullptr, nullptr,
        qh, ql, kh, kl, vth, vtl, nullptr, nullptr, QKVN, E_);

    // tensor-core flash attention -> ctx hi/lo
    flash_attn2<<<dim3(T_/128, BH_), 256, FA2_SMEM>>>(qh, ql, kh, kl, vth, vtl, ctxh, ctxl);

    // proj + bias + resid -> x2
    mma_gemm<EPI_BIAS_RESID><<<dim3(E_/128, M_/128), GT, GEMM_SMEM>>>(
        ctxh, ctxl, woTh, woTl, bo, x, x2,
        nullptr, nullptr, nullptr, nullptr, nullptr, nullptr, nullptr, nullptr, E_, E_);

    // LN2 -> h2 hi/lo
    ln_kernel<<<M_, 256>>>(x2, ln2s, ln2b, h2h, h2l);

    // MLP1 (gelu) -> mid hi/lo
    mma_gemm<EPI_BIAS_GELU_SPLIT><<<dim3(FF_/128, M_/128), GT, GEMM_SMEM>>>(
        h2h, h2l, w1Th, w1Tl, b1, nullptr, nullptr,
        nullptr, nullptr, nullptr, nullptr, nullptr, nullptr, midh, midl, FF_, E_);

    // MLP2 + bias + resid -> out
    mma_gemm<EPI_BIAS_RESID><<<dim3(E_/128, M_/128), GT, GEMM_SMEM>>>(
        midh, midl, w2Th, w2Tl, b2, x2, out,
        nullptr, nullptr, nullptr, nullptr, nullptr, nullptr, nullptr, nullptr, E_, FF_);
}

// round 8
// speedup vs baseline: 1.4230x; 1.3780x over previous
#include <cuda_runtime.h>
#include <cuda_bf16.h>
#include <cuda_fp16.h>
#include <math.h>
#include <cstdint>

#define B_  2
#define T_  2048
#define E_  768
#define H_  12
#define D_  64
#define M_  (B_*T_)    // 4096
#define FF_ (4*E_)     // 3072
#define BH_ (B_*H_)    // 24
#define QKVN (3*E_)    // 2304

typedef __nv_bfloat16 bf16;
typedef __half fp16;

// ---------------- scratch ----------------
__device__ float g_x2[M_*E_];
__device__ fp16 g_h1h[M_*E_],  g_h1l[M_*E_];
__device__ bf16 g_qh[M_*E_],  g_ql[M_*E_];     // [B,H,T,D]
__device__ bf16 g_kh[M_*E_],  g_kl[M_*E_];     // [B,H,T,D]
__device__ bf16 g_vth[M_*E_], g_vtl[M_*E_];    // [B,H,D,T]
__device__ fp16 g_ctxh[M_*E_], g_ctxl[M_*E_];
__device__ fp16 g_h2h[M_*E_],  g_h2l[M_*E_];
__device__ fp16 g_midh[(size_t)M_*FF_], g_midl[(size_t)M_*FF_];
__device__ fp16 g_wqkvT[(size_t)QKVN*E_];      // [2304,768] fp16 (hi only)
__device__ fp16 g_woT[E_*E_];
__device__ fp16 g_w1T[(size_t)E_*FF_];
__device__ fp16 g_w2T[(size_t)E_*FF_];

// ---------------- helpers ----------------
__device__ __forceinline__ uint32_t smem_u32(const void* p) {
    uint32_t a;
    asm("{ .reg .u64 t; cvta.to.shared.u64 t, %1; cvt.u32.u64 %0, t; }" : "=r"(a) : "l"(p));
    return a;
}
__device__ __forceinline__ void cpasync16(uint32_t dst, const void* src) {
    asm volatile("cp.async.ca.shared.global [%0], [%1], 16;" :: "r"(dst), "l"(src));
}
__device__ __forceinline__ void ldsm4(uint32_t* r, uint32_t addr) {
    asm volatile("ldmatrix.sync.aligned.m8n8.x4.shared.b16 {%0,%1,%2,%3}, [%4];"
        : "=r"(r[0]), "=r"(r[1]), "=r"(r[2]), "=r"(r[3]) : "r"(addr));
}
__device__ __forceinline__ void mma_bf16(float* c, const uint32_t* a, uint32_t b0, uint32_t b1) {
    asm volatile("mma.sync.aligned.m16n8k16.row.col.f32.bf16.bf16.f32 "
        "{%0,%1,%2,%3}, {%4,%5,%6,%7}, {%8,%9}, {%0,%1,%2,%3};"
        : "+f"(c[0]), "+f"(c[1]), "+f"(c[2]), "+f"(c[3])
        : "r"(a[0]), "r"(a[1]), "r"(a[2]), "r"(a[3]), "r"(b0), "r"(b1));
}
__device__ __forceinline__ void mma_f16(float* c, const uint32_t* a, uint32_t b0, uint32_t b1) {
    asm volatile("mma.sync.aligned.m16n8k16.row.col.f32.f16.f16.f32 "
        "{%0,%1,%2,%3}, {%4,%5,%6,%7}, {%8,%9}, {%0,%1,%2,%3};"
        : "+f"(c[0]), "+f"(c[1]), "+f"(c[2]), "+f"(c[3])
        : "r"(a[0]), "r"(a[1]), "r"(a[2]), "r"(a[3]), "r"(b0), "r"(b1));
}
__device__ __forceinline__ void split_bf16(float v, bf16& h, bf16& l) {
    h = __float2bfloat16(v);
    l = __float2bfloat16(v - __bfloat162float(h));
}
__device__ __forceinline__ void split_fp16(float v, fp16& h, fp16& l) {
    h = __float2half_rn(v);
    l = __float2half_rn(v - __half2float(h));
}
__device__ __forceinline__ uint32_t packbf(float a, float b) {
    __nv_bfloat162 t = __floats2bfloat162_rn(a, b);
    return *(uint32_t*)&t;
}

// ---------------- weight transpose + round: w[K,N] -> wT fp16 [N,K] ----------------
__global__ void __launch_bounds__(256)
wsplitT(const float* __restrict__ w, fp16* __restrict__ hi, int K, int N)
{
    __shared__ float t[32][33];
    const int tx = threadIdx.x & 31, ty = threadIdx.x >> 5;
    const int n0 = blockIdx.x * 32, k0 = blockIdx.y * 32;
    #pragma unroll
    for (int i = 0; i < 32; i += 8)
        t[ty + i][tx] = w[(size_t)(k0 + ty + i) * N + n0 + tx];
    __syncthreads();
    #pragma unroll
    for (int i = 0; i < 32; i += 8)
        hi[(size_t)(n0 + ty + i) * K + k0 + tx] = __float2half_rn(t[tx][ty + i]);
}

// ---------------- LayerNorm (ddof=1) -> fp16 hi/lo ----------------
__global__ void __launch_bounds__(256)
ln_kernel(const float* __restrict__ x, const float* __restrict__ sc,
          const float* __restrict__ sh, fp16* __restrict__ ohi, fp16* __restrict__ olo)
{
    int row = blockIdx.x;
    const float* xr = x + (size_t)row * E_;
    float s = 0.f, s2 = 0.f;
    for (int i = threadIdx.x; i < E_; i += 256) { float v = xr[i]; s += v; s2 += v * v; }
    __shared__ float rs[8], rs2[8];
    #pragma unroll
    for (int o = 16; o; o >>= 1) {
        s  += __shfl_xor_sync(0xffffffffu, s,  o);
        s2 += __shfl_xor_sync(0xffffffffu, s2, o);
    }
    if ((threadIdx.x & 31) == 0) { rs[threadIdx.x >> 5] = s; rs2[threadIdx.x >> 5] = s2; }
    __syncthreads();
    float ts = 0.f, ts2 = 0.f;
    #pragma unroll
    for (int i = 0; i < 8; i++) { ts += rs[i]; ts2 += rs2[i]; }
    float mean = ts * (1.f / E_);
    float var  = (ts2 - ts * mean) * (1.f / (E_ - 1));
    float rstd = rsqrtf(var + 1e-5f);
    for (int i = threadIdx.x; i < E_; i += 256) {
        float v = sc[i] * (xr[i] - mean) * rstd + sh[i];
        fp16 h, l; split_fp16(v, h, l);
        ohi[(size_t)row * E_ + i] = h;
        olo[(size_t)row * E_ + i] = l;
    }
}

// ---------------- warp-MMA GEMM: fp16 2-term, 2-stage cp.async (R5 structure) ----------------
enum { EPI_QKV = 0, EPI_BIAS_RESID = 1, EPI_BIAS_GELU_SPLIT = 2 };

#define KCH     64
#define ROWB    144
#define TILE_B  (128*ROWB)      // 18432
#define STAGE_B (3*TILE_B)      // 55296 (Ah, Al, Bh)
#define GEMM_SMEM (2*STAGE_B)   // 110592

template<int EPI>
__global__ void __launch_bounds__(256, 1)
mma_gemm(const fp16* __restrict__ Ahi, const fp16* __restrict__ Alo,
         const fp16* __restrict__ Bh_g,
         const float* __restrict__ bias, const float* __restrict__ resid,
         float* __restrict__ C,
         bf16* __restrict__ Qh, bf16* __restrict__ Ql,
         bf16* __restrict__ Kh, bf16* __restrict__ Kl,
         bf16* __restrict__ Vth, bf16* __restrict__ Vtl,
         fp16* __restrict__ Chi, fp16* __restrict__ Clo,
         int N, int K)
{
    extern __shared__ char sm[];
    const uint32_t sbase = smem_u32(sm);
    const int tid = threadIdx.x, wid = tid >> 5, lid = tid & 31;
    const int m0 = blockIdx.y * 128, n0 = blockIdx.x * 128;
    const int wm = wid >> 2, wn = wid & 3;

    const int lrow = tid >> 3;
    const int lcb  = (tid & 7) * 16;

    float acc[4][4][4] = {};

    const fp16* gs[3] = {Ahi, Alo, Bh_g};
    const int   r0s[3] = {m0, m0, n0};

    auto issue = [&](int c) {
        const int k0 = c * KCH;
        const uint32_t sb = sbase + (uint32_t)(c & 1) * STAGE_B;
        #pragma unroll
        for (int t = 0; t < 3; t++) {
            const char* g = (const char*)(gs[t] + (size_t)(r0s[t] + lrow) * K + k0) + lcb;
            uint32_t d = sb + t * TILE_B + lrow * ROWB + lcb;
            #pragma unroll
            for (int i = 0; i < 4; i++)
                cpasync16(d + i * 32 * ROWB, g + (size_t)i * 32 * K * 2);
        }
        asm volatile("cp.async.commit_group;");
    };

    const int NC = K / KCH;
    issue(0);

    const int am = (lid >> 3);
    const uint32_t aRow = wm * 64 + (am & 1) * 8 + (lid & 7);
    const uint32_t aColH = (am >> 1) * 16;
    const uint32_t bRowBase = wn * 32 + (lid & 7);
    const uint32_t bNt = (am >> 1);
    const uint32_t bColH = (am & 1) * 16;

    for (int c = 0; c < NC; c++) {
        if (c + 1 < NC) { issue(c + 1); asm volatile("cp.async.wait_group 1;"); }
        else            { asm volatile("cp.async.wait_group 0;"); }
        __syncthreads();

        const uint32_t sb = sbase + (uint32_t)(c & 1) * STAGE_B;
        const uint32_t aHiB = sb, aLoB = sb + TILE_B, bHiB = sb + 2 * TILE_B;

        #pragma unroll
        for (int ks = 0; ks < 4; ks++) {
            uint32_t bh[2][4];
            #pragma unroll
            for (int p = 0; p < 2; p++) {
                uint32_t row = bRowBase + (p * 2 + bNt) * 8;
                uint32_t off = row * ROWB + ks * 32 + bColH;
                ldsm4(bh[p], bHiB + off);
            }
            #pragma unroll
            for (int mt = 0; mt < 4; mt++) {
                uint32_t ah[4], al[4];
                uint32_t off = (aRow + mt * 16) * ROWB + ks * 32 + aColH;
                ldsm4(ah, aHiB + off);
                ldsm4(al, aLoB + off);
                #pragma unroll
                for (int nt = 0; nt < 4; nt++) {
                    const int p = nt >> 1, q = (nt & 1) * 2;
                    mma_f16(acc[mt][nt], ah, bh[p][q], bh[p][q + 1]);
                    mma_f16(acc[mt][nt], al, bh[p][q], bh[p][q + 1]);
                }
            }
        }
        __syncthreads();
    }

    #pragma unroll
    for (int mt = 0; mt < 4; mt++) {
        #pragma unroll
        for (int nt = 0; nt < 4; nt++) {
            const int r0 = m0 + wm * 64 + mt * 16 + (lid >> 2);
            const int cc = n0 + wn * 32 + nt * 8 + (lid & 3) * 2;
            #pragma unroll
            for (int hh = 0; hh < 2; hh++) {
                const int r = r0 + hh * 8;
                float v0 = acc[mt][nt][hh * 2], v1 = acc[mt][nt][hh * 2 + 1];
                if (EPI == EPI_QKV) {
                    const int bb = r >> 11, tt = r & (T_ - 1);
                    int which = (cc >= 2 * E_) ? 2 : (cc >= E_ ? 1 : 0);
                    int nn = cc - which * E_;
                    int hx = nn >> 6, d = nn & 63;
                    bf16 h0, l0, h1, l1;
                    split_bf16(v0, h0, l0);
                    split_bf16(v1, h1, l1);
                    if (which == 2) {
                        size_t o = ((size_t)(bb * H_ + hx) * D_ + d) * T_ + tt;
                        Vth[o] = h0; Vth[o + T_] = h1;
                        Vtl[o] = l0; Vtl[o + T_] = l1;
                    } else {
                        size_t o = ((size_t)(bb * H_ + hx) * T_ + tt) * D_ + d;
                        bf16* dh = (which == 0) ? Qh : Kh;
                        bf16* dl = (which == 0) ? Ql : Kl;
                        *(__nv_bfloat162*)&dh[o] = __nv_bfloat162(h0, h1);
                        *(__nv_bfloat162*)&dl[o] = __nv_bfloat162(l0, l1);
                    }
                } else if (EPI == EPI_BIAS_RESID) {
                    size_t o = (size_t)r * N + cc;
                    float2 bs = *(const float2*)&bias[cc];
                    float2 rs = *(const float2*)&resid[o];
                    *(float2*)&C[o] = make_float2(v0 + bs.x + rs.x, v1 + bs.y + rs.y);
                } else {
                    size_t o = (size_t)r * N + cc;
                    float2 bs = *(const float2*)&bias[cc];
                    float vv[2] = {v0 + bs.x, v1 + bs.y};
                    fp16 ph[2], pl[2];
                    #pragma unroll
                    for (int j = 0; j < 2; j++) {
                        float v = vv[j];
                        float u = 0.7978845608028654f * (v + 0.044715f * v * v * v);
                        v = 0.5f * v * (1.f + tanhf(u));
                        split_fp16(v, ph[j], pl[j]);
                    }
                    *(__half2*)&Chi[o] = __halves2half2(ph[0], ph[1]);
                    *(__half2*)&Clo[o] = __halves2half2(pl[0], pl[1]);
                }
            }
        }
    }
}

// ---------------- tensor-core flash attention (R5, ctx -> fp16 hi/lo) ----------------
#define FROWK 144
#define FROWV 272
#define FQH   0
#define FQL   18432
#define FSTG0 36864
#define FSTGB 71680
#define FA2_SMEM (36864 + 2*FSTGB)   // 180224

__global__ void __launch_bounds__(256, 1)
flash_attn2(const bf16* __restrict__ Qh_g, const bf16* __restrict__ Ql_g,
            const bf16* __restrict__ Kh_g, const bf16* __restrict__ Kl_g,
            const bf16* __restrict__ Vth_g, const bf16* __restrict__ Vtl_g,
            fp16* __restrict__ ctxh, fp16* __restrict__ ctxl)
{
    extern __shared__ char sm[];
    const uint32_t sb = smem_u32(sm);
    const int tid = threadIdx.x, wid = tid >> 5, lid = tid & 31;
    const int bh = blockIdx.y;
    const int mtile = (gridDim.x - 1) - blockIdx.x;
    const int q0 = mtile * 128;

    const bf16* Qhb = Qh_g + (size_t)bh * T_ * D_;
    const bf16* Qlb = Ql_g + (size_t)bh * T_ * D_;
    const bf16* Khb = Kh_g + (size_t)bh * T_ * D_;
    const bf16* Klb = Kl_g + (size_t)bh * T_ * D_;
    const bf16* Vhb = Vth_g + (size_t)bh * D_ * T_;
    const bf16* Vlb = Vtl_g + (size_t)bh * D_ * T_;

    {
        const int row = tid >> 1, half = tid & 1;
        const char* gh = (const char*)(Qhb + (size_t)(q0 + row) * D_ + half * 32);
        const char* gl = (const char*)(Qlb + (size_t)(q0 + row) * D_ + half * 32);
        uint32_t dh = sb + FQH + row * FROWK + half * 64;
        uint32_t dl = sb + FQL + row * FROWK + half * 64;
        #pragma unroll
        for (int i = 0; i < 4; i++) { cpasync16(dh + i * 16, gh + i * 16); cpasync16(dl + i * 16, gl + i * 16); }
    }

    auto issueKV = [&](int stage, int kvt) {
        const int kv0 = kvt * 128;
        const uint32_t s0 = sb + FSTG0 + (uint32_t)stage * FSTGB;
        {
            const int row = tid >> 1, half = tid & 1;
            const char* gh = (const char*)(Khb + (size_t)(kv0 + row) * D_ + half * 32);
            const char* gl = (const char*)(Klb + (size_t)(kv0 + row) * D_ + half * 32);
            uint32_t dh = s0 + row * FROWK + half * 64;
            uint32_t dl = s0 + 18432 + row * FROWK + half * 64;
            #pragma unroll
            for (int i = 0; i < 4; i++) { cpasync16(dh + i * 16, gh + i * 16); cpasync16(dl + i * 16, gl + i * 16); }
        }
        {
            const int row = tid >> 2, qt = tid & 3;
            const char* gh = (const char*)(Vhb + (size_t)row * T_ + kv0 + qt * 32);
            const char* gl = (const char*)(Vlb + (size_t)row * T_ + kv0 + qt * 32);
            uint32_t dh = s0 + 36864 + row * FROWV + qt * 64;
            uint32_t dl = s0 + 54272 + row * FROWV + qt * 64;
            #pragma unroll
            for (int i = 0; i < 4; i++) { cpasync16(dh + i * 16, gh + i * 16); cpasync16(dl + i * 16, gl + i * 16); }
        }
        asm volatile("cp.async.commit_group;");
    };

    issueKV(0, 0);

    const int am = lid >> 3;
    uint32_t qhf[4][4], qlf[4][4];
    float m_[2] = {-1e30f, -1e30f}, l_[2] = {0.f, 0.f};
    float oacc[8][4] = {};

    const int r0g = q0 + wid * 16 + (lid >> 2);
    const int c0l = (lid & 3) * 2;

    for (int kt = 0; kt <= mtile; kt++) {
        if (kt + 1 <= mtile) { issueKV((kt + 1) & 1, kt + 1); asm volatile("cp.async.wait_group 1;"); }
        else                 { asm volatile("cp.async.wait_group 0;"); }
        __syncthreads();

        if (kt == 0) {
            const uint32_t rowq = wid * 16 + (am & 1) * 8 + (lid & 7);
            #pragma unroll
            for (int ks = 0; ks < 4; ks++) {
                uint32_t off = rowq * FROWK + ks * 32 + (am >> 1) * 16;
                ldsm4(qhf[ks], sb + FQH + off);
                ldsm4(qlf[ks], sb + FQL + off);
            }
        }

        const uint32_t stg = sb + FSTG0 + (uint32_t)(kt & 1) * FSTGB;

        float sacc[16][4] = {};
        #pragma unroll
        for (int ks = 0; ks < 4; ks++) {
            #pragma unroll
            for (int ntp = 0; ntp < 8; ntp++) {
                uint32_t kh4[4], kl4[4];
                uint32_t off = (uint32_t)(ntp * 16 + ((lid >> 4) * 8) + (lid & 7)) * FROWK
                             + ks * 32 + ((lid >> 3) & 1) * 16;
                ldsm4(kh4, stg + off);
                ldsm4(kl4, stg + 18432 + off);
                mma_bf16(sacc[2 * ntp],     qhf[ks], kh4[0], kh4[1]);
                mma_bf16(sacc[2 * ntp],     qhf[ks], kl4[0], kl4[1]);
                mma_bf16(sacc[2 * ntp],     qlf[ks], kh4[0], kh4[1]);
                mma_bf16(sacc[2 * ntp + 1], qhf[ks], kh4[2], kh4[3]);
                mma_bf16(sacc[2 * ntp + 1], qhf[ks], kl4[2], kl4[3]);
                mma_bf16(sacc[2 * ntp + 1], qlf[ks], kh4[2], kh4[3]);
            }
        }

        const bool diag = (kt == mtile);
        float mx0 = -1e30f, mx1 = -1e30f;
        #pragma unroll
        for (int nt = 0; nt < 16; nt++) {
            #pragma unroll
            for (int j = 0; j < 2; j++) {
                float s = sacc[nt][j] * 0.125f;
                if (diag && (kt * 128 + nt * 8 + c0l + j) > r0g) s = -1e30f;
                sacc[nt][j] = s; mx0 = fmaxf(mx0, s);
            }
            #pragma unroll
            for (int j = 2; j < 4; j++) {
                float s = sacc[nt][j] * 0.125f;
                if (diag && (kt * 128 + nt * 8 + c0l + j - 2) > r0g + 8) s = -1e30f;
                sacc[nt][j] = s; mx1 = fmaxf(mx1, s);
            }
        }
        #pragma unroll
        for (int o = 1; o < 4; o <<= 1) {
            mx0 = fmaxf(mx0, __shfl_xor_sync(0xffffffffu, mx0, o));
            mx1 = fmaxf(mx1, __shfl_xor_sync(0xffffffffu, mx1, o));
        }
        float mn0 = fmaxf(m_[0], mx0), mn1 = fmaxf(m_[1], mx1);
        float cr0 = __expf(m_[0] - mn0), cr1 = __expf(m_[1] - mn1);
        float sum0 = 0.f, sum1 = 0.f;
        #pragma unroll
        for (int nt = 0; nt < 16; nt++) {
            float p0 = __expf(sacc[nt][0] - mn0), p1 = __expf(sacc[nt][1] - mn0);
            float p2 = __expf(sacc[nt][2] - mn1), p3 = __expf(sacc[nt][3] - mn1);
            sacc[nt][0] = p0; sacc[nt][1] = p1; sacc[nt][2] = p2; sacc[nt][3] = p3;
            sum0 += p0 + p1; sum1 += p2 + p3;
        }
        #pragma unroll
        for (int o = 1; o < 4; o <<= 1) {
            sum0 += __shfl_xor_sync(0xffffffffu, sum0, o);
            sum1 += __shfl_xor_sync(0xffffffffu, sum1, o);
        }
        l_[0] = l_[0] * cr0 + sum0; l_[1] = l_[1] * cr1 + sum1;
        m_[0] = mn0; m_[1] = mn1;
        #pragma unroll
        for (int d = 0; d < 8; d++) {
            oacc[d][0] *= cr0; oacc[d][1] *= cr0;
            oacc[d][2] *= cr1; oacc[d][3] *= cr1;
        }

        #pragma unroll
        for (int kvt = 0; kvt < 8; kvt++) {
            float p00 = sacc[2 * kvt][0],     p01 = sacc[2 * kvt][1];
            float p02 = sacc[2 * kvt][2],     p03 = sacc[2 * kvt][3];
            float p10 = sacc[2 * kvt + 1][0], p11 = sacc[2 * kvt + 1][1];
            float p12 = sacc[2 * kvt + 1][2], p13 = sacc[2 * kvt + 1][3];
            uint32_t pa_h[4], pa_l[4];
            pa_h[0] = packbf(p00, p01); pa_h[1] = packbf(p02, p03);
            pa_h[2] = packbf(p10, p11); pa_h[3] = packbf(p12, p13);
            bf16 b;
            b = __float2bfloat16(p00); float r00 = p00 - __bfloat162float(b);
            b = __float2bfloat16(p01); float r01 = p01 - __bfloat162float(b);
            b = __float2bfloat16(p02); float r02 = p02 - __bfloat162float(b);
            b = __float2bfloat16(p03); float r03 = p03 - __bfloat162float(b);
            b = __float2bfloat16(p10); float r10 = p10 - __bfloat162float(b);
            b = __float2bfloat16(p11); float r11 = p11 - __bfloat162float(b);
            b = __float2bfloat16(p12); float r12 = p12 - __bfloat162float(b);
            b = __float2bfloat16(p13); float r13 = p13 - __bfloat162float(b);
            pa_l[0] = packbf(r00, r01); pa_l[1] = packbf(r02, r03);
            pa_l[2] = packbf(r10, r11); pa_l[3] = packbf(r12, r13);

            #pragma unroll
            for (int ntp = 0; ntp < 4; ntp++) {
                uint32_t vh4[4], vl4[4];
                uint32_t off = (uint32_t)(ntp * 16 + ((lid >> 4) * 8) + (lid & 7)) * FROWV
                             + kvt * 32 + ((lid >> 3) & 1) * 16;
                ldsm4(vh4, stg + 36864 + off);
                ldsm4(vl4, stg + 54272 + off);
                mma_bf16(oacc[2 * ntp],     pa_h, vh4[0], vh4[1]);
                mma_bf16(oacc[2 * ntp],     pa_h, vl4[0], vl4[1]);
                mma_bf16(oacc[2 * ntp],     pa_l, vh4[0], vh4[1]);
                mma_bf16(oacc[2 * ntp + 1], pa_h, vh4[2], vh4[3]);
                mma_bf16(oacc[2 * ntp + 1], pa_h, vl4[2], vl4[3]);
                mma_bf16(oacc[2 * ntp + 1], pa_l, vh4[2], vh4[3]);
            }
        }
        __syncthreads();
    }

    const int b = bh / H_, h = bh - b * H_;
    float inv0 = 1.f / l_[0], inv1 = 1.f / l_[1];
    #pragma unroll
    for (int nt = 0; nt < 8; nt++) {
        const int d = nt * 8 + c0l;
        {
            float v0 = oacc[nt][0] * inv0, v1 = oacc[nt][1] * inv0;
            fp16 h0, l0, h1, l1;
            split_fp16(v0, h0, l0); split_fp16(v1, h1, l1);
            size_t o = ((size_t)(b * T_ + r0g)) * E_ + h * D_ + d;
            *(__half2*)&ctxh[o] = __halves2half2(h0, h1);
            *(__half2*)&ctxl[o] = __halves2half2(l0, l1);
        }
        {
            float v0 = oacc[nt][2] * inv1, v1 = oacc[nt][3] * inv1;
            fp16 h0, l0, h1, l1;
            split_fp16(v0, h0, l0); split_fp16(v1, h1, l1);
            size_t o = ((size_t)(b * T_ + r0g + 8)) * E_ + h * D_ + d;
            *(__half2*)&ctxh[o] = __halves2half2(h0, h1);
            *(__half2*)&ctxl[o] = __halves2half2(l0, l1);
        }
    }
}

// ---------------- launch ----------------
extern "C" void kernel_launch(void* const* d_in, const int* in_sizes, int n_in,
                              void* d_out, int out_size)
{
    const float* x    = (const float*)d_in[0];
    const float* wq   = (const float*)d_in[1];
    const float* wk   = (const float*)d_in[2];
    const float* wv   = (const float*)d_in[3];
    const float* wo   = (const float*)d_in[4];
    const float* bo   = (const float*)d_in[5];
    const float* ln1s = (const float*)d_in[6];
    const float* ln1b = (const float*)d_in[7];
    const float* ln2s = (const float*)d_in[8];
    const float* ln2b = (const float*)d_in[9];
    const float* w1   = (const float*)d_in[10];
    const float* b1   = (const float*)d_in[11];
    const float* w2   = (const float*)d_in[12];
    const float* b2   = (const float*)d_in[13];
    float* out = (float*)d_out;

    float *x2;
    fp16 *h1h, *h1l, *ctxh, *ctxl, *h2h, *h2l, *midh, *midl;
    bf16 *qh, *ql, *kh, *kl, *vth, *vtl;
    fp16 *wqkvT, *woT, *w1T, *w2T;
    cudaGetSymbolAddress((void**)&x2,  g_x2);
    cudaGetSymbolAddress((void**)&h1h, g_h1h);  cudaGetSymbolAddress((void**)&h1l, g_h1l);
    cudaGetSymbolAddress((void**)&qh,  g_qh);   cudaGetSymbolAddress((void**)&ql,  g_ql);
    cudaGetSymbolAddress((void**)&kh,  g_kh);   cudaGetSymbolAddress((void**)&kl,  g_kl);
    cudaGetSymbolAddress((void**)&vth, g_vth);  cudaGetSymbolAddress((void**)&vtl, g_vtl);
    cudaGetSymbolAddress((void**)&ctxh,g_ctxh); cudaGetSymbolAddress((void**)&ctxl,g_ctxl);
    cudaGetSymbolAddress((void**)&h2h, g_h2h);  cudaGetSymbolAddress((void**)&h2l, g_h2l);
    cudaGetSymbolAddress((void**)&midh,g_midh); cudaGetSymbolAddress((void**)&midl,g_midl);
    cudaGetSymbolAddress((void**)&wqkvT,g_wqkvT);
    cudaGetSymbolAddress((void**)&woT, g_woT);
    cudaGetSymbolAddress((void**)&w1T, g_w1T);
    cudaGetSymbolAddress((void**)&w2T, g_w2T);

    cudaFuncSetAttribute(flash_attn2, cudaFuncAttributeMaxDynamicSharedMemorySize, FA2_SMEM);
    cudaFuncSetAttribute(mma_gemm<EPI_QKV>,             cudaFuncAttributeMaxDynamicSharedMemorySize, GEMM_SMEM);
    cudaFuncSetAttribute(mma_gemm<EPI_BIAS_RESID>,      cudaFuncAttributeMaxDynamicSharedMemorySize, GEMM_SMEM);
    cudaFuncSetAttribute(mma_gemm<EPI_BIAS_GELU_SPLIT>, cudaFuncAttributeMaxDynamicSharedMemorySize, GEMM_SMEM);

    // weight transpose+round; wq/wk/wv stacked into [2304,768]
    wsplitT<<<dim3(E_/32,  E_/32), 256>>>(wq, wqkvT,            E_, E_);
    wsplitT<<<dim3(E_/32,  E_/32), 256>>>(wk, wqkvT + E_*E_,    E_, E_);
    wsplitT<<<dim3(E_/32,  E_/32), 256>>>(wv, wqkvT + 2*E_*E_,  E_, E_);
    wsplitT<<<dim3(E_/32,  E_/32), 256>>>(wo, woT, E_, E_);
    wsplitT<<<dim3(FF_/32, E_/32), 256>>>(w1, w1T, E_, FF_);
    wsplitT<<<dim3(E_/32, FF_/32), 256>>>(w2, w2T, FF_, E_);

    // LN1 -> h1 hi/lo (fp16)
    ln_kernel<<<M_, 256>>>(x, ln1s, ln1b, h1h, h1l);

    // fused QKV -> Q/K bf16 hi/lo [BH,T,D], Vt bf16 hi/lo [BH,D,T]
    mma_gemm<EPI_QKV><<<dim3(QKVN/128, M_/128), 256, GEMM_SMEM>>>(
        h1h, h1l, wqkvT, nullptr, nullptr, nullptr,
        qh, ql, kh, kl, vth, vtl, nullptr, nullptr, QKVN, E_);

    // tensor-core flash attention -> ctx fp16 hi/lo
    flash_attn2<<<dim3(T_/128, BH_), 256, FA2_SMEM>>>(qh, ql, kh, kl, vth, vtl, ctxh, ctxl);

    // proj + bias + resid -> x2
    mma_gemm<EPI_BIAS_RESID><<<dim3(E_/128, M_/128), 256, GEMM_SMEM>>>(
        ctxh, ctxl, woT, bo, x, x2,
        nullptr, nullptr, nullptr, nullptr, nullptr, nullptr, nullptr, nullptr, E_, E_);

    // LN2 -> h2 hi/lo (fp16)
    ln_kernel<<<M_, 256>>>(x2, ln2s, ln2b, h2h, h2l);

    // MLP1 (gelu) -> mid fp16 hi/lo
    mma_gemm<EPI_BIAS_GELU_SPLIT><<<dim3(FF_/128, M_/128), 256, GEMM_SMEM>>>(
        h2h, h2l, w1T, b1, nullptr, nullptr,
        nullptr, nullptr, nullptr, nullptr, nullptr, nullptr, midh, midl, FF_, E_);

    // MLP2 + bias + resid -> out
    mma_gemm<EPI_BIAS_RESID><<<dim3(E_/128, M_/128), 256, GEMM_SMEM>>>(
        midh, midl, w2T, b2, x2, out,
        nullptr, nullptr, nullptr, nullptr, nullptr, nullptr, nullptr, nullptr, E_, FF_);
}

// round 9
// speedup vs baseline: 1.5822x; 1.1119x over previous
#include <cuda_runtime.h>
#include <cuda_bf16.h>
#include <cuda_fp16.h>
#include <math.h>
#include <cstdint>

#define B_  2
#define T_  2048
#define E_  768
#define H_  12
#define D_  64
#define M_  (B_*T_)    // 4096
#define FF_ (4*E_)     // 3072
#define BH_ (B_*H_)    // 24
#define QKVN (3*E_)    // 2304

typedef __nv_bfloat16 bf16;
typedef __half fp16;

// ---------------- scratch ----------------
__device__ float g_x2[M_*E_];
__device__ fp16 g_h1h[M_*E_],  g_h1l[M_*E_];
__device__ fp16 g_qh[M_*E_],  g_ql[M_*E_];     // Q hi/lo [B,H,T,D]
__device__ fp16 g_kh[M_*E_];                   // K fp16  [B,H,T,D]
__device__ fp16 g_vth[M_*E_];                  // Vt fp16 [B,H,D,T]
__device__ fp16 g_ctxh[M_*E_], g_ctxl[M_*E_];
__device__ fp16 g_h2h[M_*E_],  g_h2l[M_*E_];
__device__ fp16 g_midh[(size_t)M_*FF_], g_midl[(size_t)M_*FF_];
__device__ fp16 g_wqkvT[(size_t)QKVN*E_];
__device__ fp16 g_woT[E_*E_];
__device__ fp16 g_w1T[(size_t)E_*FF_];
__device__ fp16 g_w2T[(size_t)E_*FF_];

// ---------------- helpers ----------------
__device__ __forceinline__ uint32_t smem_u32(const void* p) {
    uint32_t a;
    asm("{ .reg .u64 t; cvta.to.shared.u64 t, %1; cvt.u32.u64 %0, t; }" : "=r"(a) : "l"(p));
    return a;
}
__device__ __forceinline__ void cpasync16(uint32_t dst, const void* src) {
    asm volatile("cp.async.ca.shared.global [%0], [%1], 16;" :: "r"(dst), "l"(src));
}
__device__ __forceinline__ void ldsm4(uint32_t* r, uint32_t addr) {
    asm volatile("ldmatrix.sync.aligned.m8n8.x4.shared.b16 {%0,%1,%2,%3}, [%4];"
        : "=r"(r[0]), "=r"(r[1]), "=r"(r[2]), "=r"(r[3]) : "r"(addr));
}
__device__ __forceinline__ void mma_f16(float* c, const uint32_t* a, uint32_t b0, uint32_t b1) {
    asm volatile("mma.sync.aligned.m16n8k16.row.col.f32.f16.f16.f32 "
        "{%0,%1,%2,%3}, {%4,%5,%6,%7}, {%8,%9}, {%0,%1,%2,%3};"
        : "+f"(c[0]), "+f"(c[1]), "+f"(c[2]), "+f"(c[3])
        : "r"(a[0]), "r"(a[1]), "r"(a[2]), "r"(a[3]), "r"(b0), "r"(b1));
}
__device__ __forceinline__ void split_fp16(float v, fp16& h, fp16& l) {
    h = __float2half_rn(v);
    l = __float2half_rn(v - __half2float(h));
}
__device__ __forceinline__ uint32_t packh(float a, float b) {
    __half2 t = __floats2half2_rn(a, b);
    return *(uint32_t*)&t;
}

// ---------------- weight transpose + round: w[K,N] -> wT fp16 [N,K] ----------------
__global__ void __launch_bounds__(256)
wsplitT(const float* __restrict__ w, fp16* __restrict__ hi, int K, int N)
{
    __shared__ float t[32][33];
    const int tx = threadIdx.x & 31, ty = threadIdx.x >> 5;
    const int n0 = blockIdx.x * 32, k0 = blockIdx.y * 32;
    #pragma unroll
    for (int i = 0; i < 32; i += 8)
        t[ty + i][tx] = w[(size_t)(k0 + ty + i) * N + n0 + tx];
    __syncthreads();
    #pragma unroll
    for (int i = 0; i < 32; i += 8)
        hi[(size_t)(n0 + ty + i) * K + k0 + tx] = __float2half_rn(t[tx][ty + i]);
}

// ---------------- LayerNorm (ddof=1) -> fp16 hi/lo ----------------
__global__ void __launch_bounds__(256)
ln_kernel(const float* __restrict__ x, const float* __restrict__ sc,
          const float* __restrict__ sh, fp16* __restrict__ ohi, fp16* __restrict__ olo)
{
    int row = blockIdx.x;
    const float* xr = x + (size_t)row * E_;
    float s = 0.f, s2 = 0.f;
    for (int i = threadIdx.x; i < E_; i += 256) { float v = xr[i]; s += v; s2 += v * v; }
    __shared__ float rs[8], rs2[8];
    #pragma unroll
    for (int o = 16; o; o >>= 1) {
        s  += __shfl_xor_sync(0xffffffffu, s,  o);
        s2 += __shfl_xor_sync(0xffffffffu, s2, o);
    }
    if ((threadIdx.x & 31) == 0) { rs[threadIdx.x >> 5] = s; rs2[threadIdx.x >> 5] = s2; }
    __syncthreads();
    float ts = 0.f, ts2 = 0.f;
    #pragma unroll
    for (int i = 0; i < 8; i++) { ts += rs[i]; ts2 += rs2[i]; }
    float mean = ts * (1.f / E_);
    float var  = (ts2 - ts * mean) * (1.f / (E_ - 1));
    float rstd = rsqrtf(var + 1e-5f);
    for (int i = threadIdx.x; i < E_; i += 256) {
        float v = sc[i] * (xr[i] - mean) * rstd + sh[i];
        fp16 h, l; split_fp16(v, h, l);
        ohi[(size_t)row * E_ + i] = h;
        olo[(size_t)row * E_ + i] = l;
    }
}

// ---------------- warp-MMA GEMM: fp16 2-term, 2-stage cp.async ----------------
enum { EPI_QKV = 0, EPI_BIAS_RESID = 1, EPI_BIAS_GELU_SPLIT = 2 };

#define KCH     64
#define ROWB    144
#define TILE_B  (128*ROWB)      // 18432
#define STAGE_B (3*TILE_B)      // 55296
#define GEMM_SMEM (2*STAGE_B)   // 110592

template<int EPI>
__global__ void __launch_bounds__(256, 1)
mma_gemm(const fp16* __restrict__ Ahi, const fp16* __restrict__ Alo,
         const fp16* __restrict__ Bh_g,
         const float* __restrict__ bias, const float* __restrict__ resid,
         float* __restrict__ C,
         fp16* __restrict__ Qh, fp16* __restrict__ Ql,
         fp16* __restrict__ Kh, fp16* __restrict__ Vth,
         fp16* __restrict__ Chi, fp16* __restrict__ Clo,
         int N, int K)
{
    extern __shared__ char sm[];
    const uint32_t sbase = smem_u32(sm);
    const int tid = threadIdx.x, wid = tid >> 5, lid = tid & 31;
    const int m0 = blockIdx.y * 128, n0 = blockIdx.x * 128;
    const int wm = wid >> 2, wn = wid & 3;

    const int lrow = tid >> 3;
    const int lcb  = (tid & 7) * 16;

    float acc[4][4][4] = {};

    const fp16* gs[3] = {Ahi, Alo, Bh_g};
    const int   r0s[3] = {m0, m0, n0};

    auto issue = [&](int c) {
        const int k0 = c * KCH;
        const uint32_t sb = sbase + (uint32_t)(c & 1) * STAGE_B;
        #pragma unroll
        for (int t = 0; t < 3; t++) {
            const char* g = (const char*)(gs[t] + (size_t)(r0s[t] + lrow) * K + k0) + lcb;
            uint32_t d = sb + t * TILE_B + lrow * ROWB + lcb;
            #pragma unroll
            for (int i = 0; i < 4; i++)
                cpasync16(d + i * 32 * ROWB, g + (size_t)i * 32 * K * 2);
        }
        asm volatile("cp.async.commit_group;");
    };

    const int NC = K / KCH;
    issue(0);

    const int am = (lid >> 3);
    const uint32_t aRow = wm * 64 + (am & 1) * 8 + (lid & 7);
    const uint32_t aColH = (am >> 1) * 16;
    const uint32_t bRowBase = wn * 32 + (lid & 7);
    const uint32_t bNt = (am >> 1);
    const uint32_t bColH = (am & 1) * 16;

    for (int c = 0; c < NC; c++) {
        if (c + 1 < NC) { issue(c + 1); asm volatile("cp.async.wait_group 1;"); }
        else            { asm volatile("cp.async.wait_group 0;"); }
        __syncthreads();

        const uint32_t sb = sbase + (uint32_t)(c & 1) * STAGE_B;
        const uint32_t aHiB = sb, aLoB = sb + TILE_B, bHiB = sb + 2 * TILE_B;

        #pragma unroll
        for (int ks = 0; ks < 4; ks++) {
            uint32_t bh[2][4];
            #pragma unroll
            for (int p = 0; p < 2; p++) {
                uint32_t row = bRowBase + (p * 2 + bNt) * 8;
                uint32_t off = row * ROWB + ks * 32 + bColH;
                ldsm4(bh[p], bHiB + off);
            }
            #pragma unroll
            for (int mt = 0; mt < 4; mt++) {
                uint32_t ah[4], al[4];
                uint32_t off = (aRow + mt * 16) * ROWB + ks * 32 + aColH;
                ldsm4(ah, aHiB + off);
                ldsm4(al, aLoB + off);
                #pragma unroll
                for (int nt = 0; nt < 4; nt++) {
                    const int p = nt >> 1, q = (nt & 1) * 2;
                    mma_f16(acc[mt][nt], ah, bh[p][q], bh[p][q + 1]);
                    mma_f16(acc[mt][nt], al, bh[p][q], bh[p][q + 1]);
                }
            }
        }
        __syncthreads();
    }

    #pragma unroll
    for (int mt = 0; mt < 4; mt++) {
        #pragma unroll
        for (int nt = 0; nt < 4; nt++) {
            const int r0 = m0 + wm * 64 + mt * 16 + (lid >> 2);
            const int cc = n0 + wn * 32 + nt * 8 + (lid & 3) * 2;
            #pragma unroll
            for (int hh = 0; hh < 2; hh++) {
                const int r = r0 + hh * 8;
                float v0 = acc[mt][nt][hh * 2], v1 = acc[mt][nt][hh * 2 + 1];
                if (EPI == EPI_QKV) {
                    const int bb = r >> 11, tt = r & (T_ - 1);
                    int which = (cc >= 2 * E_) ? 2 : (cc >= E_ ? 1 : 0);
                    int nn = cc - which * E_;
                    int hx = nn >> 6, d = nn & 63;
                    if (which == 2) {
                        size_t o = ((size_t)(bb * H_ + hx) * D_ + d) * T_ + tt;
                        Vth[o]      = __float2half_rn(v0);
                        Vth[o + T_] = __float2half_rn(v1);
                    } else if (which == 1) {
                        size_t o = ((size_t)(bb * H_ + hx) * T_ + tt) * D_ + d;
                        *(__half2*)&Kh[o] = __floats2half2_rn(v0, v1);
                    } else {
                        size_t o = ((size_t)(bb * H_ + hx) * T_ + tt) * D_ + d;
                        fp16 h0, l0, h1, l1;
                        split_fp16(v0, h0, l0);
                        split_fp16(v1, h1, l1);
                        *(__half2*)&Qh[o] = __halves2half2(h0, h1);
                        *(__half2*)&Ql[o] = __halves2half2(l0, l1);
                    }
                } else if (EPI == EPI_BIAS_RESID) {
                    size_t o = (size_t)r * N + cc;
                    float2 bs = *(const float2*)&bias[cc];
                    float2 rs = *(const float2*)&resid[o];
                    *(float2*)&C[o] = make_float2(v0 + bs.x + rs.x, v1 + bs.y + rs.y);
                } else {
                    size_t o = (size_t)r * N + cc;
                    float2 bs = *(const float2*)&bias[cc];
                    float vv[2] = {v0 + bs.x, v1 + bs.y};
                    fp16 ph[2], pl[2];
                    #pragma unroll
                    for (int j = 0; j < 2; j++) {
                        float v = vv[j];
                        float u = 0.7978845608028654f * (v + 0.044715f * v * v * v);
                        v = 0.5f * v * (1.f + tanhf(u));
                        split_fp16(v, ph[j], pl[j]);
                    }
                    *(__half2*)&Chi[o] = __halves2half2(ph[0], ph[1]);
                    *(__half2*)&Clo[o] = __halves2half2(pl[0], pl[1]);
                }
            }
        }
    }
}

// ---------------- tensor-core flash attention: fp16 2-term ----------------
// Q hi/lo fp16 [BH,T,D]; K fp16 [BH,T,D]; Vt fp16 [BH,D,T].
// S = Qh K + Ql K ; ctx = Ph V + Pl V (P split in registers).
#define FROWK 144
#define FROWV 272
#define FQH   0
#define FQL   18432
#define FSTG0 36864
#define FSTGB 35840          // K 18432 + V 17408
#define FA2_SMEM (36864 + 2*FSTGB)   // 108544

__global__ void __launch_bounds__(256, 1)
flash_attn2(const fp16* __restrict__ Qh_g, const fp16* __restrict__ Ql_g,
            const fp16* __restrict__ Kh_g, const fp16* __restrict__ Vth_g,
            fp16* __restrict__ ctxh, fp16* __restrict__ ctxl)
{
    extern __shared__ char sm[];
    const uint32_t sb = smem_u32(sm);
    const int tid = threadIdx.x, wid = tid >> 5, lid = tid & 31;
    const int bh = blockIdx.y;
    const int mtile = (gridDim.x - 1) - blockIdx.x;
    const int q0 = mtile * 128;

    const fp16* Qhb = Qh_g + (size_t)bh * T_ * D_;
    const fp16* Qlb = Ql_g + (size_t)bh * T_ * D_;
    const fp16* Khb = Kh_g + (size_t)bh * T_ * D_;
    const fp16* Vhb = Vth_g + (size_t)bh * D_ * T_;

    // Q tile: hi/lo planes
    {
        const int row = tid >> 1, half = tid & 1;
        const char* gh = (const char*)(Qhb + (size_t)(q0 + row) * D_ + half * 32);
        const char* gl = (const char*)(Qlb + (size_t)(q0 + row) * D_ + half * 32);
        uint32_t dh = sb + FQH + row * FROWK + half * 64;
        uint32_t dl = sb + FQL + row * FROWK + half * 64;
        #pragma unroll
        for (int i = 0; i < 4; i++) { cpasync16(dh + i * 16, gh + i * 16); cpasync16(dl + i * 16, gl + i * 16); }
    }

    auto issueKV = [&](int stage, int kvt) {
        const int kv0 = kvt * 128;
        const uint32_t s0 = sb + FSTG0 + (uint32_t)stage * FSTGB;
        {
            const int row = tid >> 1, half = tid & 1;
            const char* gh = (const char*)(Khb + (size_t)(kv0 + row) * D_ + half * 32);
            uint32_t dh = s0 + row * FROWK + half * 64;
            #pragma unroll
            for (int i = 0; i < 4; i++) cpasync16(dh + i * 16, gh + i * 16);
        }
        {
            const int row = tid >> 2, qt = tid & 3;
            const char* gh = (const char*)(Vhb + (size_t)row * T_ + kv0 + qt * 32);
            uint32_t dh = s0 + 18432 + row * FROWV + qt * 64;
            #pragma unroll
            for (int i = 0; i < 4; i++) cpasync16(dh + i * 16, gh + i * 16);
        }
        asm volatile("cp.async.commit_group;");
    };

    issueKV(0, 0);

    const int am = lid >> 3;
    uint32_t qhf[4][4], qlf[4][4];
    float m_[2] = {-1e30f, -1e30f}, l_[2] = {0.f, 0.f};
    float oacc[8][4] = {};

    const int r0g = q0 + wid * 16 + (lid >> 2);
    const int c0l = (lid & 3) * 2;

    for (int kt = 0; kt <= mtile; kt++) {
        if (kt + 1 <= mtile) { issueKV((kt + 1) & 1, kt + 1); asm volatile("cp.async.wait_group 1;"); }
        else                 { asm volatile("cp.async.wait_group 0;"); }
        __syncthreads();

        if (kt == 0) {
            const uint32_t rowq = wid * 16 + (am & 1) * 8 + (lid & 7);
            #pragma unroll
            for (int ks = 0; ks < 4; ks++) {
                uint32_t off = rowq * FROWK + ks * 32 + (am >> 1) * 16;
                ldsm4(qhf[ks], sb + FQH + off);
                ldsm4(qlf[ks], sb + FQL + off);
            }
        }

        const uint32_t stg = sb + FSTG0 + (uint32_t)(kt & 1) * FSTGB;

        // S = Q K^T (2-term)
        float sacc[16][4] = {};
        #pragma unroll
        for (int ks = 0; ks < 4; ks++) {
            #pragma unroll
            for (int ntp = 0; ntp < 8; ntp++) {
                uint32_t kh4[4];
                uint32_t off = (uint32_t)(ntp * 16 + ((lid >> 4) * 8) + (lid & 7)) * FROWK
                             + ks * 32 + ((lid >> 3) & 1) * 16;
                ldsm4(kh4, stg + off);
                mma_f16(sacc[2 * ntp],     qhf[ks], kh4[0], kh4[1]);
                mma_f16(sacc[2 * ntp],     qlf[ks], kh4[0], kh4[1]);
                mma_f16(sacc[2 * ntp + 1], qhf[ks], kh4[2], kh4[3]);
                mma_f16(sacc[2 * ntp + 1], qlf[ks], kh4[2], kh4[3]);
            }
        }

        // online softmax
        const bool diag = (kt == mtile);
        float mx0 = -1e30f, mx1 = -1e30f;
        #pragma unroll
        for (int nt = 0; nt < 16; nt++) {
            #pragma unroll
            for (int j = 0; j < 2; j++) {
                float s = sacc[nt][j] * 0.125f;
                if (diag && (kt * 128 + nt * 8 + c0l + j) > r0g) s = -1e30f;
                sacc[nt][j] = s; mx0 = fmaxf(mx0, s);
            }
            #pragma unroll
            for (int j = 2; j < 4; j++) {
                float s = sacc[nt][j] * 0.125f;
                if (diag && (kt * 128 + nt * 8 + c0l + j - 2) > r0g + 8) s = -1e30f;
                sacc[nt][j] = s; mx1 = fmaxf(mx1, s);
            }
        }
        #pragma unroll
        for (int o = 1; o < 4; o <<= 1) {
            mx0 = fmaxf(mx0, __shfl_xor_sync(0xffffffffu, mx0, o));
            mx1 = fmaxf(mx1, __shfl_xor_sync(0xffffffffu, mx1, o));
        }
        float mn0 = fmaxf(m_[0], mx0), mn1 = fmaxf(m_[1], mx1);
        float cr0 = __expf(m_[0] - mn0), cr1 = __expf(m_[1] - mn1);
        float sum0 = 0.f, sum1 = 0.f;
        #pragma unroll
        for (int nt = 0; nt < 16; nt++) {
            float p0 = __expf(sacc[nt][0] - mn0), p1 = __expf(sacc[nt][1] - mn0);
            float p2 = __expf(sacc[nt][2] - mn1), p3 = __expf(sacc[nt][3] - mn1);
            sacc[nt][0] = p0; sacc[nt][1] = p1; sacc[nt][2] = p2; sacc[nt][3] = p3;
            sum0 += p0 + p1; sum1 += p2 + p3;
        }
        #pragma unroll
        for (int o = 1; o < 4; o <<= 1) {
            sum0 += __shfl_xor_sync(0xffffffffu, sum0, o);
            sum1 += __shfl_xor_sync(0xffffffffu, sum1, o);
        }
        l_[0] = l_[0] * cr0 + sum0; l_[1] = l_[1] * cr1 + sum1;
        m_[0] = mn0; m_[1] = mn1;
        #pragma unroll
        for (int d = 0; d < 8; d++) {
            oacc[d][0] *= cr0; oacc[d][1] *= cr0;
            oacc[d][2] *= cr1; oacc[d][3] *= cr1;
        }

        // ctx += P V (2-term, P split fp16 in registers)
        #pragma unroll
        for (int kvt = 0; kvt < 8; kvt++) {
            float p00 = sacc[2 * kvt][0],     p01 = sacc[2 * kvt][1];
            float p02 = sacc[2 * kvt][2],     p03 = sacc[2 * kvt][3];
            float p10 = sacc[2 * kvt + 1][0], p11 = sacc[2 * kvt + 1][1];
            float p12 = sacc[2 * kvt + 1][2], p13 = sacc[2 * kvt + 1][3];
            uint32_t pa_h[4], pa_l[4];
            pa_h[0] = packh(p00, p01); pa_h[1] = packh(p02, p03);
            pa_h[2] = packh(p10, p11); pa_h[3] = packh(p12, p13);
            float r00 = p00 - __half2float(__float2half_rn(p00));
            float r01 = p01 - __half2float(__float2half_rn(p01));
            float r02 = p02 - __half2float(__float2half_rn(p02));
            float r03 = p03 - __half2float(__float2half_rn(p03));
            float r10 = p10 - __half2float(__float2half_rn(p10));
            float r11 = p11 - __half2float(__float2half_rn(p11));
            float r12 = p12 - __half2float(__float2half_rn(p12));
            float r13 = p13 - __half2float(__float2half_rn(p13));
            pa_l[0] = packh(r00, r01); pa_l[1] = packh(r02, r03);
            pa_l[2] = packh(r10, r11); pa_l[3] = packh(r12, r13);

            #pragma unroll
            for (int ntp = 0; ntp < 4; ntp++) {
                uint32_t vh4[4];
                uint32_t off = (uint32_t)(ntp * 16 + ((lid >> 4) * 8) + (lid & 7)) * FROWV
                             + kvt * 32 + ((lid >> 3) & 1) * 16;
                ldsm4(vh4, stg + 18432 + off);
                mma_f16(oacc[2 * ntp],     pa_h, vh4[0], vh4[1]);
                mma_f16(oacc[2 * ntp],     pa_l, vh4[0], vh4[1]);
                mma_f16(oacc[2 * ntp + 1], pa_h, vh4[2], vh4[3]);
                mma_f16(oacc[2 * ntp + 1], pa_l, vh4[2], vh4[3]);
            }
        }
        __syncthreads();
    }

    const int b = bh / H_, h = bh - b * H_;
    float inv0 = 1.f / l_[0], inv1 = 1.f / l_[1];
    #pragma unroll
    for (int nt = 0; nt < 8; nt++) {
        const int d = nt * 8 + c0l;
        {
            float v0 = oacc[nt][0] * inv0, v1 = oacc[nt][1] * inv0;
            fp16 h0, l0, h1, l1;
            split_fp16(v0, h0, l0); split_fp16(v1, h1, l1);
            size_t o = ((size_t)(b * T_ + r0g)) * E_ + h * D_ + d;
            *(__half2*)&ctxh[o] = __halves2half2(h0, h1);
            *(__half2*)&ctxl[o] = __halves2half2(l0, l1);
        }
        {
            float v0 = oacc[nt][2] * inv1, v1 = oacc[nt][3] * inv1;
            fp16 h0, l0, h1, l1;
            split_fp16(v0, h0, l0); split_fp16(v1, h1, l1);
            size_t o = ((size_t)(b * T_ + r0g + 8)) * E_ + h * D_ + d;
            *(__half2*)&ctxh[o] = __halves2half2(h0, h1);
            *(__half2*)&ctxl[o] = __halves2half2(l0, l1);
        }
    }
}

// ---------------- launch ----------------
extern "C" void kernel_launch(void* const* d_in, const int* in_sizes, int n_in,
                              void* d_out, int out_size)
{
    const float* x    = (const float*)d_in[0];
    const float* wq   = (const float*)d_in[1];
    const float* wk   = (const float*)d_in[2];
    const float* wv   = (const float*)d_in[3];
    const float* wo   = (const float*)d_in[4];
    const float* bo   = (const float*)d_in[5];
    const float* ln1s = (const float*)d_in[6];
    const float* ln1b = (const float*)d_in[7];
    const float* ln2s = (const float*)d_in[8];
    const float* ln2b = (const float*)d_in[9];
    const float* w1   = (const float*)d_in[10];
    const float* b1   = (const float*)d_in[11];
    const float* w2   = (const float*)d_in[12];
    const float* b2   = (const float*)d_in[13];
    float* out = (float*)d_out;

    float *x2;
    fp16 *h1h, *h1l, *qh, *ql, *kh, *vth, *ctxh, *ctxl, *h2h, *h2l, *midh, *midl;
    fp16 *wqkvT, *woT, *w1T, *w2T;
    cudaGetSymbolAddress((void**)&x2,  g_x2);
    cudaGetSymbolAddress((void**)&h1h, g_h1h);  cudaGetSymbolAddress((void**)&h1l, g_h1l);
    cudaGetSymbolAddress((void**)&qh,  g_qh);   cudaGetSymbolAddress((void**)&ql,  g_ql);
    cudaGetSymbolAddress((void**)&kh,  g_kh);
    cudaGetSymbolAddress((void**)&vth, g_vth);
    cudaGetSymbolAddress((void**)&ctxh,g_ctxh); cudaGetSymbolAddress((void**)&ctxl,g_ctxl);
    cudaGetSymbolAddress((void**)&h2h, g_h2h);  cudaGetSymbolAddress((void**)&h2l, g_h2l);
    cudaGetSymbolAddress((void**)&midh,g_midh); cudaGetSymbolAddress((void**)&midl,g_midl);
    cudaGetSymbolAddress((void**)&wqkvT,g_wqkvT);
    cudaGetSymbolAddress((void**)&woT, g_woT);
    cudaGetSymbolAddress((void**)&w1T, g_w1T);
    cudaGetSymbolAddress((void**)&w2T, g_w2T);

    cudaFuncSetAttribute(flash_attn2, cudaFuncAttributeMaxDynamicSharedMemorySize, FA2_SMEM);
    cudaFuncSetAttribute(mma_gemm<EPI_QKV>,             cudaFuncAttributeMaxDynamicSharedMemorySize, GEMM_SMEM);
    cudaFuncSetAttribute(mma_gemm<EPI_BIAS_RESID>,      cudaFuncAttributeMaxDynamicSharedMemorySize, GEMM_SMEM);
    cudaFuncSetAttribute(mma_gemm<EPI_BIAS_GELU_SPLIT>, cudaFuncAttributeMaxDynamicSharedMemorySize, GEMM_SMEM);

    // weight transpose+round; wq/wk/wv stacked into [2304,768]
    wsplitT<<<dim3(E_/32,  E_/32), 256>>>(wq, wqkvT,            E_, E_);
    wsplitT<<<dim3(E_/32,  E_/32), 256>>>(wk, wqkvT + E_*E_,    E_, E_);
    wsplitT<<<dim3(E_/32,  E_/32), 256>>>(wv, wqkvT + 2*E_*E_,  E_, E_);
    wsplitT<<<dim3(E_/32,  E_/32), 256>>>(wo, woT, E_, E_);
    wsplitT<<<dim3(FF_/32, E_/32), 256>>>(w1, w1T, E_, FF_);
    wsplitT<<<dim3(E_/32, FF_/32), 256>>>(w2, w2T, FF_, E_);

    // LN1 -> h1 hi/lo
    ln_kernel<<<M_, 256>>>(x, ln1s, ln1b, h1h, h1l);

    // fused QKV -> Q hi/lo, K, Vt (fp16)
    mma_gemm<EPI_QKV><<<dim3(QKVN/128, M_/128), 256, GEMM_SMEM>>>(
        h1h, h1l, wqkvT, nullptr, nullptr, nullptr,
        qh, ql, kh, vth, nullptr, nullptr, QKVN, E_);

    // flash attention -> ctx fp16 hi/lo
    flash_attn2<<<dim3(T_/128, BH_), 256, FA2_SMEM>>>(qh, ql, kh, vth, ctxh, ctxl);

    // proj + bias + resid -> x2
    mma_gemm<EPI_BIAS_RESID><<<dim3(E_/128, M_/128), 256, GEMM_SMEM>>>(
        ctxh, ctxl, woT, bo, x, x2,
        nullptr, nullptr, nullptr, nullptr, nullptr, nullptr, E_, E_);

    // LN2 -> h2 hi/lo
    ln_kernel<<<M_, 256>>>(x2, ln2s, ln2b, h2h, h2l);

    // MLP1 (gelu) -> mid fp16 hi/lo
    mma_gemm<EPI_BIAS_GELU_SPLIT><<<dim3(FF_/128, M_/128), 256, GEMM_SMEM>>>(
        h2h, h2l, w1T, b1, nullptr, nullptr,
        nullptr, nullptr, nullptr, nullptr, midh, midl, FF_, E_);

    // MLP2 + bias + resid -> out
    mma_gemm<EPI_BIAS_RESID><<<dim3(E_/128, M_/128), 256, GEMM_SMEM>>>(
        midh, midl, w2T, b2, x2, out,
        nullptr, nullptr, nullptr, nullptr, nullptr, nullptr, E_, FF_);
}

// round 10
// speedup vs baseline: 2.2856x; 1.4446x over previous
#include <cuda_runtime.h>
#include <cuda_fp16.h>
#include <math.h>
#include <cstdint>

#define B_  2
#define T_  2048
#define E_  768
#define H_  12
#define D_  64
#define M_  (B_*T_)    // 4096
#define FF_ (4*E_)     // 3072
#define BH_ (B_*H_)    // 24
#define QKVN (3*E_)    // 2304

typedef __half fp16;

// ---------------- scratch ----------------
__device__ float g_x2[M_*E_];
__device__ fp16 g_h1[M_*E_];
__device__ fp16 g_q [M_*E_];                   // [B,H,T,D]
__device__ fp16 g_k [M_*E_];                   // [B,H,T,D]
__device__ fp16 g_vt[M_*E_];                   // [B,H,D,T]
__device__ fp16 g_ctx[M_*E_];
__device__ fp16 g_h2[M_*E_];
__device__ fp16 g_mid[(size_t)M_*FF_];
__device__ fp16 g_wqkvT[(size_t)QKVN*E_];
__device__ fp16 g_woT[E_*E_];
__device__ fp16 g_w1T[(size_t)E_*FF_];
__device__ fp16 g_w2T[(size_t)E_*FF_];

// ---------------- helpers ----------------
__device__ __forceinline__ uint32_t smem_u32(const void* p) {
    uint32_t a;
    asm("{ .reg .u64 t; cvta.to.shared.u64 t, %1; cvt.u32.u64 %0, t; }" : "=r"(a) : "l"(p));
    return a;
}
__device__ __forceinline__ void cpasync16(uint32_t dst, const void* src) {
    asm volatile("cp.async.ca.shared.global [%0], [%1], 16;" :: "r"(dst), "l"(src));
}
__device__ __forceinline__ void ldsm4(uint32_t* r, uint32_t addr) {
    asm volatile("ldmatrix.sync.aligned.m8n8.x4.shared.b16 {%0,%1,%2,%3}, [%4];"
        : "=r"(r[0]), "=r"(r[1]), "=r"(r[2]), "=r"(r[3]) : "r"(addr));
}
__device__ __forceinline__ void mma_f16(float* c, const uint32_t* a, uint32_t b0, uint32_t b1) {
    asm volatile("mma.sync.aligned.m16n8k16.row.col.f32.f16.f16.f32 "
        "{%0,%1,%2,%3}, {%4,%5,%6,%7}, {%8,%9}, {%0,%1,%2,%3};"
        : "+f"(c[0]), "+f"(c[1]), "+f"(c[2]), "+f"(c[3])
        : "r"(a[0]), "r"(a[1]), "r"(a[2]), "r"(a[3]), "r"(b0), "r"(b1));
}
__device__ __forceinline__ uint32_t packh(float a, float b) {
    __half2 t = __floats2half2_rn(a, b);
    return *(uint32_t*)&t;
}

// ---------------- weight transpose + round: w[K,N] -> wT fp16 [N,K] ----------------
__global__ void __launch_bounds__(256)
wsplitT(const float* __restrict__ w, fp16* __restrict__ hi, int K, int N)
{
    __shared__ float t[32][33];
    const int tx = threadIdx.x & 31, ty = threadIdx.x >> 5;
    const int n0 = blockIdx.x * 32, k0 = blockIdx.y * 32;
    #pragma unroll
    for (int i = 0; i < 32; i += 8)
        t[ty + i][tx] = w[(size_t)(k0 + ty + i) * N + n0 + tx];
    __syncthreads();
    #pragma unroll
    for (int i = 0; i < 32; i += 8)
        hi[(size_t)(n0 + ty + i) * K + k0 + tx] = __float2half_rn(t[tx][ty + i]);
}

// ---------------- LayerNorm (ddof=1) -> fp16 ----------------
__global__ void __launch_bounds__(256)
ln_kernel(const float* __restrict__ x, const float* __restrict__ sc,
          const float* __restrict__ sh, fp16* __restrict__ o16)
{
    int row = blockIdx.x;
    const float* xr = x + (size_t)row * E_;
    float s = 0.f, s2 = 0.f;
    for (int i = threadIdx.x; i < E_; i += 256) { float v = xr[i]; s += v; s2 += v * v; }
    __shared__ float rs[8], rs2[8];
    #pragma unroll
    for (int o = 16; o; o >>= 1) {
        s  += __shfl_xor_sync(0xffffffffu, s,  o);
        s2 += __shfl_xor_sync(0xffffffffu, s2, o);
    }
    if ((threadIdx.x & 31) == 0) { rs[threadIdx.x >> 5] = s; rs2[threadIdx.x >> 5] = s2; }
    __syncthreads();
    float ts = 0.f, ts2 = 0.f;
    #pragma unroll
    for (int i = 0; i < 8; i++) { ts += rs[i]; ts2 += rs2[i]; }
    float mean = ts * (1.f / E_);
    float var  = (ts2 - ts * mean) * (1.f / (E_ - 1));
    float rstd = rsqrtf(var + 1e-5f);
    for (int i = threadIdx.x; i < E_; i += 256) {
        float v = sc[i] * (xr[i] - mean) * rstd + sh[i];
        o16[(size_t)row * E_ + i] = __float2half_rn(v);
    }
}

// ---------------- warp-MMA GEMM: fp16 single-term, 2-stage cp.async ----------------
enum { EPI_QKV = 0, EPI_BIAS_RESID = 1, EPI_BIAS_GELU = 2 };

#define KCH     64
#define ROWB    144
#define TILE_B  (128*ROWB)      // 18432
#define STAGE_B (2*TILE_B)      // 36864 (A, B)
#define GEMM_SMEM (2*STAGE_B)   // 73728

template<int EPI>
__global__ void __launch_bounds__(256, 1)
mma_gemm(const fp16* __restrict__ A_g, const fp16* __restrict__ B_g,
         const float* __restrict__ bias, const float* __restrict__ resid,
         float* __restrict__ C,
         fp16* __restrict__ Qo, fp16* __restrict__ Ko, fp16* __restrict__ Vto,
         fp16* __restrict__ C16,
         int N, int K)
{
    extern __shared__ char sm[];
    const uint32_t sbase = smem_u32(sm);
    const int tid = threadIdx.x, wid = tid >> 5, lid = tid & 31;
    const int m0 = blockIdx.y * 128, n0 = blockIdx.x * 128;
    const int wm = wid >> 2, wn = wid & 3;

    const int lrow = tid >> 3;
    const int lcb  = (tid & 7) * 16;

    float acc[4][4][4] = {};

    const fp16* gs[2] = {A_g, B_g};
    const int   r0s[2] = {m0, n0};

    auto issue = [&](int c) {
        const int k0 = c * KCH;
        const uint32_t sb = sbase + (uint32_t)(c & 1) * STAGE_B;
        #pragma unroll
        for (int t = 0; t < 2; t++) {
            const char* g = (const char*)(gs[t] + (size_t)(r0s[t] + lrow) * K + k0) + lcb;
            uint32_t d = sb + t * TILE_B + lrow * ROWB + lcb;
            #pragma unroll
            for (int i = 0; i < 4; i++)
                cpasync16(d + i * 32 * ROWB, g + (size_t)i * 32 * K * 2);
        }
        asm volatile("cp.async.commit_group;");
    };

    const int NC = K / KCH;
    issue(0);

    const int am = (lid >> 3);
    const uint32_t aRow = wm * 64 + (am & 1) * 8 + (lid & 7);
    const uint32_t aColH = (am >> 1) * 16;
    const uint32_t bRowBase = wn * 32 + (lid & 7);
    const uint32_t bNt = (am >> 1);
    const uint32_t bColH = (am & 1) * 16;

    for (int c = 0; c < NC; c++) {
        if (c + 1 < NC) { issue(c + 1); asm volatile("cp.async.wait_group 1;"); }
        else            { asm volatile("cp.async.wait_group 0;"); }
        __syncthreads();

        const uint32_t sb = sbase + (uint32_t)(c & 1) * STAGE_B;
        const uint32_t aB = sb, bB = sb + TILE_B;

        #pragma unroll
        for (int ks = 0; ks < 4; ks++) {
            uint32_t bh[2][4];
            #pragma unroll
            for (int p = 0; p < 2; p++) {
                uint32_t row = bRowBase + (p * 2 + bNt) * 8;
                uint32_t off = row * ROWB + ks * 32 + bColH;
                ldsm4(bh[p], bB + off);
            }
            #pragma unroll
            for (int mt = 0; mt < 4; mt++) {
                uint32_t ah[4];
                uint32_t off = (aRow + mt * 16) * ROWB + ks * 32 + aColH;
                ldsm4(ah, aB + off);
                #pragma unroll
                for (int nt = 0; nt < 4; nt++) {
                    const int p = nt >> 1, q = (nt & 1) * 2;
                    mma_f16(acc[mt][nt], ah, bh[p][q], bh[p][q + 1]);
                }
            }
        }
        __syncthreads();
    }

    #pragma unroll
    for (int mt = 0; mt < 4; mt++) {
        #pragma unroll
        for (int nt = 0; nt < 4; nt++) {
            const int r0 = m0 + wm * 64 + mt * 16 + (lid >> 2);
            const int cc = n0 + wn * 32 + nt * 8 + (lid & 3) * 2;
            #pragma unroll
            for (int hh = 0; hh < 2; hh++) {
                const int r = r0 + hh * 8;
                float v0 = acc[mt][nt][hh * 2], v1 = acc[mt][nt][hh * 2 + 1];
                if (EPI == EPI_QKV) {
                    const int bb = r >> 11, tt = r & (T_ - 1);
                    int which = (cc >= 2 * E_) ? 2 : (cc >= E_ ? 1 : 0);
                    int nn = cc - which * E_;
                    int hx = nn >> 6, d = nn & 63;
                    if (which == 2) {
                        size_t o = ((size_t)(bb * H_ + hx) * D_ + d) * T_ + tt;
                        Vto[o]      = __float2half_rn(v0);
                        Vto[o + T_] = __float2half_rn(v1);
                    } else {
                        size_t o = ((size_t)(bb * H_ + hx) * T_ + tt) * D_ + d;
                        fp16* dst = (which == 0) ? Qo : Ko;
                        *(__half2*)&dst[o] = __floats2half2_rn(v0, v1);
                    }
                } else if (EPI == EPI_BIAS_RESID) {
                    size_t o = (size_t)r * N + cc;
                    float2 bs = *(const float2*)&bias[cc];
                    float2 rs = *(const float2*)&resid[o];
                    *(float2*)&C[o] = make_float2(v0 + bs.x + rs.x, v1 + bs.y + rs.y);
                } else {
                    size_t o = (size_t)r * N + cc;
                    float2 bs = *(const float2*)&bias[cc];
                    float vv[2] = {v0 + bs.x, v1 + bs.y};
                    #pragma unroll
                    for (int j = 0; j < 2; j++) {
                        float v = vv[j];
                        float u = 0.7978845608028654f * (v + 0.044715f * v * v * v);
                        vv[j] = 0.5f * v * (1.f + tanhf(u));
                    }
                    *(__half2*)&C16[o] = __floats2half2_rn(vv[0], vv[1]);
                }
            }
        }
    }
}

// ---------------- tensor-core flash attention: fp16 single-term ----------------
#define FROWK 144
#define FROWV 272
#define FQ    0
#define FSTG0 18432
#define FSTGB 35840          // K 18432 + V 17408
#define FA2_SMEM (18432 + 2*FSTGB)   // 90112

__global__ void __launch_bounds__(256, 1)
flash_attn2(const fp16* __restrict__ Q_g, const fp16* __restrict__ K_g,
            const fp16* __restrict__ Vt_g, fp16* __restrict__ ctx)
{
    extern __shared__ char sm[];
    const uint32_t sb = smem_u32(sm);
    const int tid = threadIdx.x, wid = tid >> 5, lid = tid & 31;
    const int bh = blockIdx.y;
    const int mtile = (gridDim.x - 1) - blockIdx.x;
    const int q0 = mtile * 128;

    const fp16* Qb = Q_g + (size_t)bh * T_ * D_;
    const fp16* Kb = K_g + (size_t)bh * T_ * D_;
    const fp16* Vb = Vt_g + (size_t)bh * D_ * T_;

    // Q tile
    {
        const int row = tid >> 1, half = tid & 1;
        const char* g = (const char*)(Qb + (size_t)(q0 + row) * D_ + half * 32);
        uint32_t d = sb + FQ + row * FROWK + half * 64;
        #pragma unroll
        for (int i = 0; i < 4; i++) cpasync16(d + i * 16, g + i * 16);
    }

    auto issueKV = [&](int stage, int kvt) {
        const int kv0 = kvt * 128;
        const uint32_t s0 = sb + FSTG0 + (uint32_t)stage * FSTGB;
        {
            const int row = tid >> 1, half = tid & 1;
            const char* g = (const char*)(Kb + (size_t)(kv0 + row) * D_ + half * 32);
            uint32_t d = s0 + row * FROWK + half * 64;
            #pragma unroll
            for (int i = 0; i < 4; i++) cpasync16(d + i * 16, g + i * 16);
        }
        {
            const int row = tid >> 2, qt = tid & 3;
            const char* g = (const char*)(Vb + (size_t)row * T_ + kv0 + qt * 32);
            uint32_t d = s0 + 18432 + row * FROWV + qt * 64;
            #pragma unroll
            for (int i = 0; i < 4; i++) cpasync16(d + i * 16, g + i * 16);
        }
        asm volatile("cp.async.commit_group;");
    };

    issueKV(0, 0);

    const int am = lid >> 3;
    uint32_t qf[4][4];
    float m_[2] = {-1e30f, -1e30f}, l_[2] = {0.f, 0.f};
    float oacc[8][4] = {};

    const int r0g = q0 + wid * 16 + (lid >> 2);
    const int c0l = (lid & 3) * 2;

    for (int kt = 0; kt <= mtile; kt++) {
        if (kt + 1 <= mtile) { issueKV((kt + 1) & 1, kt + 1); asm volatile("cp.async.wait_group 1;"); }
        else                 { asm volatile("cp.async.wait_group 0;"); }
        __syncthreads();

        if (kt == 0) {
            const uint32_t rowq = wid * 16 + (am & 1) * 8 + (lid & 7);
            #pragma unroll
            for (int ks = 0; ks < 4; ks++) {
                uint32_t off = rowq * FROWK + ks * 32 + (am >> 1) * 16;
                ldsm4(qf[ks], sb + FQ + off);
            }
        }

        const uint32_t stg = sb + FSTG0 + (uint32_t)(kt & 1) * FSTGB;

        // S = Q K^T (single term)
        float sacc[16][4] = {};
        #pragma unroll
        for (int ks = 0; ks < 4; ks++) {
            #pragma unroll
            for (int ntp = 0; ntp < 8; ntp++) {
                uint32_t kh4[4];
                uint32_t off = (uint32_t)(ntp * 16 + ((lid >> 4) * 8) + (lid & 7)) * FROWK
                             + ks * 32 + ((lid >> 3) & 1) * 16;
                ldsm4(kh4, stg + off);
                mma_f16(sacc[2 * ntp],     qf[ks], kh4[0], kh4[1]);
                mma_f16(sacc[2 * ntp + 1], qf[ks], kh4[2], kh4[3]);
            }
        }

        // online softmax
        const bool diag = (kt == mtile);
        float mx0 = -1e30f, mx1 = -1e30f;
        #pragma unroll
        for (int nt = 0; nt < 16; nt++) {
            #pragma unroll
            for (int j = 0; j < 2; j++) {
                float s = sacc[nt][j] * 0.125f;
                if (diag && (kt * 128 + nt * 8 + c0l + j) > r0g) s = -1e30f;
                sacc[nt][j] = s; mx0 = fmaxf(mx0, s);
            }
            #pragma unroll
            for (int j = 2; j < 4; j++) {
                float s = sacc[nt][j] * 0.125f;
                if (diag && (kt * 128 + nt * 8 + c0l + j - 2) > r0g + 8) s = -1e30f;
                sacc[nt][j] = s; mx1 = fmaxf(mx1, s);
            }
        }
        #pragma unroll
        for (int o = 1; o < 4; o <<= 1) {
            mx0 = fmaxf(mx0, __shfl_xor_sync(0xffffffffu, mx0, o));
            mx1 = fmaxf(mx1, __shfl_xor_sync(0xffffffffu, mx1, o));
        }
        float mn0 = fmaxf(m_[0], mx0), mn1 = fmaxf(m_[1], mx1);
        float cr0 = __expf(m_[0] - mn0), cr1 = __expf(m_[1] - mn1);
        float sum0 = 0.f, sum1 = 0.f;
        #pragma unroll
        for (int nt = 0; nt < 16; nt++) {
            float p0 = __expf(sacc[nt][0] - mn0), p1 = __expf(sacc[nt][1] - mn0);
            float p2 = __expf(sacc[nt][2] - mn1), p3 = __expf(sacc[nt][3] - mn1);
            sacc[nt][0] = p0; sacc[nt][1] = p1; sacc[nt][2] = p2; sacc[nt][3] = p3;
            sum0 += p0 + p1; sum1 += p2 + p3;
        }
        #pragma unroll
        for (int o = 1; o < 4; o <<= 1) {
            sum0 += __shfl_xor_sync(0xffffffffu, sum0, o);
            sum1 += __shfl_xor_sync(0xffffffffu, sum1, o);
        }
        l_[0] = l_[0] * cr0 + sum0; l_[1] = l_[1] * cr1 + sum1;
        m_[0] = mn0; m_[1] = mn1;
        #pragma unroll
        for (int d = 0; d < 8; d++) {
            oacc[d][0] *= cr0; oacc[d][1] *= cr0;
            oacc[d][2] *= cr1; oacc[d][3] *= cr1;
        }

        // ctx += P V (single term)
        #pragma unroll
        for (int kvt = 0; kvt < 8; kvt++) {
            uint32_t pa[4];
            pa[0] = packh(sacc[2 * kvt][0],     sacc[2 * kvt][1]);
            pa[1] = packh(sacc[2 * kvt][2],     sacc[2 * kvt][3]);
            pa[2] = packh(sacc[2 * kvt + 1][0], sacc[2 * kvt + 1][1]);
            pa[3] = packh(sacc[2 * kvt + 1][2], sacc[2 * kvt + 1][3]);

            #pragma unroll
            for (int ntp = 0; ntp < 4; ntp++) {
                uint32_t vh4[4];
                uint32_t off = (uint32_t)(ntp * 16 + ((lid >> 4) * 8) + (lid & 7)) * FROWV
                             + kvt * 32 + ((lid >> 3) & 1) * 16;
                ldsm4(vh4, stg + 18432 + off);
                mma_f16(oacc[2 * ntp],     pa, vh4[0], vh4[1]);
                mma_f16(oacc[2 * ntp + 1], pa, vh4[2], vh4[3]);
            }
        }
        __syncthreads();
    }

    const int b = bh / H_, h = bh - b * H_;
    float inv0 = 1.f / l_[0], inv1 = 1.f / l_[1];
    #pragma unroll
    for (int nt = 0; nt < 8; nt++) {
        const int d = nt * 8 + c0l;
        {
            size_t o = ((size_t)(b * T_ + r0g)) * E_ + h * D_ + d;
            *(__half2*)&ctx[o] = __floats2half2_rn(oacc[nt][0] * inv0, oacc[nt][1] * inv0);
        }
        {
            size_t o = ((size_t)(b * T_ + r0g + 8)) * E_ + h * D_ + d;
            *(__half2*)&ctx[o] = __floats2half2_rn(oacc[nt][2] * inv1, oacc[nt][3] * inv1);
        }
    }
}

// ---------------- launch ----------------
extern "C" void kernel_launch(void* const* d_in, const int* in_sizes, int n_in,
                              void* d_out, int out_size)
{
    const float* x    = (const float*)d_in[0];
    const float* wq   = (const float*)d_in[1];
    const float* wk   = (const float*)d_in[2];
    const float* wv   = (const float*)d_in[3];
    const float* wo   = (const float*)d_in[4];
    const float* bo   = (const float*)d_in[5];
    const float* ln1s = (const float*)d_in[6];
    const float* ln1b = (const float*)d_in[7];
    const float* ln2s = (const float*)d_in[8];
    const float* ln2b = (const float*)d_in[9];
    const float* w1   = (const float*)d_in[10];
    const float* b1   = (const float*)d_in[11];
    const float* w2   = (const float*)d_in[12];
    const float* b2   = (const float*)d_in[13];
    float* out = (float*)d_out;

    float *x2;
    fp16 *h1, *q, *k, *vt, *ctx, *h2, *mid;
    fp16 *wqkvT, *woT, *w1T, *w2T;
    cudaGetSymbolAddress((void**)&x2,  g_x2);
    cudaGetSymbolAddress((void**)&h1,  g_h1);
    cudaGetSymbolAddress((void**)&q,   g_q);
    cudaGetSymbolAddress((void**)&k,   g_k);
    cudaGetSymbolAddress((void**)&vt,  g_vt);
    cudaGetSymbolAddress((void**)&ctx, g_ctx);
    cudaGetSymbolAddress((void**)&h2,  g_h2);
    cudaGetSymbolAddress((void**)&mid, g_mid);
    cudaGetSymbolAddress((void**)&wqkvT, g_wqkvT);
    cudaGetSymbolAddress((void**)&woT, g_woT);
    cudaGetSymbolAddress((void**)&w1T, g_w1T);
    cudaGetSymbolAddress((void**)&w2T, g_w2T);

    cudaFuncSetAttribute(flash_attn2, cudaFuncAttributeMaxDynamicSharedMemorySize, FA2_SMEM);
    cudaFuncSetAttribute(mma_gemm<EPI_QKV>,        cudaFuncAttributeMaxDynamicSharedMemorySize, GEMM_SMEM);
    cudaFuncSetAttribute(mma_gemm<EPI_BIAS_RESID>, cudaFuncAttributeMaxDynamicSharedMemorySize, GEMM_SMEM);
    cudaFuncSetAttribute(mma_gemm<EPI_BIAS_GELU>,  cudaFuncAttributeMaxDynamicSharedMemorySize, GEMM_SMEM);

    // weight transpose+round; wq/wk/wv stacked into [2304,768]
    wsplitT<<<dim3(E_/32,  E_/32), 256>>>(wq, wqkvT,            E_, E_);
    wsplitT<<<dim3(E_/32,  E_/32), 256>>>(wk, wqkvT + E_*E_,    E_, E_);
    wsplitT<<<dim3(E_/32,  E_/32), 256>>>(wv, wqkvT + 2*E_*E_,  E_, E_);
    wsplitT<<<dim3(E_/32,  E_/32), 256>>>(wo, woT, E_, E_);
    wsplitT<<<dim3(FF_/32, E_/32), 256>>>(w1, w1T, E_, FF_);
    wsplitT<<<dim3(E_/32, FF_/32), 256>>>(w2, w2T, FF_, E_);

    // LN1 -> h1 (fp16)
    ln_kernel<<<M_, 256>>>(x, ln1s, ln1b, h1);

    // fused QKV -> Q, K, Vt (fp16)
    mma_gemm<EPI_QKV><<<dim3(QKVN/128, M_/128), 256, GEMM_SMEM>>>(
        h1, wqkvT, nullptr, nullptr, nullptr, q, k, vt, nullptr, QKVN, E_);

    // flash attention -> ctx fp16
    flash_attn2<<<dim3(T_/128, BH_), 256, FA2_SMEM>>>(q, k, vt, ctx);

    // proj + bias + resid -> x2
    mma_gemm<EPI_BIAS_RESID><<<dim3(E_/128, M_/128), 256, GEMM_SMEM>>>(
        ctx, woT, bo, x, x2, nullptr, nullptr, nullptr, nullptr, E_, E_);

    // LN2 -> h2 (fp16)
    ln_kernel<<<M_, 256>>>(x2, ln2s, ln2b, h2);

    // MLP1 (gelu) -> mid fp16
    mma_gemm<EPI_BIAS_GELU><<<dim3(FF_/128, M_/128), 256, GEMM_SMEM>>>(
        h2, w1T, b1, nullptr, nullptr, nullptr, nullptr, nullptr, mid, FF_, E_);

    // MLP2 + bias + resid -> out
    mma_gemm<EPI_BIAS_RESID><<<dim3(E_/128, M_/128), 256, GEMM_SMEM>>>(
        mid, w2T, b2, x2, out, nullptr, nullptr, nullptr, nullptr, E_, FF_);
}

// round 11
// speedup vs baseline: 2.5706x; 1.1247x over previous
#include <cuda_runtime.h>
#include <cuda_fp16.h>
#include <math.h>
#include <cstdint>

#define B_  2
#define T_  2048
#define E_  768
#define H_  12
#define D_  64
#define M_  (B_*T_)    // 4096
#define FF_ (4*E_)     // 3072
#define BH_ (B_*H_)    // 24
#define QKVN (3*E_)    // 2304

typedef __half fp16;

// ---------------- scratch ----------------
__device__ float g_x2[M_*E_];
__device__ fp16 g_h1[M_*E_];
__device__ fp16 g_q [M_*E_];                   // [B,H,T,D]
__device__ fp16 g_k [M_*E_];                   // [B,H,T,D]
__device__ fp16 g_vt[M_*E_];                   // [B,H,D,T]
__device__ fp16 g_ctx[M_*E_];
__device__ fp16 g_h2[M_*E_];
__device__ fp16 g_mid[(size_t)M_*FF_];
__device__ fp16 g_wqkvT[(size_t)QKVN*E_];
__device__ fp16 g_woT[E_*E_];
__device__ fp16 g_w1T[(size_t)E_*FF_];
__device__ fp16 g_w2T[(size_t)E_*FF_];

// ---------------- helpers ----------------
__device__ __forceinline__ uint32_t smem_u32(const void* p) {
    uint32_t a;
    asm("{ .reg .u64 t; cvta.to.shared.u64 t, %1; cvt.u32.u64 %0, t; }" : "=r"(a) : "l"(p));
    return a;
}
__device__ __forceinline__ void cpasync16(uint32_t dst, const void* src) {
    asm volatile("cp.async.ca.shared.global [%0], [%1], 16;" :: "r"(dst), "l"(src));
}
__device__ __forceinline__ void ldsm4(uint32_t* r, uint32_t addr) {
    asm volatile("ldmatrix.sync.aligned.m8n8.x4.shared.b16 {%0,%1,%2,%3}, [%4];"
        : "=r"(r[0]), "=r"(r[1]), "=r"(r[2]), "=r"(r[3]) : "r"(addr));
}
__device__ __forceinline__ void mma_f16(float* c, const uint32_t* a, uint32_t b0, uint32_t b1) {
    asm volatile("mma.sync.aligned.m16n8k16.row.col.f32.f16.f16.f32 "
        "{%0,%1,%2,%3}, {%4,%5,%6,%7}, {%8,%9}, {%0,%1,%2,%3};"
        : "+f"(c[0]), "+f"(c[1]), "+f"(c[2]), "+f"(c[3])
        : "r"(a[0]), "r"(a[1]), "r"(a[2]), "r"(a[3]), "r"(b0), "r"(b1));
}
__device__ __forceinline__ uint32_t packh(float a, float b) {
    __half2 t = __floats2half2_rn(a, b);
    return *(uint32_t*)&t;
}

// ---------------- weight transpose + round: w[K,N] -> wT fp16 [N,K] ----------------
__global__ void __launch_bounds__(256)
wsplitT(const float* __restrict__ w, fp16* __restrict__ hi, int K, int N)
{
    __shared__ float t[32][33];
    const int tx = threadIdx.x & 31, ty = threadIdx.x >> 5;
    const int n0 = blockIdx.x * 32, k0 = blockIdx.y * 32;
    #pragma unroll
    for (int i = 0; i < 32; i += 8)
        t[ty + i][tx] = w[(size_t)(k0 + ty + i) * N + n0 + tx];
    __syncthreads();
    #pragma unroll
    for (int i = 0; i < 32; i += 8)
        hi[(size_t)(n0 + ty + i) * K + k0 + tx] = __float2half_rn(t[tx][ty + i]);
}

// four E x E weights in one launch (z selects wq/wk/wv/wo)
__global__ void __launch_bounds__(256)
wsplitT4(const float* __restrict__ wqp, const float* __restrict__ wkp,
         const float* __restrict__ wvp, const float* __restrict__ wop,
         fp16* __restrict__ hqkv, fp16* __restrict__ hwo)
{
    const int z = blockIdx.z;
    const float* w = (z == 0) ? wqp : (z == 1) ? wkp : (z == 2) ? wvp : wop;
    fp16* hi = (z < 3) ? hqkv + (size_t)z * E_ * E_ : hwo;
    __shared__ float t[32][33];
    const int tx = threadIdx.x & 31, ty = threadIdx.x >> 5;
    const int n0 = blockIdx.x * 32, k0 = blockIdx.y * 32;
    #pragma unroll
    for (int i = 0; i < 32; i += 8)
        t[ty + i][tx] = w[(size_t)(k0 + ty + i) * E_ + n0 + tx];
    __syncthreads();
    #pragma unroll
    for (int i = 0; i < 32; i += 8)
        hi[(size_t)(n0 + ty + i) * E_ + k0 + tx] = __float2half_rn(t[tx][ty + i]);
}

// ---------------- LayerNorm (ddof=1) -> fp16 ----------------
__global__ void __launch_bounds__(256)
ln_kernel(const float* __restrict__ x, const float* __restrict__ sc,
          const float* __restrict__ sh, fp16* __restrict__ o16)
{
    int row = blockIdx.x;
    const float* xr = x + (size_t)row * E_;
    float s = 0.f, s2 = 0.f;
    for (int i = threadIdx.x; i < E_; i += 256) { float v = xr[i]; s += v; s2 += v * v; }
    __shared__ float rs[8], rs2[8];
    #pragma unroll
    for (int o = 16; o; o >>= 1) {
        s  += __shfl_xor_sync(0xffffffffu, s,  o);
        s2 += __shfl_xor_sync(0xffffffffu, s2, o);
    }
    if ((threadIdx.x & 31) == 0) { rs[threadIdx.x >> 5] = s; rs2[threadIdx.x >> 5] = s2; }
    __syncthreads();
    float ts = 0.f, ts2 = 0.f;
    #pragma unroll
    for (int i = 0; i < 8; i++) { ts += rs[i]; ts2 += rs2[i]; }
    float mean = ts * (1.f / E_);
    float var  = (ts2 - ts * mean) * (1.f / (E_ - 1));
    float rstd = rsqrtf(var + 1e-5f);
    for (int i = threadIdx.x; i < E_; i += 256) {
        float v = sc[i] * (xr[i] - mean) * rstd + sh[i];
        o16[(size_t)row * E_ + i] = __float2half_rn(v);
    }
}

// ---------------- warp-MMA GEMM: fp16 single-term, 2-stage cp.async, occ=2 ----------------
enum { EPI_QKV = 0, EPI_BIAS_RESID = 1, EPI_BIAS_GELU = 2 };

#define KCH     64
#define ROWB    144
#define TILE_B  (128*ROWB)      // 18432
#define STAGE_B (2*TILE_B)      // 36864 (A, B)
#define GEMM_SMEM (2*STAGE_B)   // 73728

template<int EPI>
__global__ void __launch_bounds__(256, 2)
mma_gemm(const fp16* __restrict__ A_g, const fp16* __restrict__ B_g,
         const float* __restrict__ bias, const float* __restrict__ resid,
         float* __restrict__ C,
         fp16* __restrict__ Qo, fp16* __restrict__ Ko, fp16* __restrict__ Vto,
         fp16* __restrict__ C16,
         int N, int K)
{
    extern __shared__ char sm[];
    const uint32_t sbase = smem_u32(sm);
    const int tid = threadIdx.x, wid = tid >> 5, lid = tid & 31;
    const int m0 = blockIdx.y * 128, n0 = blockIdx.x * 128;
    const int wm = wid >> 2, wn = wid & 3;

    const int lrow = tid >> 3;
    const int lcb  = (tid & 7) * 16;

    float acc[4][4][4] = {};

    const fp16* gs[2] = {A_g, B_g};
    const int   r0s[2] = {m0, n0};

    auto issue = [&](int c) {
        const int k0 = c * KCH;
        const uint32_t sb = sbase + (uint32_t)(c & 1) * STAGE_B;
        #pragma unroll
        for (int t = 0; t < 2; t++) {
            const char* g = (const char*)(gs[t] + (size_t)(r0s[t] + lrow) * K + k0) + lcb;
            uint32_t d = sb + t * TILE_B + lrow * ROWB + lcb;
            #pragma unroll
            for (int i = 0; i < 4; i++)
                cpasync16(d + i * 32 * ROWB, g + (size_t)i * 32 * K * 2);
        }
        asm volatile("cp.async.commit_group;");
    };

    const int NC = K / KCH;
    issue(0);

    const int am = (lid >> 3);
    const uint32_t aRow = wm * 64 + (am & 1) * 8 + (lid & 7);
    const uint32_t aColH = (am >> 1) * 16;
    const uint32_t bRowBase = wn * 32 + (lid & 7);
    const uint32_t bNt = (am >> 1);
    const uint32_t bColH = (am & 1) * 16;

    for (int c = 0; c < NC; c++) {
        if (c + 1 < NC) { issue(c + 1); asm volatile("cp.async.wait_group 1;"); }
        else            { asm volatile("cp.async.wait_group 0;"); }
        __syncthreads();

        const uint32_t sb = sbase + (uint32_t)(c & 1) * STAGE_B;
        const uint32_t aB = sb, bB = sb + TILE_B;

        #pragma unroll
        for (int ks = 0; ks < 4; ks++) {
            uint32_t bh[2][4];
            #pragma unroll
            for (int p = 0; p < 2; p++) {
                uint32_t row = bRowBase + (p * 2 + bNt) * 8;
                uint32_t off = row * ROWB + ks * 32 + bColH;
                ldsm4(bh[p], bB + off);
            }
            #pragma unroll
            for (int mt = 0; mt < 4; mt++) {
                uint32_t ah[4];
                uint32_t off = (aRow + mt * 16) * ROWB + ks * 32 + aColH;
                ldsm4(ah, aB + off);
                #pragma unroll
                for (int nt = 0; nt < 4; nt++) {
                    const int p = nt >> 1, q = (nt & 1) * 2;
                    mma_f16(acc[mt][nt], ah, bh[p][q], bh[p][q + 1]);
                }
            }
        }
        __syncthreads();
    }

    #pragma unroll
    for (int mt = 0; mt < 4; mt++) {
        #pragma unroll
        for (int nt = 0; nt < 4; nt++) {
            const int r0 = m0 + wm * 64 + mt * 16 + (lid >> 2);
            const int cc = n0 + wn * 32 + nt * 8 + (lid & 3) * 2;
            #pragma unroll
            for (int hh = 0; hh < 2; hh++) {
                const int r = r0 + hh * 8;
                float v0 = acc[mt][nt][hh * 2], v1 = acc[mt][nt][hh * 2 + 1];
                if (EPI == EPI_QKV) {
                    const int bb = r >> 11, tt = r & (T_ - 1);
                    int which = (cc >= 2 * E_) ? 2 : (cc >= E_ ? 1 : 0);
                    int nn = cc - which * E_;
                    int hx = nn >> 6, d = nn & 63;
                    if (which == 2) {
                        size_t o = ((size_t)(bb * H_ + hx) * D_ + d) * T_ + tt;
                        Vto[o]      = __float2half_rn(v0);
                        Vto[o + T_] = __float2half_rn(v1);
                    } else {
                        size_t o = ((size_t)(bb * H_ + hx) * T_ + tt) * D_ + d;
                        fp16* dst = (which == 0) ? Qo : Ko;
                        *(__half2*)&dst[o] = __floats2half2_rn(v0, v1);
                    }
                } else if (EPI == EPI_BIAS_RESID) {
                    size_t o = (size_t)r * N + cc;
                    float2 bs = *(const float2*)&bias[cc];
                    float2 rs = *(const float2*)&resid[o];
                    *(float2*)&C[o] = make_float2(v0 + bs.x + rs.x, v1 + bs.y + rs.y);
                } else {
                    size_t o = (size_t)r * N + cc;
                    float2 bs = *(const float2*)&bias[cc];
                    float vv[2] = {v0 + bs.x, v1 + bs.y};
                    #pragma unroll
                    for (int j = 0; j < 2; j++) {
                        float v = vv[j];
                        float u = 0.7978845608028654f * (v + 0.044715f * v * v * v);
                        vv[j] = 0.5f * v * (1.f + tanhf(u));
                    }
                    *(__half2*)&C16[o] = __floats2half2_rn(vv[0], vv[1]);
                }
            }
        }
    }
}

// ---------------- tensor-core flash attention: fp16 single-term ----------------
#define FROWK 144
#define FROWV 272
#define FQ    0
#define FSTG0 18432
#define FSTGB 35840          // K 18432 + V 17408
#define FA2_SMEM (18432 + 2*FSTGB)   // 90112

__global__ void __launch_bounds__(256, 1)
flash_attn2(const fp16* __restrict__ Q_g, const fp16* __restrict__ K_g,
            const fp16* __restrict__ Vt_g, fp16* __restrict__ ctx)
{
    extern __shared__ char sm[];
    const uint32_t sb = smem_u32(sm);
    const int tid = threadIdx.x, wid = tid >> 5, lid = tid & 31;
    const int bh = blockIdx.y;
    const int mtile = (gridDim.x - 1) - blockIdx.x;
    const int q0 = mtile * 128;

    const fp16* Qb = Q_g + (size_t)bh * T_ * D_;
    const fp16* Kb = K_g + (size_t)bh * T_ * D_;
    const fp16* Vb = Vt_g + (size_t)bh * D_ * T_;

    {
        const int row = tid >> 1, half = tid & 1;
        const char* g = (const char*)(Qb + (size_t)(q0 + row) * D_ + half * 32);
        uint32_t d = sb + FQ + row * FROWK + half * 64;
        #pragma unroll
        for (int i = 0; i < 4; i++) cpasync16(d + i * 16, g + i * 16);
    }

    auto issueKV = [&](int stage, int kvt) {
        const int kv0 = kvt * 128;
        const uint32_t s0 = sb + FSTG0 + (uint32_t)stage * FSTGB;
        {
            const int row = tid >> 1, half = tid & 1;
            const char* g = (const char*)(Kb + (size_t)(kv0 + row) * D_ + half * 32);
            uint32_t d = s0 + row * FROWK + half * 64;
            #pragma unroll
            for (int i = 0; i < 4; i++) cpasync16(d + i * 16, g + i * 16);
        }
        {
            const int row = tid >> 2, qt = tid & 3;
            const char* g = (const char*)(Vb + (size_t)row * T_ + kv0 + qt * 32);
            uint32_t d = s0 + 18432 + row * FROWV + qt * 64;
            #pragma unroll
            for (int i = 0; i < 4; i++) cpasync16(d + i * 16, g + i * 16);
        }
        asm volatile("cp.async.commit_group;");
    };

    issueKV(0, 0);

    const int am = lid >> 3;
    uint32_t qf[4][4];
    float m_[2] = {-1e30f, -1e30f}, l_[2] = {0.f, 0.f};
    float oacc[8][4] = {};

    const int r0g = q0 + wid * 16 + (lid >> 2);
    const int c0l = (lid & 3) * 2;

    for (int kt = 0; kt <= mtile; kt++) {
        if (kt + 1 <= mtile) { issueKV((kt + 1) & 1, kt + 1); asm volatile("cp.async.wait_group 1;"); }
        else                 { asm volatile("cp.async.wait_group 0;"); }
        __syncthreads();

        if (kt == 0) {
            const uint32_t rowq = wid * 16 + (am & 1) * 8 + (lid & 7);
            #pragma unroll
            for (int ks = 0; ks < 4; ks++) {
                uint32_t off = rowq * FROWK + ks * 32 + (am >> 1) * 16;
                ldsm4(qf[ks], sb + FQ + off);
            }
        }

        const uint32_t stg = sb + FSTG0 + (uint32_t)(kt & 1) * FSTGB;

        float sacc[16][4] = {};
        #pragma unroll
        for (int ks = 0; ks < 4; ks++) {
            #pragma unroll
            for (int ntp = 0; ntp < 8; ntp++) {
                uint32_t kh4[4];
                uint32_t off = (uint32_t)(ntp * 16 + ((lid >> 4) * 8) + (lid & 7)) * FROWK
                             + ks * 32 + ((lid >> 3) & 1) * 16;
                ldsm4(kh4, stg + off);
                mma_f16(sacc[2 * ntp],     qf[ks], kh4[0], kh4[1]);
                mma_f16(sacc[2 * ntp + 1], qf[ks], kh4[2], kh4[3]);
            }
        }

        const bool diag = (kt == mtile);
        float mx0 = -1e30f, mx1 = -1e30f;
        #pragma unroll
        for (int nt = 0; nt < 16; nt++) {
            #pragma unroll
            for (int j = 0; j < 2; j++) {
                float s = sacc[nt][j] * 0.125f;
                if (diag && (kt * 128 + nt * 8 + c0l + j) > r0g) s = -1e30f;
                sacc[nt][j] = s; mx0 = fmaxf(mx0, s);
            }
            #pragma unroll
            for (int j = 2; j < 4; j++) {
                float s = sacc[nt][j] * 0.125f;
                if (diag && (kt * 128 + nt * 8 + c0l + j - 2) > r0g + 8) s = -1e30f;
                sacc[nt][j] = s; mx1 = fmaxf(mx1, s);
            }
        }
        #pragma unroll
        for (int o = 1; o < 4; o <<= 1) {
            mx0 = fmaxf(mx0, __shfl_xor_sync(0xffffffffu, mx0, o));
            mx1 = fmaxf(mx1, __shfl_xor_sync(0xffffffffu, mx1, o));
        }
        float mn0 = fmaxf(m_[0], mx0), mn1 = fmaxf(m_[1], mx1);
        float cr0 = __expf(m_[0] - mn0), cr1 = __expf(m_[1] - mn1);
        float sum0 = 0.f, sum1 = 0.f;
        #pragma unroll
        for (int nt = 0; nt < 16; nt++) {
            float p0 = __expf(sacc[nt][0] - mn0), p1 = __expf(sacc[nt][1] - mn0);
            float p2 = __expf(sacc[nt][2] - mn1), p3 = __expf(sacc[nt][3] - mn1);
            sacc[nt][0] = p0; sacc[nt][1] = p1; sacc[nt][2] = p2; sacc[nt][3] = p3;
            sum0 += p0 + p1; sum1 += p2 + p3;
        }
        #pragma unroll
        for (int o = 1; o < 4; o <<= 1) {
            sum0 += __shfl_xor_sync(0xffffffffu, sum0, o);
            sum1 += __shfl_xor_sync(0xffffffffu, sum1, o);
        }
        l_[0] = l_[0] * cr0 + sum0; l_[1] = l_[1] * cr1 + sum1;
        m_[0] = mn0; m_[1] = mn1;
        #pragma unroll
        for (int d = 0; d < 8; d++) {
            oacc[d][0] *= cr0; oacc[d][1] *= cr0;
            oacc[d][2] *= cr1; oacc[d][3] *= cr1;
        }

        #pragma unroll
        for (int kvt = 0; kvt < 8; kvt++) {
            uint32_t pa[4];
            pa[0] = packh(sacc[2 * kvt][0],     sacc[2 * kvt][1]);
            pa[1] = packh(sacc[2 * kvt][2],     sacc[2 * kvt][3]);
            pa[2] = packh(sacc[2 * kvt + 1][0], sacc[2 * kvt + 1][1]);
            pa[3] = packh(sacc[2 * kvt + 1][2], sacc[2 * kvt + 1][3]);

            #pragma unroll
            for (int ntp = 0; ntp < 4; ntp++) {
                uint32_t vh4[4];
                uint32_t off = (uint32_t)(ntp * 16 + ((lid >> 4) * 8) + (lid & 7)) * FROWV
                             + kvt * 32 + ((lid >> 3) & 1) * 16;
                ldsm4(vh4, stg + 18432 + off);
                mma_f16(oacc[2 * ntp],     pa, vh4[0], vh4[1]);
                mma_f16(oacc[2 * ntp + 1], pa, vh4[2], vh4[3]);
            }
        }
        __syncthreads();
    }

    const int b = bh / H_, h = bh - b * H_;
    float inv0 = 1.f / l_[0], inv1 = 1.f / l_[1];
    #pragma unroll
    for (int nt = 0; nt < 8; nt++) {
        const int d = nt * 8 + c0l;
        {
            size_t o = ((size_t)(b * T_ + r0g)) * E_ + h * D_ + d;
            *(__half2*)&ctx[o] = __floats2half2_rn(oacc[nt][0] * inv0, oacc[nt][1] * inv0);
        }
        {
            size_t o = ((size_t)(b * T_ + r0g + 8)) * E_ + h * D_ + d;
            *(__half2*)&ctx[o] = __floats2half2_rn(oacc[nt][2] * inv1, oacc[nt][3] * inv1);
        }
    }
}

// ---------------- launch ----------------
extern "C" void kernel_launch(void* const* d_in, const int* in_sizes, int n_in,
                              void* d_out, int out_size)
{
    const float* x    = (const float*)d_in[0];
    const float* wq   = (const float*)d_in[1];
    const float* wk   = (const float*)d_in[2];
    const float* wv   = (const float*)d_in[3];
    const float* wo   = (const float*)d_in[4];
    const float* bo   = (const float*)d_in[5];
    const float* ln1s = (const float*)d_in[6];
    const float* ln1b = (const float*)d_in[7];
    const float* ln2s = (const float*)d_in[8];
    const float* ln2b = (const float*)d_in[9];
    const float* w1   = (const float*)d_in[10];
    const float* b1   = (const float*)d_in[11];
    const float* w2   = (const float*)d_in[12];
    const float* b2   = (const float*)d_in[13];
    float* out = (float*)d_out;

    float *x2;
    fp16 *h1, *q, *k, *vt, *ctx, *h2, *mid;
    fp16 *wqkvT, *woT, *w1T, *w2T;
    cudaGetSymbolAddress((void**)&x2,  g_x2);
    cudaGetSymbolAddress((void**)&h1,  g_h1);
    cudaGetSymbolAddress((void**)&q,   g_q);
    cudaGetSymbolAddress((void**)&k,   g_k);
    cudaGetSymbolAddress((void**)&vt,  g_vt);
    cudaGetSymbolAddress((void**)&ctx, g_ctx);
    cudaGetSymbolAddress((void**)&h2,  g_h2);
    cudaGetSymbolAddress((void**)&mid, g_mid);
    cudaGetSymbolAddress((void**)&wqkvT, g_wqkvT);
    cudaGetSymbolAddress((void**)&woT, g_woT);
    cudaGetSymbolAddress((void**)&w1T, g_w1T);
    cudaGetSymbolAddress((void**)&w2T, g_w2T);

    cudaFuncSetAttribute(flash_attn2, cudaFuncAttributeMaxDynamicSharedMemorySize, FA2_SMEM);
    cudaFuncSetAttribute(mma_gemm<EPI_QKV>,        cudaFuncAttributeMaxDynamicSharedMemorySize, GEMM_SMEM);
    cudaFuncSetAttribute(mma_gemm<EPI_BIAS_RESID>, cudaFuncAttributeMaxDynamicSharedMemorySize, GEMM_SMEM);
    cudaFuncSetAttribute(mma_gemm<EPI_BIAS_GELU>,  cudaFuncAttributeMaxDynamicSharedMemorySize, GEMM_SMEM);

    // weight transpose+round; wq/wk/wv stacked into [2304,768]
    wsplitT4<<<dim3(E_/32, E_/32, 4), 256>>>(wq, wk, wv, wo, wqkvT, woT);
    wsplitT<<<dim3(FF_/32, E_/32), 256>>>(w1, w1T, E_, FF_);
    wsplitT<<<dim3(E_/32, FF_/32), 256>>>(w2, w2T, FF_, E_);

    // LN1 -> h1 (fp16)
    ln_kernel<<<M_, 256>>>(x, ln1s, ln1b, h1);

    // fused QKV -> Q, K, Vt (fp16)
    mma_gemm<EPI_QKV><<<dim3(QKVN/128, M_/128), 256, GEMM_SMEM>>>(
        h1, wqkvT, nullptr, nullptr, nullptr, q, k, vt, nullptr, QKVN, E_);

    // flash attention -> ctx fp16
    flash_attn2<<<dim3(T_/128, BH_), 256, FA2_SMEM>>>(q, k, vt, ctx);

    // proj + bias + resid -> x2
    mma_gemm<EPI_BIAS_RESID><<<dim3(E_/128, M_/128), 256, GEMM_SMEM>>>(
        ctx, woT, bo, x, x2, nullptr, nullptr, nullptr, nullptr, E_, E_);

    // LN2 -> h2 (fp16)
    ln_kernel<<<M_, 256>>>(x2, ln2s, ln2b, h2);

    // MLP1 (gelu) -> mid fp16
    mma_gemm<EPI_BIAS_GELU><<<dim3(FF_/128, M_/128), 256, GEMM_SMEM>>>(
        h2, w1T, b1, nullptr, nullptr, nullptr, nullptr, nullptr, mid, FF_, E_);

    // MLP2 + bias + resid -> out
    mma_gemm<EPI_BIAS_RESID><<<dim3(E_/128, M_/128), 256, GEMM_SMEM>>>(
        mid, w2T, b2, x2, out, nullptr, nullptr, nullptr, nullptr, E_, FF_);
}

// round 12
// speedup vs baseline: 2.6975x; 1.0494x over previous
#include <cuda_runtime.h>
#include <cuda_fp16.h>
#include <math.h>
#include <cstdint>

#define B_  2
#define T_  2048
#define E_  768
#define H_  12
#define D_  64
#define M_  (B_*T_)    // 4096
#define FF_ (4*E_)     // 3072
#define BH_ (B_*H_)    // 24
#define QKVN (3*E_)    // 2304

typedef __half fp16;

// ---------------- scratch ----------------
__device__ float g_x2[M_*E_];
__device__ fp16 g_h1[M_*E_];
__device__ fp16 g_q [M_*E_];                   // [B,H,T,D]
__device__ fp16 g_k [M_*E_];                   // [B,H,T,D]
__device__ fp16 g_vt[M_*E_];                   // [B,H,D,T]
__device__ fp16 g_ctx[M_*E_];
__device__ fp16 g_h2[M_*E_];
__device__ fp16 g_mid[(size_t)M_*FF_];
__device__ fp16 g_wqkvT[(size_t)QKVN*E_];
__device__ fp16 g_woT[E_*E_];
__device__ fp16 g_w1T[(size_t)E_*FF_];
__device__ fp16 g_w2T[(size_t)E_*FF_];

// ---------------- helpers ----------------
__device__ __forceinline__ uint32_t smem_u32(const void* p) {
    uint32_t a;
    asm("{ .reg .u64 t; cvta.to.shared.u64 t, %1; cvt.u32.u64 %0, t; }" : "=r"(a) : "l"(p));
    return a;
}
__device__ __forceinline__ void cpasync16(uint32_t dst, const void* src) {
    asm volatile("cp.async.ca.shared.global [%0], [%1], 16;" :: "r"(dst), "l"(src));
}
__device__ __forceinline__ void ldsm4(uint32_t* r, uint32_t addr) {
    asm volatile("ldmatrix.sync.aligned.m8n8.x4.shared.b16 {%0,%1,%2,%3}, [%4];"
        : "=r"(r[0]), "=r"(r[1]), "=r"(r[2]), "=r"(r[3]) : "r"(addr));
}
__device__ __forceinline__ void mma_f16(float* c, const uint32_t* a, uint32_t b0, uint32_t b1) {
    asm volatile("mma.sync.aligned.m16n8k16.row.col.f32.f16.f16.f32 "
        "{%0,%1,%2,%3}, {%4,%5,%6,%7}, {%8,%9}, {%0,%1,%2,%3};"
        : "+f"(c[0]), "+f"(c[1]), "+f"(c[2]), "+f"(c[3])
        : "r"(a[0]), "r"(a[1]), "r"(a[2]), "r"(a[3]), "r"(b0), "r"(b1));
}
__device__ __forceinline__ uint32_t packh(float a, float b) {
    __half2 t = __floats2half2_rn(a, b);
    return *(uint32_t*)&t;
}
__device__ __forceinline__ float tanh_fast(float x) {
    float y;
    asm("tanh.approx.f32 %0, %1;" : "=f"(y) : "f"(x));
    return y;
}

// ---------------- weight transpose + round: w[K,N] -> wT fp16 [N,K] ----------------
__global__ void __launch_bounds__(256)
wsplitT(const float* __restrict__ w, fp16* __restrict__ hi, int K, int N)
{
    __shared__ float t[32][33];
    const int tx = threadIdx.x & 31, ty = threadIdx.x >> 5;
    const int n0 = blockIdx.x * 32, k0 = blockIdx.y * 32;
    #pragma unroll
    for (int i = 0; i < 32; i += 8)
        t[ty + i][tx] = w[(size_t)(k0 + ty + i) * N + n0 + tx];
    __syncthreads();
    #pragma unroll
    for (int i = 0; i < 32; i += 8)
        hi[(size_t)(n0 + ty + i) * K + k0 + tx] = __float2half_rn(t[tx][ty + i]);
}

// four E x E weights in one launch
__global__ void __launch_bounds__(256)
wsplitT4(const float* __restrict__ wqp, const float* __restrict__ wkp,
         const float* __restrict__ wvp, const float* __restrict__ wop,
         fp16* __restrict__ hqkv, fp16* __restrict__ hwo)
{
    const int z = blockIdx.z;
    const float* w = (z == 0) ? wqp : (z == 1) ? wkp : (z == 2) ? wvp : wop;
    fp16* hi = (z < 3) ? hqkv + (size_t)z * E_ * E_ : hwo;
    __shared__ float t[32][33];
    const int tx = threadIdx.x & 31, ty = threadIdx.x >> 5;
    const int n0 = blockIdx.x * 32, k0 = blockIdx.y * 32;
    #pragma unroll
    for (int i = 0; i < 32; i += 8)
        t[ty + i][tx] = w[(size_t)(k0 + ty + i) * E_ + n0 + tx];
    __syncthreads();
    #pragma unroll
    for (int i = 0; i < 32; i += 8)
        hi[(size_t)(n0 + ty + i) * E_ + k0 + tx] = __float2half_rn(t[tx][ty + i]);
}

// ---------------- LayerNorm (ddof=1), warp-per-row -> fp16 ----------------
// 8 warps/block, each warp owns one row; 768 = 32 lanes x 6 float4 slots.
__global__ void __launch_bounds__(256)
ln_kernel(const float* __restrict__ x, const float* __restrict__ sc,
          const float* __restrict__ sh, fp16* __restrict__ o16)
{
    const int warp = threadIdx.x >> 5, lane = threadIdx.x & 31;
    const int row = blockIdx.x * 8 + warp;
    const float* xr = x + (size_t)row * E_;

    float4 v[6];
    float s = 0.f, s2 = 0.f;
    #pragma unroll
    for (int p = 0; p < 6; p++) {
        v[p] = *(const float4*)&xr[lane * 4 + p * 128];
        s  += v[p].x + v[p].y + v[p].z + v[p].w;
        s2 += v[p].x * v[p].x + v[p].y * v[p].y + v[p].z * v[p].z + v[p].w * v[p].w;
    }
    #pragma unroll
    for (int o = 16; o; o >>= 1) {
        s  += __shfl_xor_sync(0xffffffffu, s,  o);
        s2 += __shfl_xor_sync(0xffffffffu, s2, o);
    }
    const float mean = s * (1.f / E_);
    const float var  = (s2 - s * mean) * (1.f / (E_ - 1));
    const float rstd = rsqrtf(var + 1e-5f);

    fp16* orow = o16 + (size_t)row * E_;
    #pragma unroll
    for (int p = 0; p < 6; p++) {
        const int i = lane * 4 + p * 128;
        float4 c = *(const float4*)&sc[i];
        float4 b = *(const float4*)&sh[i];
        __half2 h0 = __floats2half2_rn(c.x * (v[p].x - mean) * rstd + b.x,
                                       c.y * (v[p].y - mean) * rstd + b.y);
        __half2 h1 = __floats2half2_rn(c.z * (v[p].z - mean) * rstd + b.z,
                                       c.w * (v[p].w - mean) * rstd + b.w);
        uint2 pk = make_uint2(*(uint32_t*)&h0, *(uint32_t*)&h1);
        *(uint2*)&orow[i] = pk;
    }
}

// ---------------- warp-MMA GEMM: fp16 single-term, 2-stage cp.async, occ=2 ----------------
enum { EPI_QKV = 0, EPI_BIAS_RESID = 1, EPI_BIAS_GELU = 2 };

#define KCH     64
#define ROWB    144
#define TILE_B  (128*ROWB)      // 18432
#define STAGE_B (2*TILE_B)      // 36864 (A, B)
#define GEMM_SMEM (2*STAGE_B)   // 73728

template<int EPI>
__global__ void __launch_bounds__(256, 2)
mma_gemm(const fp16* __restrict__ A_g, const fp16* __restrict__ B_g,
         const float* __restrict__ bias, const float* __restrict__ resid,
         float* __restrict__ C,
         fp16* __restrict__ Qo, fp16* __restrict__ Ko, fp16* __restrict__ Vto,
         fp16* __restrict__ C16,
         int N, int K)
{
    extern __shared__ char sm[];
    const uint32_t sbase = smem_u32(sm);
    const int tid = threadIdx.x, wid = tid >> 5, lid = tid & 31;
    const int m0 = blockIdx.y * 128, n0 = blockIdx.x * 128;
    const int wm = wid >> 2, wn = wid & 3;

    const int lrow = tid >> 3;
    const int lcb  = (tid & 7) * 16;

    float acc[4][4][4] = {};

    const fp16* gs[2] = {A_g, B_g};
    const int   r0s[2] = {m0, n0};

    auto issue = [&](int c) {
        const int k0 = c * KCH;
        const uint32_t sb = sbase + (uint32_t)(c & 1) * STAGE_B;
        #pragma unroll
        for (int t = 0; t < 2; t++) {
            const char* g = (const char*)(gs[t] + (size_t)(r0s[t] + lrow) * K + k0) + lcb;
            uint32_t d = sb + t * TILE_B + lrow * ROWB + lcb;
            #pragma unroll
            for (int i = 0; i < 4; i++)
                cpasync16(d + i * 32 * ROWB, g + (size_t)i * 32 * K * 2);
        }
        asm volatile("cp.async.commit_group;");
    };

    const int NC = K / KCH;
    issue(0);

    const int am = (lid >> 3);
    const uint32_t aRow = wm * 64 + (am & 1) * 8 + (lid & 7);
    const uint32_t aColH = (am >> 1) * 16;
    const uint32_t bRowBase = wn * 32 + (lid & 7);
    const uint32_t bNt = (am >> 1);
    const uint32_t bColH = (am & 1) * 16;

    for (int c = 0; c < NC; c++) {
        if (c + 1 < NC) { issue(c + 1); asm volatile("cp.async.wait_group 1;"); }
        else            { asm volatile("cp.async.wait_group 0;"); }
        __syncthreads();

        const uint32_t sb = sbase + (uint32_t)(c & 1) * STAGE_B;
        const uint32_t aB = sb, bB = sb + TILE_B;

        #pragma unroll
        for (int ks = 0; ks < 4; ks++) {
            uint32_t bh[2][4];
            #pragma unroll
            for (int p = 0; p < 2; p++) {
                uint32_t row = bRowBase + (p * 2 + bNt) * 8;
                uint32_t off = row * ROWB + ks * 32 + bColH;
                ldsm4(bh[p], bB + off);
            }
            #pragma unroll
            for (int mt = 0; mt < 4; mt++) {
                uint32_t ah[4];
                uint32_t off = (aRow + mt * 16) * ROWB + ks * 32 + aColH;
                ldsm4(ah, aB + off);
                #pragma unroll
                for (int nt = 0; nt < 4; nt++) {
                    const int p = nt >> 1, q = (nt & 1) * 2;
                    mma_f16(acc[mt][nt], ah, bh[p][q], bh[p][q + 1]);
                }
            }
        }
        __syncthreads();
    }

    #pragma unroll
    for (int mt = 0; mt < 4; mt++) {
        #pragma unroll
        for (int nt = 0; nt < 4; nt++) {
            const int r0 = m0 + wm * 64 + mt * 16 + (lid >> 2);
            const int cc = n0 + wn * 32 + nt * 8 + (lid & 3) * 2;
            #pragma unroll
            for (int hh = 0; hh < 2; hh++) {
                const int r = r0 + hh * 8;
                float v0 = acc[mt][nt][hh * 2], v1 = acc[mt][nt][hh * 2 + 1];
                if (EPI == EPI_QKV) {
                    const int bb = r >> 11, tt = r & (T_ - 1);
                    int which = (cc >= 2 * E_) ? 2 : (cc >= E_ ? 1 : 0);
                    int nn = cc - which * E_;
                    int hx = nn >> 6, d = nn & 63;
                    if (which == 2) {
                        size_t o = ((size_t)(bb * H_ + hx) * D_ + d) * T_ + tt;
                        Vto[o]      = __float2half_rn(v0);
                        Vto[o + T_] = __float2half_rn(v1);
                    } else {
                        size_t o = ((size_t)(bb * H_ + hx) * T_ + tt) * D_ + d;
                        fp16* dst = (which == 0) ? Qo : Ko;
                        *(__half2*)&dst[o] = __floats2half2_rn(v0, v1);
                    }
                } else if (EPI == EPI_BIAS_RESID) {
                    size_t o = (size_t)r * N + cc;
                    float2 bs = *(const float2*)&bias[cc];
                    float2 rs = *(const float2*)&resid[o];
                    *(float2*)&C[o] = make_float2(v0 + bs.x + rs.x, v1 + bs.y + rs.y);
                } else {
                    size_t o = (size_t)r * N + cc;
                    float2 bs = *(const float2*)&bias[cc];
                    float vv[2] = {v0 + bs.x, v1 + bs.y};
                    #pragma unroll
                    for (int j = 0; j < 2; j++) {
                        float v = vv[j];
                        float u = 0.7978845608028654f * (v + 0.044715f * v * v * v);
                        vv[j] = 0.5f * v * (1.f + tanh_fast(u));
                    }
                    *(__half2*)&C16[o] = __floats2half2_rn(vv[0], vv[1]);
                }
            }
        }
    }
}

// ---------------- tensor-core flash attention: fp16 single-term ----------------
#define FROWK 144
#define FROWV 272
#define FQ    0
#define FSTG0 18432
#define FSTGB 35840          // K 18432 + V 17408
#define FA2_SMEM (18432 + 2*FSTGB)   // 90112

__global__ void __launch_bounds__(256, 1)
flash_attn2(const fp16* __restrict__ Q_g, const fp16* __restrict__ K_g,
            const fp16* __restrict__ Vt_g, fp16* __restrict__ ctx)
{
    extern __shared__ char sm[];
    const uint32_t sb = smem_u32(sm);
    const int tid = threadIdx.x, wid = tid >> 5, lid = tid & 31;
    const int bh = blockIdx.y;
    const int mtile = (gridDim.x - 1) - blockIdx.x;
    const int q0 = mtile * 128;

    const fp16* Qb = Q_g + (size_t)bh * T_ * D_;
    const fp16* Kb = K_g + (size_t)bh * T_ * D_;
    const fp16* Vb = Vt_g + (size_t)bh * D_ * T_;

    {
        const int row = tid >> 1, half = tid & 1;
        const char* g = (const char*)(Qb + (size_t)(q0 + row) * D_ + half * 32);
        uint32_t d = sb + FQ + row * FROWK + half * 64;
        #pragma unroll
        for (int i = 0; i < 4; i++) cpasync16(d + i * 16, g + i * 16);
    }

    auto issueKV = [&](int stage, int kvt) {
        const int kv0 = kvt * 128;
        const uint32_t s0 = sb + FSTG0 + (uint32_t)stage * FSTGB;
        {
            const int row = tid >> 1, half = tid & 1;
            const char* g = (const char*)(Kb + (size_t)(kv0 + row) * D_ + half * 32);
            uint32_t d = s0 + row * FROWK + half * 64;
            #pragma unroll
            for (int i = 0; i < 4; i++) cpasync16(d + i * 16, g + i * 16);
        }
        {
            const int row = tid >> 2, qt = tid & 3;
            const char* g = (const char*)(Vb + (size_t)row * T_ + kv0 + qt * 32);
            uint32_t d = s0 + 18432 + row * FROWV + qt * 64;
            #pragma unroll
            for (int i = 0; i < 4; i++) cpasync16(d + i * 16, g + i * 16);
        }
        asm volatile("cp.async.commit_group;");
    };

    issueKV(0, 0);

    const int am = lid >> 3;
    uint32_t qf[4][4];
    float m_[2] = {-1e30f, -1e30f}, l_[2] = {0.f, 0.f};
    float oacc[8][4] = {};

    const int r0g = q0 + wid * 16 + (lid >> 2);
    const int c0l = (lid & 3) * 2;

    for (int kt = 0; kt <= mtile; kt++) {
        if (kt + 1 <= mtile) { issueKV((kt + 1) & 1, kt + 1); asm volatile("cp.async.wait_group 1;"); }
        else                 { asm volatile("cp.async.wait_group 0;"); }
        __syncthreads();

        if (kt == 0) {
            const uint32_t rowq = wid * 16 + (am & 1) * 8 + (lid & 7);
            #pragma unroll
            for (int ks = 0; ks < 4; ks++) {
                uint32_t off = rowq * FROWK + ks * 32 + (am >> 1) * 16;
                ldsm4(qf[ks], sb + FQ + off);
            }
        }

        const uint32_t stg = sb + FSTG0 + (uint32_t)(kt & 1) * FSTGB;

        float sacc[16][4] = {};
        #pragma unroll
        for (int ks = 0; ks < 4; ks++) {
            #pragma unroll
            for (int ntp = 0; ntp < 8; ntp++) {
                uint32_t kh4[4];
                uint32_t off = (uint32_t)(ntp * 16 + ((lid >> 4) * 8) + (lid & 7)) * FROWK
                             + ks * 32 + ((lid >> 3) & 1) * 16;
                ldsm4(kh4, stg + off);
                mma_f16(sacc[2 * ntp],     qf[ks], kh4[0], kh4[1]);
                mma_f16(sacc[2 * ntp + 1], qf[ks], kh4[2], kh4[3]);
            }
        }

        const bool diag = (kt == mtile);
        float mx0 = -1e30f, mx1 = -1e30f;
        #pragma unroll
        for (int nt = 0; nt < 16; nt++) {
            #pragma unroll
            for (int j = 0; j < 2; j++) {
                float s = sacc[nt][j] * 0.125f;
                if (diag && (kt * 128 + nt * 8 + c0l + j) > r0g) s = -1e30f;
                sacc[nt][j] = s; mx0 = fmaxf(mx0, s);
            }
            #pragma unroll
            for (int j = 2; j < 4; j++) {
                float s = sacc[nt][j] * 0.125f;
                if (diag && (kt * 128 + nt * 8 + c0l + j - 2) > r0g + 8) s = -1e30f;
                sacc[nt][j] = s; mx1 = fmaxf(mx1, s);
            }
        }
        #pragma unroll
        for (int o = 1; o < 4; o <<= 1) {
            mx0 = fmaxf(mx0, __shfl_xor_sync(0xffffffffu, mx0, o));
            mx1 = fmaxf(mx1, __shfl_xor_sync(0xffffffffu, mx1, o));
        }
        float mn0 = fmaxf(m_[0], mx0), mn1 = fmaxf(m_[1], mx1);
        float cr0 = __expf(m_[0] - mn0), cr1 = __expf(m_[1] - mn1);
        float sum0 = 0.f, sum1 = 0.f;
        #pragma unroll
        for (int nt = 0; nt < 16; nt++) {
            float p0 = __expf(sacc[nt][0] - mn0), p1 = __expf(sacc[nt][1] - mn0);
            float p2 = __expf(sacc[nt][2] - mn1), p3 = __expf(sacc[nt][3] - mn1);
            sacc[nt][0] = p0; sacc[nt][1] = p1; sacc[nt][2] = p2; sacc[nt][3] = p3;
            sum0 += p0 + p1; sum1 += p2 + p3;
        }
        #pragma unroll
        for (int o = 1; o < 4; o <<= 1) {
            sum0 += __shfl_xor_sync(0xffffffffu, sum0, o);
            sum1 += __shfl_xor_sync(0xffffffffu, sum1, o);
        }
        l_[0] = l_[0] * cr0 + sum0; l_[1] = l_[1] * cr1 + sum1;
        m_[0] = mn0; m_[1] = mn1;
        #pragma unroll
        for (int d = 0; d < 8; d++) {
            oacc[d][0] *= cr0; oacc[d][1] *= cr0;
            oacc[d][2] *= cr1; oacc[d][3] *= cr1;
        }

        #pragma unroll
        for (int kvt = 0; kvt < 8; kvt++) {
            uint32_t pa[4];
            pa[0] = packh(sacc[2 * kvt][0],     sacc[2 * kvt][1]);
            pa[1] = packh(sacc[2 * kvt][2],     sacc[2 * kvt][3]);
            pa[2] = packh(sacc[2 * kvt + 1][0], sacc[2 * kvt + 1][1]);
            pa[3] = packh(sacc[2 * kvt + 1][2], sacc[2 * kvt + 1][3]);

            #pragma unroll
            for (int ntp = 0; ntp < 4; ntp++) {
                uint32_t vh4[4];
                uint32_t off = (uint32_t)(ntp * 16 + ((lid >> 4) * 8) + (lid & 7)) * FROWV
                             + kvt * 32 + ((lid >> 3) & 1) * 16;
                ldsm4(vh4, stg + 18432 + off);
                mma_f16(oacc[2 * ntp],     pa, vh4[0], vh4[1]);
                mma_f16(oacc[2 * ntp + 1], pa, vh4[2], vh4[3]);
            }
        }
        __syncthreads();
    }

    const int b = bh / H_, h = bh - b * H_;
    float inv0 = 1.f / l_[0], inv1 = 1.f / l_[1];
    #pragma unroll
    for (int nt = 0; nt < 8; nt++) {
        const int d = nt * 8 + c0l;
        {
            size_t o = ((size_t)(b * T_ + r0g)) * E_ + h * D_ + d;
            *(__half2*)&ctx[o] = __floats2half2_rn(oacc[nt][0] * inv0, oacc[nt][1] * inv0);
        }
        {
            size_t o = ((size_t)(b * T_ + r0g + 8)) * E_ + h * D_ + d;
            *(__half2*)&ctx[o] = __floats2half2_rn(oacc[nt][2] * inv1, oacc[nt][3] * inv1);
        }
    }
}

// ---------------- launch ----------------
extern "C" void kernel_launch(void* const* d_in, const int* in_sizes, int n_in,
                              void* d_out, int out_size)
{
    const float* x    = (const float*)d_in[0];
    const float* wq   = (const float*)d_in[1];
    const float* wk   = (const float*)d_in[2];
    const float* wv   = (const float*)d_in[3];
    const float* wo   = (const float*)d_in[4];
    const float* bo   = (const float*)d_in[5];
    const float* ln1s = (const float*)d_in[6];
    const float* ln1b = (const float*)d_in[7];
    const float* ln2s = (const float*)d_in[8];
    const float* ln2b = (const float*)d_in[9];
    const float* w1   = (const float*)d_in[10];
    const float* b1   = (const float*)d_in[11];
    const float* w2   = (const float*)d_in[12];
    const float* b2   = (const float*)d_in[13];
    float* out = (float*)d_out;

    float *x2;
    fp16 *h1, *q, *k, *vt, *ctx, *h2, *mid;
    fp16 *wqkvT, *woT, *w1T, *w2T;
    cudaGetSymbolAddress((void**)&x2,  g_x2);
    cudaGetSymbolAddress((void**)&h1,  g_h1);
    cudaGetSymbolAddress((void**)&q,   g_q);
    cudaGetSymbolAddress((void**)&k,   g_k);
    cudaGetSymbolAddress((void**)&vt,  g_vt);
    cudaGetSymbolAddress((void**)&ctx, g_ctx);
    cudaGetSymbolAddress((void**)&h2,  g_h2);
    cudaGetSymbolAddress((void**)&mid, g_mid);
    cudaGetSymbolAddress((void**)&wqkvT, g_wqkvT);
    cudaGetSymbolAddress((void**)&woT, g_woT);
    cudaGetSymbolAddress((void**)&w1T, g_w1T);
    cudaGetSymbolAddress((void**)&w2T, g_w2T);

    cudaFuncSetAttribute(flash_attn2, cudaFuncAttributeMaxDynamicSharedMemorySize, FA2_SMEM);
    cudaFuncSetAttribute(mma_gemm<EPI_QKV>,        cudaFuncAttributeMaxDynamicSharedMemorySize, GEMM_SMEM);
    cudaFuncSetAttribute(mma_gemm<EPI_BIAS_RESID>, cudaFuncAttributeMaxDynamicSharedMemorySize, GEMM_SMEM);
    cudaFuncSetAttribute(mma_gemm<EPI_BIAS_GELU>,  cudaFuncAttributeMaxDynamicSharedMemorySize, GEMM_SMEM);

    // weight transpose+round; wq/wk/wv stacked into [2304,768]
    wsplitT4<<<dim3(E_/32, E_/32, 4), 256>>>(wq, wk, wv, wo, wqkvT, woT);
    wsplitT<<<dim3(FF_/32, E_/32), 256>>>(w1, w1T, E_, FF_);
    wsplitT<<<dim3(E_/32, FF_/32), 256>>>(w2, w2T, FF_, E_);

    // LN1 -> h1 (fp16), warp-per-row
    ln_kernel<<<M_/8, 256>>>(x, ln1s, ln1b, h1);

    // fused QKV -> Q, K, Vt (fp16)
    mma_gemm<EPI_QKV><<<dim3(QKVN/128, M_/128), 256, GEMM_SMEM>>>(
        h1, wqkvT, nullptr, nullptr, nullptr, q, k, vt, nullptr, QKVN, E_);

    // flash attention -> ctx fp16
    flash_attn2<<<dim3(T_/128, BH_), 256, FA2_SMEM>>>(q, k, vt, ctx);

    // proj + bias + resid -> x2
    mma_gemm<EPI_BIAS_RESID><<<dim3(E_/128, M_/128), 256, GEMM_SMEM>>>(
        ctx, woT, bo, x, x2, nullptr, nullptr, nullptr, nullptr, E_, E_);

    // LN2 -> h2 (fp16), warp-per-row
    ln_kernel<<<M_/8, 256>>>(x2, ln2s, ln2b, h2);

    // MLP1 (gelu, tanh.approx) -> mid fp16
    mma_gemm<EPI_BIAS_GELU><<<dim3(FF_/128, M_/128), 256, GEMM_SMEM>>>(
        h2, w1T, b1, nullptr, nullptr, nullptr, nullptr, nullptr, mid, FF_, E_);

    // MLP2 + bias + resid -> out
    mma_gemm<EPI_BIAS_RESID><<<dim3(E_/128, M_/128), 256, GEMM_SMEM>>>(
        mid, w2T, b2, x2, out, nullptr, nullptr, nullptr, nullptr, E_, FF_);
}

// round 13
// speedup vs baseline: 2.7085x; 1.0041x over previous
#include <cuda_runtime.h>
#include <cuda_fp16.h>
#include <math.h>
#include <cstdint>

#define B_  2
#define T_  2048
#define E_  768
#define H_  12
#define D_  64
#define M_  (B_*T_)    // 4096
#define FF_ (4*E_)     // 3072
#define BH_ (B_*H_)    // 24
#define QKVN (3*E_)    // 2304

typedef __half fp16;

// ---------------- scratch ----------------
__device__ float g_x2[M_*E_];
__device__ fp16 g_h1[M_*E_];
__device__ fp16 g_q [M_*E_];                   // [B,H,T,D]
__device__ fp16 g_k [M_*E_];                   // [B,H,T,D]
__device__ fp16 g_vt[M_*E_];                   // [B,H,D,T]
__device__ fp16 g_ctx[M_*E_];
__device__ fp16 g_h2[M_*E_];
__device__ fp16 g_mid[(size_t)M_*FF_];
__device__ fp16 g_wqkvT[(size_t)QKVN*E_];
__device__ fp16 g_woT[E_*E_];
__device__ fp16 g_w1T[(size_t)E_*FF_];
__device__ fp16 g_w2T[(size_t)E_*FF_];

// ---------------- helpers ----------------
__device__ __forceinline__ uint32_t smem_u32(const void* p) {
    uint32_t a;
    asm("{ .reg .u64 t; cvta.to.shared.u64 t, %1; cvt.u32.u64 %0, t; }" : "=r"(a) : "l"(p));
    return a;
}
__device__ __forceinline__ void cpasync16(uint32_t dst, const void* src) {
    asm volatile("cp.async.ca.shared.global [%0], [%1], 16;" :: "r"(dst), "l"(src));
}
__device__ __forceinline__ void ldsm4(uint32_t* r, uint32_t addr) {
    asm volatile("ldmatrix.sync.aligned.m8n8.x4.shared.b16 {%0,%1,%2,%3}, [%4];"
        : "=r"(r[0]), "=r"(r[1]), "=r"(r[2]), "=r"(r[3]) : "r"(addr));
}
__device__ __forceinline__ void mma_f16(float* c, const uint32_t* a, uint32_t b0, uint32_t b1) {
    asm volatile("mma.sync.aligned.m16n8k16.row.col.f32.f16.f16.f32 "
        "{%0,%1,%2,%3}, {%4,%5,%6,%7}, {%8,%9}, {%0,%1,%2,%3};"
        : "+f"(c[0]), "+f"(c[1]), "+f"(c[2]), "+f"(c[3])
        : "r"(a[0]), "r"(a[1]), "r"(a[2]), "r"(a[3]), "r"(b0), "r"(b1));
}
__device__ __forceinline__ uint32_t packh(float a, float b) {
    __half2 t = __floats2half2_rn(a, b);
    return *(uint32_t*)&t;
}
__device__ __forceinline__ float tanh_fast(float x) {
    float y;
    asm("tanh.approx.f32 %0, %1;" : "=f"(y) : "f"(x));
    return y;
}

// ---------------- weight transpose + round ----------------
__global__ void __launch_bounds__(256)
wsplitT(const float* __restrict__ w, fp16* __restrict__ hi, int K, int N)
{
    __shared__ float t[32][33];
    const int tx = threadIdx.x & 31, ty = threadIdx.x >> 5;
    const int n0 = blockIdx.x * 32, k0 = blockIdx.y * 32;
    #pragma unroll
    for (int i = 0; i < 32; i += 8)
        t[ty + i][tx] = w[(size_t)(k0 + ty + i) * N + n0 + tx];
    __syncthreads();
    #pragma unroll
    for (int i = 0; i < 32; i += 8)
        hi[(size_t)(n0 + ty + i) * K + k0 + tx] = __float2half_rn(t[tx][ty + i]);
}

__global__ void __launch_bounds__(256)
wsplitT4(const float* __restrict__ wqp, const float* __restrict__ wkp,
         const float* __restrict__ wvp, const float* __restrict__ wop,
         fp16* __restrict__ hqkv, fp16* __restrict__ hwo)
{
    const int z = blockIdx.z;
    const float* w = (z == 0) ? wqp : (z == 1) ? wkp : (z == 2) ? wvp : wop;
    fp16* hi = (z < 3) ? hqkv + (size_t)z * E_ * E_ : hwo;
    __shared__ float t[32][33];
    const int tx = threadIdx.x & 31, ty = threadIdx.x >> 5;
    const int n0 = blockIdx.x * 32, k0 = blockIdx.y * 32;
    #pragma unroll
    for (int i = 0; i < 32; i += 8)
        t[ty + i][tx] = w[(size_t)(k0 + ty + i) * E_ + n0 + tx];
    __syncthreads();
    #pragma unroll
    for (int i = 0; i < 32; i += 8)
        hi[(size_t)(n0 + ty + i) * E_ + k0 + tx] = __float2half_rn(t[tx][ty + i]);
}

// ---------------- LayerNorm (ddof=1), warp-per-row -> fp16 ----------------
__global__ void __launch_bounds__(256)
ln_kernel(const float* __restrict__ x, const float* __restrict__ sc,
          const float* __restrict__ sh, fp16* __restrict__ o16)
{
    const int warp = threadIdx.x >> 5, lane = threadIdx.x & 31;
    const int row = blockIdx.x * 8 + warp;
    const float* xr = x + (size_t)row * E_;

    float4 v[6];
    float s = 0.f, s2 = 0.f;
    #pragma unroll
    for (int p = 0; p < 6; p++) {
        v[p] = *(const float4*)&xr[lane * 4 + p * 128];
        s  += v[p].x + v[p].y + v[p].z + v[p].w;
        s2 += v[p].x * v[p].x + v[p].y * v[p].y + v[p].z * v[p].z + v[p].w * v[p].w;
    }
    #pragma unroll
    for (int o = 16; o; o >>= 1) {
        s  += __shfl_xor_sync(0xffffffffu, s,  o);
        s2 += __shfl_xor_sync(0xffffffffu, s2, o);
    }
    const float mean = s * (1.f / E_);
    const float var  = (s2 - s * mean) * (1.f / (E_ - 1));
    const float rstd = rsqrtf(var + 1e-5f);

    fp16* orow = o16 + (size_t)row * E_;
    #pragma unroll
    for (int p = 0; p < 6; p++) {
        const int i = lane * 4 + p * 128;
        float4 c = *(const float4*)&sc[i];
        float4 b = *(const float4*)&sh[i];
        __half2 h0 = __floats2half2_rn(c.x * (v[p].x - mean) * rstd + b.x,
                                       c.y * (v[p].y - mean) * rstd + b.y);
        __half2 h1 = __floats2half2_rn(c.z * (v[p].z - mean) * rstd + b.z,
                                       c.w * (v[p].w - mean) * rstd + b.w);
        uint2 pk = make_uint2(*(uint32_t*)&h0, *(uint32_t*)&h1);
        *(uint2*)&orow[i] = pk;
    }
}

// ---------------- warp-MMA GEMM: fp16 single-term, 2-stage cp.async, occ=2 ----------------
enum { EPI_QKV = 0, EPI_BIAS_RESID = 1, EPI_BIAS_GELU = 2 };

#define KCH     64
#define ROWB    144
#define TILE_B  (128*ROWB)      // 18432
#define STAGE_B (2*TILE_B)      // 36864 (A, B)
#define GEMM_SMEM (2*STAGE_B)   // 73728
#define VROW    272

template<int EPI>
__global__ void __launch_bounds__(256, 2)
mma_gemm(const fp16* __restrict__ A_g, const fp16* __restrict__ B_g,
         const float* __restrict__ bias, const float* __restrict__ resid,
         float* __restrict__ C,
         fp16* __restrict__ Qo, fp16* __restrict__ Ko, fp16* __restrict__ Vto,
         fp16* __restrict__ C16,
         int N, int K)
{
    extern __shared__ char sm[];
    const uint32_t sbase = smem_u32(sm);
    const int tid = threadIdx.x, wid = tid >> 5, lid = tid & 31;
    const int m0 = blockIdx.y * 128, n0 = blockIdx.x * 128;
    const int wm = wid >> 2, wn = wid & 3;

    const int lrow = tid >> 3;
    const int lcb  = (tid & 7) * 16;

    float acc[4][4][4] = {};

    const fp16* gs[2] = {A_g, B_g};
    const int   r0s[2] = {m0, n0};

    auto issue = [&](int c) {
        const int k0 = c * KCH;
        const uint32_t sb = sbase + (uint32_t)(c & 1) * STAGE_B;
        #pragma unroll
        for (int t = 0; t < 2; t++) {
            const char* g = (const char*)(gs[t] + (size_t)(r0s[t] + lrow) * K + k0) + lcb;
            uint32_t d = sb + t * TILE_B + lrow * ROWB + lcb;
            #pragma unroll
            for (int i = 0; i < 4; i++)
                cpasync16(d + i * 32 * ROWB, g + (size_t)i * 32 * K * 2);
        }
        asm volatile("cp.async.commit_group;");
    };

    const int NC = K / KCH;
    issue(0);

    const int am = (lid >> 3);
    const uint32_t aRow = wm * 64 + (am & 1) * 8 + (lid & 7);
    const uint32_t aColH = (am >> 1) * 16;
    const uint32_t bRowBase = wn * 32 + (lid & 7);
    const uint32_t bNt = (am >> 1);
    const uint32_t bColH = (am & 1) * 16;

    for (int c = 0; c < NC; c++) {
        if (c + 1 < NC) { issue(c + 1); asm volatile("cp.async.wait_group 1;"); }
        else            { asm volatile("cp.async.wait_group 0;"); }
        __syncthreads();

        const uint32_t sb = sbase + (uint32_t)(c & 1) * STAGE_B;
        const uint32_t aB = sb, bB = sb + TILE_B;

        #pragma unroll
        for (int ks = 0; ks < 4; ks++) {
            uint32_t bh[2][4];
            #pragma unroll
            for (int p = 0; p < 2; p++) {
                uint32_t row = bRowBase + (p * 2 + bNt) * 8;
                uint32_t off = row * ROWB + ks * 32 + bColH;
                ldsm4(bh[p], bB + off);
            }
            #pragma unroll
            for (int mt = 0; mt < 4; mt++) {
                uint32_t ah[4];
                uint32_t off = (aRow + mt * 16) * ROWB + ks * 32 + aColH;
                ldsm4(ah, aB + off);
                #pragma unroll
                for (int nt = 0; nt < 4; nt++) {
                    const int p = nt >> 1, q = (nt & 1) * 2;
                    mma_f16(acc[mt][nt], ah, bh[p][q], bh[p][q + 1]);
                }
            }
        }
        __syncthreads();
    }

    const bool isV = (EPI == EPI_QKV) && (n0 >= 2 * E_);

    #pragma unroll
    for (int mt = 0; mt < 4; mt++) {
        #pragma unroll
        for (int nt = 0; nt < 4; nt++) {
            const int r0 = m0 + wm * 64 + mt * 16 + (lid >> 2);
            const int cc = n0 + wn * 32 + nt * 8 + (lid & 3) * 2;
            #pragma unroll
            for (int hh = 0; hh < 2; hh++) {
                const int r = r0 + hh * 8;
                float v0 = acc[mt][nt][hh * 2], v1 = acc[mt][nt][hh * 2 + 1];
                if (EPI == EPI_QKV) {
                    if (isV) {
                        // stage transposed in smem (coalesced writeout below)
                        const int rl = r - m0;
                        const int cl = cc - n0;
                        *(fp16*)(sm + cl * VROW + rl * 2)       = __float2half_rn(v0);
                        *(fp16*)(sm + (cl + 1) * VROW + rl * 2) = __float2half_rn(v1);
                    } else {
                        const int bb = r >> 11, tt = r & (T_ - 1);
                        int which = (cc >= E_) ? 1 : 0;
                        int nn = cc - which * E_;
                        int hx = nn >> 6, d = nn & 63;
                        size_t o = ((size_t)(bb * H_ + hx) * T_ + tt) * D_ + d;
                        fp16* dst = (which == 0) ? Qo : Ko;
                        *(__half2*)&dst[o] = __floats2half2_rn(v0, v1);
                    }
                } else if (EPI == EPI_BIAS_RESID) {
                    size_t o = (size_t)r * N + cc;
                    float2 bs = *(const float2*)&bias[cc];
                    float2 rs = *(const float2*)&resid[o];
                    *(float2*)&C[o] = make_float2(v0 + bs.x + rs.x, v1 + bs.y + rs.y);
                } else {
                    size_t o = (size_t)r * N + cc;
                    float2 bs = *(const float2*)&bias[cc];
                    float vv[2] = {v0 + bs.x, v1 + bs.y};
                    #pragma unroll
                    for (int j = 0; j < 2; j++) {
                        float v = vv[j];
                        float u = 0.7978845608028654f * (v + 0.044715f * v * v * v);
                        vv[j] = 0.5f * v * (1.f + tanh_fast(u));
                    }
                    *(__half2*)&C16[o] = __floats2half2_rn(vv[0], vv[1]);
                }
            }
        }
    }

    if (isV) {
        __syncthreads();
        const int bb = m0 >> 11, tt0 = m0 & (T_ - 1);
        const int nh = n0 - 2 * E_;
        #pragma unroll
        for (int it = 0; it < 8; it++) {
            const int nl = it * 16 + (tid >> 4);       // 0..127
            const int hx = (nh + nl) >> 6, d = (nh + nl) & 63;
            const uint4 v = *(const uint4*)(sm + nl * VROW + (tid & 15) * 16);
            *(uint4*)&Vto[((size_t)(bb * H_ + hx) * D_ + d) * T_ + tt0 + (tid & 15) * 8] = v;
        }
    }
}

// ---------------- flash attention: 64q x 128kv tiles, 128 threads, occ=2 ----------------
#define FROWK 144
#define FROWV 272
#define FQ    0
#define FSTG0 9216
#define FSTGB 35840          // K 18432 + V 17408
#define FA3_SMEM (9216 + 2*FSTGB)   // 80896

__global__ void __launch_bounds__(128, 2)
flash_attn3(const fp16* __restrict__ Q_g, const fp16* __restrict__ K_g,
            const fp16* __restrict__ Vt_g, fp16* __restrict__ ctx)
{
    extern __shared__ char sm[];
    const uint32_t sb = smem_u32(sm);
    const int tid = threadIdx.x, wid = tid >> 5, lid = tid & 31;
    const int bh = blockIdx.y;
    const int qt = (gridDim.x - 1) - blockIdx.x;   // heavy tiles first
    const int q0 = qt * 64;
    const int ktmax = qt >> 1;

    const fp16* Qb = Q_g + (size_t)bh * T_ * D_;
    const fp16* Kb = K_g + (size_t)bh * T_ * D_;
    const fp16* Vb = Vt_g + (size_t)bh * D_ * T_;

    // Q tile: 64 rows
    {
        const int row = tid >> 1, half = tid & 1;
        const char* g = (const char*)(Qb + (size_t)(q0 + row) * D_ + half * 32);
        uint32_t d = sb + FQ + row * FROWK + half * 64;
        #pragma unroll
        for (int i = 0; i < 4; i++) cpasync16(d + i * 16, g + i * 16);
    }

    auto issueKV = [&](int stage, int kvt) {
        const int kv0 = kvt * 128;
        const uint32_t s0 = sb + FSTG0 + (uint32_t)stage * FSTGB;
        #pragma unroll
        for (int it = 0; it < 2; it++) {
            const int row = (tid >> 1) + it * 64;      // 0..127
            const int half = tid & 1;
            const char* g = (const char*)(Kb + (size_t)(kv0 + row) * D_ + half * 32);
            uint32_t d = s0 + row * FROWK + half * 64;
            #pragma unroll
            for (int i = 0; i < 4; i++) cpasync16(d + i * 16, g + i * 16);
        }
        #pragma unroll
        for (int it = 0; it < 2; it++) {
            const int row = (tid >> 2) + it * 32;      // 0..63
            const int qtc = tid & 3;
            const char* g = (const char*)(Vb + (size_t)row * T_ + kv0 + qtc * 32);
            uint32_t d = s0 + 18432 + row * FROWV + qtc * 64;
            #pragma unroll
            for (int i = 0; i < 4; i++) cpasync16(d + i * 16, g + i * 16);
        }
        asm volatile("cp.async.commit_group;");
    };

    issueKV(0, 0);

    const int am = lid >> 3;
    uint32_t qf[4][4];
    float m_[2] = {-1e30f, -1e30f}, l_[2] = {0.f, 0.f};
    float oacc[8][4] = {};

    const int r0g = q0 + wid * 16 + (lid >> 2);
    const int c0l = (lid & 3) * 2;

    for (int kt = 0; kt <= ktmax; kt++) {
        if (kt + 1 <= ktmax) { issueKV((kt + 1) & 1, kt + 1); asm volatile("cp.async.wait_group 1;"); }
        else                 { asm volatile("cp.async.wait_group 0;"); }
        __syncthreads();

        if (kt == 0) {
            const uint32_t rowq = wid * 16 + (am & 1) * 8 + (lid & 7);
            #pragma unroll
            for (int ks = 0; ks < 4; ks++) {
                uint32_t off = rowq * FROWK + ks * 32 + (am >> 1) * 16;
                ldsm4(qf[ks], sb + FQ + off);
            }
        }

        const uint32_t stg = sb + FSTG0 + (uint32_t)(kt & 1) * FSTGB;

        float sacc[16][4] = {};
        #pragma unroll
        for (int ks = 0; ks < 4; ks++) {
            #pragma unroll
            for (int ntp = 0; ntp < 8; ntp++) {
                uint32_t kh4[4];
                uint32_t off = (uint32_t)(ntp * 16 + ((lid >> 4) * 8) + (lid & 7)) * FROWK
                             + ks * 32 + ((lid >> 3) & 1) * 16;
                ldsm4(kh4, stg + off);
                mma_f16(sacc[2 * ntp],     qf[ks], kh4[0], kh4[1]);
                mma_f16(sacc[2 * ntp + 1], qf[ks], kh4[2], kh4[3]);
            }
        }

        const bool diag = (kt == ktmax);
        float mx0 = -1e30f, mx1 = -1e30f;
        #pragma unroll
        for (int nt = 0; nt < 16; nt++) {
            #pragma unroll
            for (int j = 0; j < 2; j++) {
                float s = sacc[nt][j] * 0.125f;
                if (diag && (kt * 128 + nt * 8 + c0l + j) > r0g) s = -1e30f;
                sacc[nt][j] = s; mx0 = fmaxf(mx0, s);
            }
            #pragma unroll
            for (int j = 2; j < 4; j++) {
                float s = sacc[nt][j] * 0.125f;
                if (diag && (kt * 128 + nt * 8 + c0l + j - 2) > r0g + 8) s = -1e30f;
                sacc[nt][j] = s; mx1 = fmaxf(mx1, s);
            }
        }
        #pragma unroll
        for (int o = 1; o < 4; o <<= 1) {
            mx0 = fmaxf(mx0, __shfl_xor_sync(0xffffffffu, mx0, o));
            mx1 = fmaxf(mx1, __shfl_xor_sync(0xffffffffu, mx1, o));
        }
        float mn0 = fmaxf(m_[0], mx0), mn1 = fmaxf(m_[1], mx1);
        float cr0 = __expf(m_[0] - mn0), cr1 = __expf(m_[1] - mn1);
        float sum0 = 0.f, sum1 = 0.f;
        #pragma unroll
        for (int nt = 0; nt < 16; nt++) {
            float p0 = __expf(sacc[nt][0] - mn0), p1 = __expf(sacc[nt][1] - mn0);
            float p2 = __expf(sacc[nt][2] - mn1), p3 = __expf(sacc[nt][3] - mn1);
            sacc[nt][0] = p0; sacc[nt][1] = p1; sacc[nt][2] = p2; sacc[nt][3] = p3;
            sum0 += p0 + p1; sum1 += p2 + p3;
        }
        #pragma unroll
        for (int o = 1; o < 4; o <<= 1) {
            sum0 += __shfl_xor_sync(0xffffffffu, sum0, o);
            sum1 += __shfl_xor_sync(0xffffffffu, sum1, o);
        }
        l_[0] = l_[0] * cr0 + sum0; l_[1] = l_[1] * cr1 + sum1;
        m_[0] = mn0; m_[1] = mn1;
        #pragma unroll
        for (int d = 0; d < 8; d++) {
            oacc[d][0] *= cr0; oacc[d][1] *= cr0;
            oacc[d][2] *= cr1; oacc[d][3] *= cr1;
        }

        #pragma unroll
        for (int kvt = 0; kvt < 8; kvt++) {
            uint32_t pa[4];
            pa[0] = packh(sacc[2 * kvt][0],     sacc[2 * kvt][1]);
            pa[1] = packh(sacc[2 * kvt][2],     sacc[2 * kvt][3]);
            pa[2] = packh(sacc[2 * kvt + 1][0], sacc[2 * kvt + 1][1]);
            pa[3] = packh(sacc[2 * kvt + 1][2], sacc[2 * kvt + 1][3]);

            #pragma unroll
            for (int ntp = 0; ntp < 4; ntp++) {
                uint32_t vh4[4];
                uint32_t off = (uint32_t)(ntp * 16 + ((lid >> 4) * 8) + (lid & 7)) * FROWV
                             + kvt * 32 + ((lid >> 3) & 1) * 16;
                ldsm4(vh4, stg + 18432 + off);
                mma_f16(oacc[2 * ntp],     pa, vh4[0], vh4[1]);
                mma_f16(oacc[2 * ntp + 1], pa, vh4[2], vh4[3]);
            }
        }
        __syncthreads();
    }

    const int b = bh / H_, h = bh - b * H_;
    float inv0 = 1.f / l_[0], inv1 = 1.f / l_[1];
    #pragma unroll
    for (int nt = 0; nt < 8; nt++) {
        const int d = nt * 8 + c0l;
        {
            size_t o = ((size_t)(b * T_ + r0g)) * E_ + h * D_ + d;
            *(__half2*)&ctx[o] = __floats2half2_rn(oacc[nt][0] * inv0, oacc[nt][1] * inv0);
        }
        {
            size_t o = ((size_t)(b * T_ + r0g + 8)) * E_ + h * D_ + d;
            *(__half2*)&ctx[o] = __floats2half2_rn(oacc[nt][2] * inv1, oacc[nt][3] * inv1);
        }
    }
}

// ---------------- launch ----------------
extern "C" void kernel_launch(void* const* d_in, const int* in_sizes, int n_in,
                              void* d_out, int out_size)
{
    const float* x    = (const float*)d_in[0];
    const float* wq   = (const float*)d_in[1];
    const float* wk   = (const float*)d_in[2];
    const float* wv   = (const float*)d_in[3];
    const float* wo   = (const float*)d_in[4];
    const float* bo   = (const float*)d_in[5];
    const float* ln1s = (const float*)d_in[6];
    const float* ln1b = (const float*)d_in[7];
    const float* ln2s = (const float*)d_in[8];
    const float* ln2b = (const float*)d_in[9];
    const float* w1   = (const float*)d_in[10];
    const float* b1   = (const float*)d_in[11];
    const float* w2   = (const float*)d_in[12];
    const float* b2   = (const float*)d_in[13];
    float* out = (float*)d_out;

    float *x2;
    fp16 *h1, *q, *k, *vt, *ctx, *h2, *mid;
    fp16 *wqkvT, *woT, *w1T, *w2T;
    cudaGetSymbolAddress((void**)&x2,  g_x2);
    cudaGetSymbolAddress((void**)&h1,  g_h1);
    cudaGetSymbolAddress((void**)&q,   g_q);
    cudaGetSymbolAddress((void**)&k,   g_k);
    cudaGetSymbolAddress((void**)&vt,  g_vt);
    cudaGetSymbolAddress((void**)&ctx, g_ctx);
    cudaGetSymbolAddress((void**)&h2,  g_h2);
    cudaGetSymbolAddress((void**)&mid, g_mid);
    cudaGetSymbolAddress((void**)&wqkvT, g_wqkvT);
    cudaGetSymbolAddress((void**)&woT, g_woT);
    cudaGetSymbolAddress((void**)&w1T, g_w1T);
    cudaGetSymbolAddress((void**)&w2T, g_w2T);

    cudaFuncSetAttribute(flash_attn3, cudaFuncAttributeMaxDynamicSharedMemorySize, FA3_SMEM);
    cudaFuncSetAttribute(mma_gemm<EPI_QKV>,        cudaFuncAttributeMaxDynamicSharedMemorySize, GEMM_SMEM);
    cudaFuncSetAttribute(mma_gemm<EPI_BIAS_RESID>, cudaFuncAttributeMaxDynamicSharedMemorySize, GEMM_SMEM);
    cudaFuncSetAttribute(mma_gemm<EPI_BIAS_GELU>,  cudaFuncAttributeMaxDynamicSharedMemorySize, GEMM_SMEM);

    // weight transpose+round; wq/wk/wv stacked into [2304,768]
    wsplitT4<<<dim3(E_/32, E_/32, 4), 256>>>(wq, wk, wv, wo, wqkvT, woT);
    wsplitT<<<dim3(FF_/32, E_/32), 256>>>(w1, w1T, E_, FF_);
    wsplitT<<<dim3(E_/32, FF_/32), 256>>>(w2, w2T, FF_, E_);

    // LN1 -> h1 (fp16), warp-per-row
    ln_kernel<<<M_/8, 256>>>(x, ln1s, ln1b, h1);

    // fused QKV -> Q, K, Vt (fp16; V staged via smem transpose)
    mma_gemm<EPI_QKV><<<dim3(QKVN/128, M_/128), 256, GEMM_SMEM>>>(
        h1, wqkvT, nullptr, nullptr, nullptr, q, k, vt, nullptr, QKVN, E_);

    // flash attention (64q tiles, occ=2) -> ctx fp16
    flash_attn3<<<dim3(T_/64, BH_), 128, FA3_SMEM>>>(q, k, vt, ctx);

    // proj + bias + resid -> x2
    mma_gemm<EPI_BIAS_RESID><<<dim3(E_/128, M_/128), 256, GEMM_SMEM>>>(
        ctx, woT, bo, x, x2, nullptr, nullptr, nullptr, nullptr, E_, E_);

    // LN2 -> h2 (fp16), warp-per-row
    ln_kernel<<<M_/8, 256>>>(x2, ln2s, ln2b, h2);

    // MLP1 (gelu, tanh.approx) -> mid fp16
    mma_gemm<EPI_BIAS_GELU><<<dim3(FF_/128, M_/128), 256, GEMM_SMEM>>>(
        h2, w1T, b1, nullptr, nullptr, nullptr, nullptr, nullptr, mid, FF_, E_);

    // MLP2 + bias + resid -> out
    mma_gemm<EPI_BIAS_RESID><<<dim3(E_/128, M_/128), 256, GEMM_SMEM>>>(
        mid, w2T, b2, x2, out, nullptr, nullptr, nullptr, nullptr, E_, FF_);
}

// round 14
// speedup vs baseline: 2.7256x; 1.0063x over previous
#include <cuda_runtime.h>
#include <cuda_fp16.h>
#include <math.h>
#include <cstdint>

#define B_  2
#define T_  2048
#define E_  768
#define H_  12
#define D_  64
#define M_  (B_*T_)    // 4096
#define FF_ (4*E_)     // 3072
#define BH_ (B_*H_)    // 24
#define QKVN (3*E_)    // 2304

typedef __half fp16;

// ---------------- scratch ----------------
__device__ float g_x2[M_*E_];
__device__ fp16 g_h1[M_*E_];
__device__ fp16 g_q [M_*E_];                   // [B,H,T,D]
__device__ fp16 g_k [M_*E_];                   // [B,H,T,D]
__device__ fp16 g_vt[M_*E_];                   // [B,H,D,T]
__device__ fp16 g_ctx[M_*E_];
__device__ fp16 g_h2[M_*E_];
__device__ fp16 g_mid[(size_t)M_*FF_];
__device__ fp16 g_wqkvT[(size_t)QKVN*E_];
__device__ fp16 g_woT[E_*E_];
__device__ fp16 g_w1T[(size_t)E_*FF_];
__device__ fp16 g_w2T[(size_t)E_*FF_];

// ---------------- helpers ----------------
__device__ __forceinline__ uint32_t smem_u32(const void* p) {
    uint32_t a;
    asm("{ .reg .u64 t; cvta.to.shared.u64 t, %1; cvt.u32.u64 %0, t; }" : "=r"(a) : "l"(p));
    return a;
}
__device__ __forceinline__ void cpasync16(uint32_t dst, const void* src) {
    asm volatile("cp.async.ca.shared.global [%0], [%1], 16;" :: "r"(dst), "l"(src));
}
__device__ __forceinline__ void ldsm4(uint32_t* r, uint32_t addr) {
    asm volatile("ldmatrix.sync.aligned.m8n8.x4.shared.b16 {%0,%1,%2,%3}, [%4];"
        : "=r"(r[0]), "=r"(r[1]), "=r"(r[2]), "=r"(r[3]) : "r"(addr));
}
__device__ __forceinline__ void mma_f16(float* c, const uint32_t* a, uint32_t b0, uint32_t b1) {
    asm volatile("mma.sync.aligned.m16n8k16.row.col.f32.f16.f16.f32 "
        "{%0,%1,%2,%3}, {%4,%5,%6,%7}, {%8,%9}, {%0,%1,%2,%3};"
        : "+f"(c[0]), "+f"(c[1]), "+f"(c[2]), "+f"(c[3])
        : "r"(a[0]), "r"(a[1]), "r"(a[2]), "r"(a[3]), "r"(b0), "r"(b1));
}
__device__ __forceinline__ uint32_t packh(float a, float b) {
    __half2 t = __floats2half2_rn(a, b);
    return *(uint32_t*)&t;
}
__device__ __forceinline__ float tanh_fast(float x) {
    float y;
    asm("tanh.approx.f32 %0, %1;" : "=f"(y) : "f"(x));
    return y;
}

// ---------------- fused preamble: all weight converts + LN1 in ONE launch ----------------
// block ranges:
//   [0, 2304)        : four E x E transposes (wq, wk, wv -> wqkvT stacked; wo -> woT)
//   [2304, 4608)     : w1 [E, FF]  -> w1T [FF, E]
//   [4608, 6912)     : w2 [FF, E]  -> w2T [E, FF]
//   [6912, 7424)     : LN1 (warp-per-row, 8 rows/block)
#define NB_EE   2304
#define NB_W1   2304
#define NB_W2   2304
#define NB_LN   512
#define NB_PREP (NB_EE + NB_W1 + NB_W2 + NB_LN)

__device__ __forceinline__ void wconv_tile(const float* __restrict__ w, fp16* __restrict__ o,
                                           int K, int N, int bx, int by, float (*t)[33])
{
    const int tx = threadIdx.x & 31, ty = threadIdx.x >> 5;
    const int n0 = bx * 32, k0 = by * 32;
    #pragma unroll
    for (int i = 0; i < 32; i += 8)
        t[ty + i][tx] = w[(size_t)(k0 + ty + i) * N + n0 + tx];
    __syncthreads();
    #pragma unroll
    for (int i = 0; i < 32; i += 8)
        o[(size_t)(n0 + ty + i) * K + k0 + tx] = __float2half_rn(t[tx][ty + i]);
}

__global__ void __launch_bounds__(256)
prep_kernel(const float* __restrict__ x,
            const float* __restrict__ ln1s, const float* __restrict__ ln1b,
            const float* __restrict__ wq, const float* __restrict__ wk,
            const float* __restrict__ wv, const float* __restrict__ wo,
            const float* __restrict__ w1, const float* __restrict__ w2,
            fp16* __restrict__ h1, fp16* __restrict__ wqkvT, fp16* __restrict__ woT,
            fp16* __restrict__ w1T, fp16* __restrict__ w2T)
{
    __shared__ float t[32][33];
    const int bid = blockIdx.x;

    if (bid < NB_EE) {
        const int z = bid / 576, r = bid - z * 576;
        const float* w = (z == 0) ? wq : (z == 1) ? wk : (z == 2) ? wv : wo;
        fp16* o = (z < 3) ? wqkvT + (size_t)z * E_ * E_ : woT;
        wconv_tile(w, o, E_, E_, r % 24, r / 24, t);
    } else if (bid < NB_EE + NB_W1) {
        const int r = bid - NB_EE;
        wconv_tile(w1, w1T, E_, FF_, r % 96, r / 96, t);
    } else if (bid < NB_EE + NB_W1 + NB_W2) {
        const int r = bid - NB_EE - NB_W1;
        wconv_tile(w2, w2T, FF_, E_, r % 24, r / 24, t);
    } else {
        // LN1: warp-per-row
        const int warp = threadIdx.x >> 5, lane = threadIdx.x & 31;
        const int row = (bid - NB_EE - NB_W1 - NB_W2) * 8 + warp;
        const float* xr = x + (size_t)row * E_;

        float4 v[6];
        float s = 0.f, s2 = 0.f;
        #pragma unroll
        for (int p = 0; p < 6; p++) {
            v[p] = *(const float4*)&xr[lane * 4 + p * 128];
            s  += v[p].x + v[p].y + v[p].z + v[p].w;
            s2 += v[p].x * v[p].x + v[p].y * v[p].y + v[p].z * v[p].z + v[p].w * v[p].w;
        }
        #pragma unroll
        for (int o = 16; o; o >>= 1) {
            s  += __shfl_xor_sync(0xffffffffu, s,  o);
            s2 += __shfl_xor_sync(0xffffffffu, s2, o);
        }
        const float mean = s * (1.f / E_);
        const float var  = (s2 - s * mean) * (1.f / (E_ - 1));
        const float rstd = rsqrtf(var + 1e-5f);

        fp16* orow = h1 + (size_t)row * E_;
        #pragma unroll
        for (int p = 0; p < 6; p++) {
            const int i = lane * 4 + p * 128;
            float4 c = *(const float4*)&ln1s[i];
            float4 b = *(const float4*)&ln1b[i];
            __half2 h0 = __floats2half2_rn(c.x * (v[p].x - mean) * rstd + b.x,
                                           c.y * (v[p].y - mean) * rstd + b.y);
            __half2 h1v = __floats2half2_rn(c.z * (v[p].z - mean) * rstd + b.z,
                                            c.w * (v[p].w - mean) * rstd + b.w);
            uint2 pk = make_uint2(*(uint32_t*)&h0, *(uint32_t*)&h1v);
            *(uint2*)&orow[i] = pk;
        }
    }
}

// ---------------- LayerNorm (ddof=1), warp-per-row -> fp16 (LN2) ----------------
__global__ void __launch_bounds__(256)
ln_kernel(const float* __restrict__ x, const float* __restrict__ sc,
          const float* __restrict__ sh, fp16* __restrict__ o16)
{
    const int warp = threadIdx.x >> 5, lane = threadIdx.x & 31;
    const int row = blockIdx.x * 8 + warp;
    const float* xr = x + (size_t)row * E_;

    float4 v[6];
    float s = 0.f, s2 = 0.f;
    #pragma unroll
    for (int p = 0; p < 6; p++) {
        v[p] = *(const float4*)&xr[lane * 4 + p * 128];
        s  += v[p].x + v[p].y + v[p].z + v[p].w;
        s2 += v[p].x * v[p].x + v[p].y * v[p].y + v[p].z * v[p].z + v[p].w * v[p].w;
    }
    #pragma unroll
    for (int o = 16; o; o >>= 1) {
        s  += __shfl_xor_sync(0xffffffffu, s,  o);
        s2 += __shfl_xor_sync(0xffffffffu, s2, o);
    }
    const float mean = s * (1.f / E_);
    const float var  = (s2 - s * mean) * (1.f / (E_ - 1));
    const float rstd = rsqrtf(var + 1e-5f);

    fp16* orow = o16 + (size_t)row * E_;
    #pragma unroll
    for (int p = 0; p < 6; p++) {
        const int i = lane * 4 + p * 128;
        float4 c = *(const float4*)&sc[i];
        float4 b = *(const float4*)&sh[i];
        __half2 h0 = __floats2half2_rn(c.x * (v[p].x - mean) * rstd + b.x,
                                       c.y * (v[p].y - mean) * rstd + b.y);
        __half2 h1 = __floats2half2_rn(c.z * (v[p].z - mean) * rstd + b.z,
                                       c.w * (v[p].w - mean) * rstd + b.w);
        uint2 pk = make_uint2(*(uint32_t*)&h0, *(uint32_t*)&h1);
        *(uint2*)&orow[i] = pk;
    }
}

// ---------------- warp-MMA GEMM: fp16 single-term, 2-stage cp.async, occ=2 ----------------
enum { EPI_QKV = 0, EPI_BIAS_RESID = 1, EPI_BIAS_GELU = 2 };

#define KCH     64
#define ROWB    144
#define TILE_B  (128*ROWB)      // 18432
#define STAGE_B (2*TILE_B)      // 36864 (A, B)
#define GEMM_SMEM (2*STAGE_B)   // 73728
#define VROW    272

template<int EPI>
__global__ void __launch_bounds__(256, 2)
mma_gemm(const fp16* __restrict__ A_g, const fp16* __restrict__ B_g,
         const float* __restrict__ bias, const float* __restrict__ resid,
         float* __restrict__ C,
         fp16* __restrict__ Qo, fp16* __restrict__ Ko, fp16* __restrict__ Vto,
         fp16* __restrict__ C16,
         int N, int K)
{
    extern __shared__ char sm[];
    const uint32_t sbase = smem_u32(sm);
    const int tid = threadIdx.x, wid = tid >> 5, lid = tid & 31;
    const int m0 = blockIdx.y * 128, n0 = blockIdx.x * 128;
    const int wm = wid >> 2, wn = wid & 3;

    const int lrow = tid >> 3;
    const int lcb  = (tid & 7) * 16;

    float acc[4][4][4] = {};

    const fp16* gs[2] = {A_g, B_g};
    const int   r0s[2] = {m0, n0};

    auto issue = [&](int c) {
        const int k0 = c * KCH;
        const uint32_t sb = sbase + (uint32_t)(c & 1) * STAGE_B;
        #pragma unroll
        for (int t = 0; t < 2; t++) {
            const char* g = (const char*)(gs[t] + (size_t)(r0s[t] + lrow) * K + k0) + lcb;
            uint32_t d = sb + t * TILE_B + lrow * ROWB + lcb;
            #pragma unroll
            for (int i = 0; i < 4; i++)
                cpasync16(d + i * 32 * ROWB, g + (size_t)i * 32 * K * 2);
        }
        asm volatile("cp.async.commit_group;");
    };

    const int NC = K / KCH;
    issue(0);

    const int am = (lid >> 3);
    const uint32_t aRow = wm * 64 + (am & 1) * 8 + (lid & 7);
    const uint32_t aColH = (am >> 1) * 16;
    const uint32_t bRowBase = wn * 32 + (lid & 7);
    const uint32_t bNt = (am >> 1);
    const uint32_t bColH = (am & 1) * 16;

    for (int c = 0; c < NC; c++) {
        if (c + 1 < NC) { issue(c + 1); asm volatile("cp.async.wait_group 1;"); }
        else            { asm volatile("cp.async.wait_group 0;"); }
        __syncthreads();

        const uint32_t sb = sbase + (uint32_t)(c & 1) * STAGE_B;
        const uint32_t aB = sb, bB = sb + TILE_B;

        #pragma unroll
        for (int ks = 0; ks < 4; ks++) {
            uint32_t bh[2][4];
            #pragma unroll
            for (int p = 0; p < 2; p++) {
                uint32_t row = bRowBase + (p * 2 + bNt) * 8;
                uint32_t off = row * ROWB + ks * 32 + bColH;
                ldsm4(bh[p], bB + off);
            }
            #pragma unroll
            for (int mt = 0; mt < 4; mt++) {
                uint32_t ah[4];
                uint32_t off = (aRow + mt * 16) * ROWB + ks * 32 + aColH;
                ldsm4(ah, aB + off);
                #pragma unroll
                for (int nt = 0; nt < 4; nt++) {
                    const int p = nt >> 1, q = (nt & 1) * 2;
                    mma_f16(acc[mt][nt], ah, bh[p][q], bh[p][q + 1]);
                }
            }
        }
        __syncthreads();
    }

    const bool isV = (EPI == EPI_QKV) && (n0 >= 2 * E_);

    #pragma unroll
    for (int mt = 0; mt < 4; mt++) {
        #pragma unroll
        for (int nt = 0; nt < 4; nt++) {
            const int r0 = m0 + wm * 64 + mt * 16 + (lid >> 2);
            const int cc = n0 + wn * 32 + nt * 8 + (lid & 3) * 2;
            #pragma unroll
            for (int hh = 0; hh < 2; hh++) {
                const int r = r0 + hh * 8;
                float v0 = acc[mt][nt][hh * 2], v1 = acc[mt][nt][hh * 2 + 1];
                if (EPI == EPI_QKV) {
                    if (isV) {
                        const int rl = r - m0;
                        const int cl = cc - n0;
                        *(fp16*)(sm + cl * VROW + rl * 2)       = __float2half_rn(v0);
                        *(fp16*)(sm + (cl + 1) * VROW + rl * 2) = __float2half_rn(v1);
                    } else {
                        const int bb = r >> 11, tt = r & (T_ - 1);
                        int which = (cc >= E_) ? 1 : 0;
                        int nn = cc - which * E_;
                        int hx = nn >> 6, d = nn & 63;
                        size_t o = ((size_t)(bb * H_ + hx) * T_ + tt) * D_ + d;
                        fp16* dst = (which == 0) ? Qo : Ko;
                        *(__half2*)&dst[o] = __floats2half2_rn(v0, v1);
                    }
                } else if (EPI == EPI_BIAS_RESID) {
                    size_t o = (size_t)r * N + cc;
                    float2 bs = *(const float2*)&bias[cc];
                    float2 rs = *(const float2*)&resid[o];
                    *(float2*)&C[o] = make_float2(v0 + bs.x + rs.x, v1 + bs.y + rs.y);
                } else {
                    size_t o = (size_t)r * N + cc;
                    float2 bs = *(const float2*)&bias[cc];
                    float vv[2] = {v0 + bs.x, v1 + bs.y};
                    #pragma unroll
                    for (int j = 0; j < 2; j++) {
                        float v = vv[j];
                        float u = 0.7978845608028654f * (v + 0.044715f * v * v * v);
                        vv[j] = 0.5f * v * (1.f + tanh_fast(u));
                    }
                    *(__half2*)&C16[o] = __floats2half2_rn(vv[0], vv[1]);
                }
            }
        }
    }

    if (isV) {
        __syncthreads();
        const int bb = m0 >> 11, tt0 = m0 & (T_ - 1);
        const int nh = n0 - 2 * E_;
        #pragma unroll
        for (int it = 0; it < 8; it++) {
            const int nl = it * 16 + (tid >> 4);
            const int hx = (nh + nl) >> 6, d = (nh + nl) & 63;
            const uint4 v = *(const uint4*)(sm + nl * VROW + (tid & 15) * 16);
            *(uint4*)&Vto[((size_t)(bb * H_ + hx) * D_ + d) * T_ + tt0 + (tid & 15) * 8] = v;
        }
    }
}

// ---------------- flash attention: 64q x 128kv tiles, 128 threads, occ=2 ----------------
#define FROWK 144
#define FROWV 272
#define FQ    0
#define FSTG0 9216
#define FSTGB 35840
#define FA3_SMEM (9216 + 2*FSTGB)   // 80896

__global__ void __launch_bounds__(128, 2)
flash_attn3(const fp16* __restrict__ Q_g, const fp16* __restrict__ K_g,
            const fp16* __restrict__ Vt_g, fp16* __restrict__ ctx)
{
    extern __shared__ char sm[];
    const uint32_t sb = smem_u32(sm);
    const int tid = threadIdx.x, wid = tid >> 5, lid = tid & 31;
    const int bh = blockIdx.y;
    const int qt = (gridDim.x - 1) - blockIdx.x;
    const int q0 = qt * 64;
    const int ktmax = qt >> 1;

    const fp16* Qb = Q_g + (size_t)bh * T_ * D_;
    const fp16* Kb = K_g + (size_t)bh * T_ * D_;
    const fp16* Vb = Vt_g + (size_t)bh * D_ * T_;

    {
        const int row = tid >> 1, half = tid & 1;
        const char* g = (const char*)(Qb + (size_t)(q0 + row) * D_ + half * 32);
        uint32_t d = sb + FQ + row * FROWK + half * 64;
        #pragma unroll
        for (int i = 0; i < 4; i++) cpasync16(d + i * 16, g + i * 16);
    }

    auto issueKV = [&](int stage, int kvt) {
        const int kv0 = kvt * 128;
        const uint32_t s0 = sb + FSTG0 + (uint32_t)stage * FSTGB;
        #pragma unroll
        for (int it = 0; it < 2; it++) {
            const int row = (tid >> 1) + it * 64;
            const int half = tid & 1;
            const char* g = (const char*)(Kb + (size_t)(kv0 + row) * D_ + half * 32);
            uint32_t d = s0 + row * FROWK + half * 64;
            #pragma unroll
            for (int i = 0; i < 4; i++) cpasync16(d + i * 16, g + i * 16);
        }
        #pragma unroll
        for (int it = 0; it < 2; it++) {
            const int row = (tid >> 2) + it * 32;
            const int qtc = tid & 3;
            const char* g = (const char*)(Vb + (size_t)row * T_ + kv0 + qtc * 32);
            uint32_t d = s0 + 18432 + row * FROWV + qtc * 64;
            #pragma unroll
            for (int i = 0; i < 4; i++) cpasync16(d + i * 16, g + i * 16);
        }
        asm volatile("cp.async.commit_group;");
    };

    issueKV(0, 0);

    const int am = lid >> 3;
    uint32_t qf[4][4];
    float m_[2] = {-1e30f, -1e30f}, l_[2] = {0.f, 0.f};
    float oacc[8][4] = {};

    const int r0g = q0 + wid * 16 + (lid >> 2);
    const int c0l = (lid & 3) * 2;

    for (int kt = 0; kt <= ktmax; kt++) {
        if (kt + 1 <= ktmax) { issueKV((kt + 1) & 1, kt + 1); asm volatile("cp.async.wait_group 1;"); }
        else                 { asm volatile("cp.async.wait_group 0;"); }
        __syncthreads();

        if (kt == 0) {
            const uint32_t rowq = wid * 16 + (am & 1) * 8 + (lid & 7);
            #pragma unroll
            for (int ks = 0; ks < 4; ks++) {
                uint32_t off = rowq * FROWK + ks * 32 + (am >> 1) * 16;
                ldsm4(qf[ks], sb + FQ + off);
            }
        }

        const uint32_t stg = sb + FSTG0 + (uint32_t)(kt & 1) * FSTGB;

        float sacc[16][4] = {};
        #pragma unroll
        for (int ks = 0; ks < 4; ks++) {
            #pragma unroll
            for (int ntp = 0; ntp < 8; ntp++) {
                uint32_t kh4[4];
                uint32_t off = (uint32_t)(ntp * 16 + ((lid >> 4) * 8) + (lid & 7)) * FROWK
                             + ks * 32 + ((lid >> 3) & 1) * 16;
                ldsm4(kh4, stg + off);
                mma_f16(sacc[2 * ntp],     qf[ks], kh4[0], kh4[1]);
                mma_f16(sacc[2 * ntp + 1], qf[ks], kh4[2], kh4[3]);
            }
        }

        const bool diag = (kt == ktmax);
        float mx0 = -1e30f, mx1 = -1e30f;
        #pragma unroll
        for (int nt = 0; nt < 16; nt++) {
            #pragma unroll
            for (int j = 0; j < 2; j++) {
                float s = sacc[nt][j] * 0.125f;
                if (diag && (kt * 128 + nt * 8 + c0l + j) > r0g) s = -1e30f;
                sacc[nt][j] = s; mx0 = fmaxf(mx0, s);
            }
            #pragma unroll
            for (int j = 2; j < 4; j++) {
                float s = sacc[nt][j] * 0.125f;
                if (diag && (kt * 128 + nt * 8 + c0l + j - 2) > r0g + 8) s = -1e30f;
                sacc[nt][j] = s; mx1 = fmaxf(mx1, s);
            }
        }
        #pragma unroll
        for (int o = 1; o < 4; o <<= 1) {
            mx0 = fmaxf(mx0, __shfl_xor_sync(0xffffffffu, mx0, o));
            mx1 = fmaxf(mx1, __shfl_xor_sync(0xffffffffu, mx1, o));
        }
        float mn0 = fmaxf(m_[0], mx0), mn1 = fmaxf(m_[1], mx1);
        float cr0 = __expf(m_[0] - mn0), cr1 = __expf(m_[1] - mn1);
        float sum0 = 0.f, sum1 = 0.f;
        #pragma unroll
        for (int nt = 0; nt < 16; nt++) {
            float p0 = __expf(sacc[nt][0] - mn0), p1 = __expf(sacc[nt][1] - mn0);
            float p2 = __expf(sacc[nt][2] - mn1), p3 = __expf(sacc[nt][3] - mn1);
            sacc[nt][0] = p0; sacc[nt][1] = p1; sacc[nt][2] = p2; sacc[nt][3] = p3;
            sum0 += p0 + p1; sum1 += p2 + p3;
        }
        #pragma unroll
        for (int o = 1; o < 4; o <<= 1) {
            sum0 += __shfl_xor_sync(0xffffffffu, sum0, o);
            sum1 += __shfl_xor_sync(0xffffffffu, sum1, o);
        }
        l_[0] = l_[0] * cr0 + sum0; l_[1] = l_[1] * cr1 + sum1;
        m_[0] = mn0; m_[1] = mn1;
        #pragma unroll
        for (int d = 0; d < 8; d++) {
            oacc[d][0] *= cr0; oacc[d][1] *= cr0;
            oacc[d][2] *= cr1; oacc[d][3] *= cr1;
        }

        #pragma unroll
        for (int kvt = 0; kvt < 8; kvt++) {
            uint32_t pa[4];
            pa[0] = packh(sacc[2 * kvt][0],     sacc[2 * kvt][1]);
            pa[1] = packh(sacc[2 * kvt][2],     sacc[2 * kvt][3]);
            pa[2] = packh(sacc[2 * kvt + 1][0], sacc[2 * kvt + 1][1]);
            pa[3] = packh(sacc[2 * kvt + 1][2], sacc[2 * kvt + 1][3]);

            #pragma unroll
            for (int ntp = 0; ntp < 4; ntp++) {
                uint32_t vh4[4];
                uint32_t off = (uint32_t)(ntp * 16 + ((lid >> 4) * 8) + (lid & 7)) * FROWV
                             + kvt * 32 + ((lid >> 3) & 1) * 16;
                ldsm4(vh4, stg + 18432 + off);
                mma_f16(oacc[2 * ntp],     pa, vh4[0], vh4[1]);
                mma_f16(oacc[2 * ntp + 1], pa, vh4[2], vh4[3]);
            }
        }
        __syncthreads();
    }

    const int b = bh / H_, h = bh - b * H_;
    float inv0 = 1.f / l_[0], inv1 = 1.f / l_[1];
    #pragma unroll
    for (int nt = 0; nt < 8; nt++) {
        const int d = nt * 8 + c0l;
        {
            size_t o = ((size_t)(b * T_ + r0g)) * E_ + h * D_ + d;
            *(__half2*)&ctx[o] = __floats2half2_rn(oacc[nt][0] * inv0, oacc[nt][1] * inv0);
        }
        {
            size_t o = ((size_t)(b * T_ + r0g + 8)) * E_ + h * D_ + d;
            *(__half2*)&ctx[o] = __floats2half2_rn(oacc[nt][2] * inv1, oacc[nt][3] * inv1);
        }
    }
}

// ---------------- launch ----------------
extern "C" void kernel_launch(void* const* d_in, const int* in_sizes, int n_in,
                              void* d_out, int out_size)
{
    const float* x    = (const float*)d_in[0];
    const float* wq   = (const float*)d_in[1];
    const float* wk   = (const float*)d_in[2];
    const float* wv   = (const float*)d_in[3];
    const float* wo   = (const float*)d_in[4];
    const float* bo   = (const float*)d_in[5];
    const float* ln1s = (const float*)d_in[6];
    const float* ln1b = (const float*)d_in[7];
    const float* ln2s = (const float*)d_in[8];
    const float* ln2b = (const float*)d_in[9];
    const float* w1   = (const float*)d_in[10];
    const float* b1   = (const float*)d_in[11];
    const float* w2   = (const float*)d_in[12];
    const float* b2   = (const float*)d_in[13];
    float* out = (float*)d_out;

    float *x2;
    fp16 *h1, *q, *k, *vt, *ctx, *h2, *mid;
    fp16 *wqkvT, *woT, *w1T, *w2T;
    cudaGetSymbolAddress((void**)&x2,  g_x2);
    cudaGetSymbolAddress((void**)&h1,  g_h1);
    cudaGetSymbolAddress((void**)&q,   g_q);
    cudaGetSymbolAddress((void**)&k,   g_k);
    cudaGetSymbolAddress((void**)&vt,  g_vt);
    cudaGetSymbolAddress((void**)&ctx, g_ctx);
    cudaGetSymbolAddress((void**)&h2,  g_h2);
    cudaGetSymbolAddress((void**)&mid, g_mid);
    cudaGetSymbolAddress((void**)&wqkvT, g_wqkvT);
    cudaGetSymbolAddress((void**)&woT, g_woT);
    cudaGetSymbolAddress((void**)&w1T, g_w1T);
    cudaGetSymbolAddress((void**)&w2T, g_w2T);

    cudaFuncSetAttribute(flash_attn3, cudaFuncAttributeMaxDynamicSharedMemorySize, FA3_SMEM);
    cudaFuncSetAttribute(mma_gemm<EPI_QKV>,        cudaFuncAttributeMaxDynamicSharedMemorySize, GEMM_SMEM);
    cudaFuncSetAttribute(mma_gemm<EPI_BIAS_RESID>, cudaFuncAttributeMaxDynamicSharedMemorySize, GEMM_SMEM);
    cudaFuncSetAttribute(mma_gemm<EPI_BIAS_GELU>,  cudaFuncAttributeMaxDynamicSharedMemorySize, GEMM_SMEM);

    // fused preamble: all weight conversions + LN1 in one launch
    prep_kernel<<<NB_PREP, 256>>>(x, ln1s, ln1b, wq, wk, wv, wo, w1, w2,
                                  h1, wqkvT, woT, w1T, w2T);

    // fused QKV -> Q, K, Vt (fp16; V staged via smem transpose)
    mma_gemm<EPI_QKV><<<dim3(QKVN/128, M_/128), 256, GEMM_SMEM>>>(
        h1, wqkvT, nullptr, nullptr, nullptr, q, k, vt, nullptr, QKVN, E_);

    // flash attention (64q tiles, occ=2) -> ctx fp16
    flash_attn3<<<dim3(T_/64, BH_), 128, FA3_SMEM>>>(q, k, vt, ctx);

    // proj + bias + resid -> x2
    mma_gemm<EPI_BIAS_RESID><<<dim3(E_/128, M_/128), 256, GEMM_SMEM>>>(
        ctx, woT, bo, x, x2, nullptr, nullptr, nullptr, nullptr, E_, E_);

    // LN2 -> h2 (fp16), warp-per-row
    ln_kernel<<<M_/8, 256>>>(x2, ln2s, ln2b, h2);

    // MLP1 (gelu, tanh.approx) -> mid fp16
    mma_gemm<EPI_BIAS_GELU><<<dim3(FF_/128, M_/128), 256, GEMM_SMEM>>>(
        h2, w1T, b1, nullptr, nullptr, nullptr, nullptr, nullptr, mid, FF_, E_);

    // MLP2 + bias + resid -> out
    mma_gemm<EPI_BIAS_RESID><<<dim3(E_/128, M_/128), 256, GEMM_SMEM>>>(
        mid, w2T, b2, x2, out, nullptr, nullptr, nullptr, nullptr, E_, FF_);
}

// round 15
// speedup vs baseline: 2.7798x; 1.0199x over previous
#include <cuda_runtime.h>
#include <cuda_fp16.h>
#include <math.h>
#include <cstdint>

#define B_  2
#define T_  2048
#define E_  768
#define H_  12
#define D_  64
#define M_  (B_*T_)    // 4096
#define FF_ (4*E_)     // 3072
#define BH_ (B_*H_)    // 24
#define QKVN (3*E_)    // 2304

typedef __half fp16;

// ---------------- scratch ----------------
__device__ float g_x2[M_*E_];
__device__ fp16 g_h1[M_*E_];
__device__ fp16 g_q [M_*E_];                   // [B,H,T,D]
__device__ fp16 g_k [M_*E_];                   // [B,H,T,D]
__device__ fp16 g_vt[M_*E_];                   // [B,H,D,T]
__device__ fp16 g_ctx[M_*E_];
__device__ fp16 g_h2[M_*E_];
__device__ fp16 g_mid[(size_t)M_*FF_];
__device__ fp16 g_wqkvT[(size_t)QKVN*E_];
__device__ fp16 g_woT[E_*E_];
__device__ fp16 g_w1T[(size_t)E_*FF_];
__device__ fp16 g_w2T[(size_t)E_*FF_];

// ---------------- helpers ----------------
__device__ __forceinline__ uint32_t smem_u32(const void* p) {
    uint32_t a;
    asm("{ .reg .u64 t; cvta.to.shared.u64 t, %1; cvt.u32.u64 %0, t; }" : "=r"(a) : "l"(p));
    return a;
}
__device__ __forceinline__ void cpasync16(uint32_t dst, const void* src) {
    asm volatile("cp.async.ca.shared.global [%0], [%1], 16;" :: "r"(dst), "l"(src));
}
__device__ __forceinline__ void ldsm4(uint32_t* r, uint32_t addr) {
    asm volatile("ldmatrix.sync.aligned.m8n8.x4.shared.b16 {%0,%1,%2,%3}, [%4];"
        : "=r"(r[0]), "=r"(r[1]), "=r"(r[2]), "=r"(r[3]) : "r"(addr));
}
__device__ __forceinline__ void mma_f16(float* c, const uint32_t* a, uint32_t b0, uint32_t b1) {
    asm volatile("mma.sync.aligned.m16n8k16.row.col.f32.f16.f16.f32 "
        "{%0,%1,%2,%3}, {%4,%5,%6,%7}, {%8,%9}, {%0,%1,%2,%3};"
        : "+f"(c[0]), "+f"(c[1]), "+f"(c[2]), "+f"(c[3])
        : "r"(a[0]), "r"(a[1]), "r"(a[2]), "r"(a[3]), "r"(b0), "r"(b1));
}
__device__ __forceinline__ uint32_t packh(float a, float b) {
    __half2 t = __floats2half2_rn(a, b);
    return *(uint32_t*)&t;
}
__device__ __forceinline__ float tanh_fast(float x) {
    float y;
    asm("tanh.approx.f32 %0, %1;" : "=f"(y) : "f"(x));
    return y;
}

// ---------------- fused preamble (R14) ----------------
#define NB_EE   2304
#define NB_W1   2304
#define NB_W2   2304
#define NB_LN   512
#define NB_PREP (NB_EE + NB_W1 + NB_W2 + NB_LN)

__device__ __forceinline__ void wconv_tile(const float* __restrict__ w, fp16* __restrict__ o,
                                           int K, int N, int bx, int by, float (*t)[33])
{
    const int tx = threadIdx.x & 31, ty = threadIdx.x >> 5;
    const int n0 = bx * 32, k0 = by * 32;
    #pragma unroll
    for (int i = 0; i < 32; i += 8)
        t[ty + i][tx] = w[(size_t)(k0 + ty + i) * N + n0 + tx];
    __syncthreads();
    #pragma unroll
    for (int i = 0; i < 32; i += 8)
        o[(size_t)(n0 + ty + i) * K + k0 + tx] = __float2half_rn(t[tx][ty + i]);
}

__global__ void __launch_bounds__(256)
prep_kernel(const float* __restrict__ x,
            const float* __restrict__ ln1s, const float* __restrict__ ln1b,
            const float* __restrict__ wq, const float* __restrict__ wk,
            const float* __restrict__ wv, const float* __restrict__ wo,
            const float* __restrict__ w1, const float* __restrict__ w2,
            fp16* __restrict__ h1, fp16* __restrict__ wqkvT, fp16* __restrict__ woT,
            fp16* __restrict__ w1T, fp16* __restrict__ w2T)
{
    __shared__ float t[32][33];
    const int bid = blockIdx.x;

    if (bid < NB_EE) {
        const int z = bid / 576, r = bid - z * 576;
        const float* w = (z == 0) ? wq : (z == 1) ? wk : (z == 2) ? wv : wo;
        fp16* o = (z < 3) ? wqkvT + (size_t)z * E_ * E_ : woT;
        wconv_tile(w, o, E_, E_, r % 24, r / 24, t);
    } else if (bid < NB_EE + NB_W1) {
        const int r = bid - NB_EE;
        wconv_tile(w1, w1T, E_, FF_, r % 96, r / 96, t);
    } else if (bid < NB_EE + NB_W1 + NB_W2) {
        const int r = bid - NB_EE - NB_W1;
        wconv_tile(w2, w2T, FF_, E_, r % 24, r / 24, t);
    } else {
        const int warp = threadIdx.x >> 5, lane = threadIdx.x & 31;
        const int row = (bid - NB_EE - NB_W1 - NB_W2) * 8 + warp;
        const float* xr = x + (size_t)row * E_;

        float4 v[6];
        float s = 0.f, s2 = 0.f;
        #pragma unroll
        for (int p = 0; p < 6; p++) {
            v[p] = *(const float4*)&xr[lane * 4 + p * 128];
            s  += v[p].x + v[p].y + v[p].z + v[p].w;
            s2 += v[p].x * v[p].x + v[p].y * v[p].y + v[p].z * v[p].z + v[p].w * v[p].w;
        }
        #pragma unroll
        for (int o = 16; o; o >>= 1) {
            s  += __shfl_xor_sync(0xffffffffu, s,  o);
            s2 += __shfl_xor_sync(0xffffffffu, s2, o);
        }
        const float mean = s * (1.f / E_);
        const float var  = (s2 - s * mean) * (1.f / (E_ - 1));
        const float rstd = rsqrtf(var + 1e-5f);

        fp16* orow = h1 + (size_t)row * E_;
        #pragma unroll
        for (int p = 0; p < 6; p++) {
            const int i = lane * 4 + p * 128;
            float4 c = *(const float4*)&ln1s[i];
            float4 b = *(const float4*)&ln1b[i];
            __half2 h0 = __floats2half2_rn(c.x * (v[p].x - mean) * rstd + b.x,
                                           c.y * (v[p].y - mean) * rstd + b.y);
            __half2 h1v = __floats2half2_rn(c.z * (v[p].z - mean) * rstd + b.z,
                                            c.w * (v[p].w - mean) * rstd + b.w);
            uint2 pk = make_uint2(*(uint32_t*)&h0, *(uint32_t*)&h1v);
            *(uint2*)&orow[i] = pk;
        }
    }
}

// ---------------- LayerNorm (LN2), warp-per-row -> fp16 ----------------
__global__ void __launch_bounds__(256)
ln_kernel(const float* __restrict__ x, const float* __restrict__ sc,
          const float* __restrict__ sh, fp16* __restrict__ o16)
{
    const int warp = threadIdx.x >> 5, lane = threadIdx.x & 31;
    const int row = blockIdx.x * 8 + warp;
    const float* xr = x + (size_t)row * E_;

    float4 v[6];
    float s = 0.f, s2 = 0.f;
    #pragma unroll
    for (int p = 0; p < 6; p++) {
        v[p] = *(const float4*)&xr[lane * 4 + p * 128];
        s  += v[p].x + v[p].y + v[p].z + v[p].w;
        s2 += v[p].x * v[p].x + v[p].y * v[p].y + v[p].z * v[p].z + v[p].w * v[p].w;
    }
    #pragma unroll
    for (int o = 16; o; o >>= 1) {
        s  += __shfl_xor_sync(0xffffffffu, s,  o);
        s2 += __shfl_xor_sync(0xffffffffu, s2, o);
    }
    const float mean = s * (1.f / E_);
    const float var  = (s2 - s * mean) * (1.f / (E_ - 1));
    const float rstd = rsqrtf(var + 1e-5f);

    fp16* orow = o16 + (size_t)row * E_;
    #pragma unroll
    for (int p = 0; p < 6; p++) {
        const int i = lane * 4 + p * 128;
        float4 c = *(const float4*)&sc[i];
        float4 b = *(const float4*)&sh[i];
        __half2 h0 = __floats2half2_rn(c.x * (v[p].x - mean) * rstd + b.x,
                                       c.y * (v[p].y - mean) * rstd + b.y);
        __half2 h1 = __floats2half2_rn(c.z * (v[p].z - mean) * rstd + b.z,
                                       c.w * (v[p].w - mean) * rstd + b.w);
        uint2 pk = make_uint2(*(uint32_t*)&h0, *(uint32_t*)&h1);
        *(uint2*)&orow[i] = pk;
    }
}

// ---------------- warp-MMA GEMM, templated tile-N (128 or 64) ----------------
enum { EPI_QKV = 0, EPI_BIAS_RESID = 1, EPI_BIAS_GELU = 2 };

#define KCH     64
#define ROWB    144
#define TILE_B  (128*ROWB)      // A tile: 18432
#define VROW    272

// TN=128: stage 36864, occ 2. TN=64: stage 27648, occ 3.
template<int EPI, int TN>
__global__ void __launch_bounds__(256, (TN == 64) ? 3 : 2)
mma_gemm(const fp16* __restrict__ A_g, const fp16* __restrict__ B_g,
         const float* __restrict__ bias, const float* __restrict__ resid,
         float* __restrict__ C,
         fp16* __restrict__ Qo, fp16* __restrict__ Ko, fp16* __restrict__ Vto,
         fp16* __restrict__ C16,
         int N, int K)
{
    constexpr int TILE_BB = TN * ROWB;
    constexpr int STG = TILE_B + TILE_BB;
    constexpr int MT = (TN == 128) ? 4 : 2;        // 16-row m-tiles per warp
    constexpr int WMROWS = MT * 16;

    extern __shared__ char sm[];
    const uint32_t sbase = smem_u32(sm);
    const int tid = threadIdx.x, wid = tid >> 5, lid = tid & 31;
    const int m0 = blockIdx.y * 128, n0 = blockIdx.x * TN;
    const int wm = (TN == 128) ? (wid >> 2) : (wid >> 1);
    const int wn = (TN == 128) ? (wid & 3)  : (wid & 1);

    const int lrow = tid >> 3;
    const int lcb  = (tid & 7) * 16;

    float acc[MT][4][4] = {};

    auto issue = [&](int c) {
        const int k0 = c * KCH;
        const uint32_t sb = sbase + (uint32_t)(c & 1) * STG;
        {
            const char* g = (const char*)(A_g + (size_t)(m0 + lrow) * K + k0) + lcb;
            uint32_t d = sb + lrow * ROWB + lcb;
            #pragma unroll
            for (int i = 0; i < 4; i++)
                cpasync16(d + i * 32 * ROWB, g + (size_t)i * 32 * K * 2);
        }
        {
            const char* g = (const char*)(B_g + (size_t)(n0 + lrow) * K + k0) + lcb;
            uint32_t d = sb + TILE_B + lrow * ROWB + lcb;
            #pragma unroll
            for (int i = 0; i < TN / 32; i++)
                cpasync16(d + i * 32 * ROWB, g + (size_t)i * 32 * K * 2);
        }
        asm volatile("cp.async.commit_group;");
    };

    const int NC = K / KCH;
    issue(0);

    const int am = (lid >> 3);
    const uint32_t aRow = wm * WMROWS + (am & 1) * 8 + (lid & 7);
    const uint32_t aColH = (am >> 1) * 16;
    const uint32_t bRowBase = wn * 32 + (lid & 7);
    const uint32_t bNt = (am >> 1);
    const uint32_t bColH = (am & 1) * 16;

    for (int c = 0; c < NC; c++) {
        if (c + 1 < NC) { issue(c + 1); asm volatile("cp.async.wait_group 1;"); }
        else            { asm volatile("cp.async.wait_group 0;"); }
        __syncthreads();

        const uint32_t sb = sbase + (uint32_t)(c & 1) * STG;
        const uint32_t aB = sb, bB = sb + TILE_B;

        #pragma unroll
        for (int ks = 0; ks < 4; ks++) {
            uint32_t bh[2][4];
            #pragma unroll
            for (int p = 0; p < 2; p++) {
                uint32_t row = bRowBase + (p * 2 + bNt) * 8;
                uint32_t off = row * ROWB + ks * 32 + bColH;
                ldsm4(bh[p], bB + off);
            }
            #pragma unroll
            for (int mt = 0; mt < MT; mt++) {
                uint32_t ah[4];
                uint32_t off = (aRow + mt * 16) * ROWB + ks * 32 + aColH;
                ldsm4(ah, aB + off);
                #pragma unroll
                for (int nt = 0; nt < 4; nt++) {
                    const int p = nt >> 1, q = (nt & 1) * 2;
                    mma_f16(acc[mt][nt], ah, bh[p][q], bh[p][q + 1]);
                }
            }
        }
        __syncthreads();
    }

    const bool isV = (EPI == EPI_QKV) && (n0 >= 2 * E_);

    #pragma unroll
    for (int mt = 0; mt < MT; mt++) {
        #pragma unroll
        for (int nt = 0; nt < 4; nt++) {
            const int r0 = m0 + wm * WMROWS + mt * 16 + (lid >> 2);
            const int cc = n0 + wn * 32 + nt * 8 + (lid & 3) * 2;
            #pragma unroll
            for (int hh = 0; hh < 2; hh++) {
                const int r = r0 + hh * 8;
                float v0 = acc[mt][nt][hh * 2], v1 = acc[mt][nt][hh * 2 + 1];
                if (EPI == EPI_QKV) {
                    if (isV) {
                        const int rl = r - m0;
                        const int cl = cc - n0;
                        *(fp16*)(sm + cl * VROW + rl * 2)       = __float2half_rn(v0);
                        *(fp16*)(sm + (cl + 1) * VROW + rl * 2) = __float2half_rn(v1);
                    } else {
                        const int bb = r >> 11, tt = r & (T_ - 1);
                        int which = (cc >= E_) ? 1 : 0;
                        int nn = cc - which * E_;
                        int hx = nn >> 6, d = nn & 63;
                        size_t o = ((size_t)(bb * H_ + hx) * T_ + tt) * D_ + d;
                        fp16* dst = (which == 0) ? Qo : Ko;
                        *(__half2*)&dst[o] = __floats2half2_rn(v0, v1);
                    }
                } else if (EPI == EPI_BIAS_RESID) {
                    size_t o = (size_t)r * N + cc;
                    float2 bs = *(const float2*)&bias[cc];
                    float2 rs = *(const float2*)&resid[o];
                    *(float2*)&C[o] = make_float2(v0 + bs.x + rs.x, v1 + bs.y + rs.y);
                } else {
                    size_t o = (size_t)r * N + cc;
                    float2 bs = *(const float2*)&bias[cc];
                    float vv[2] = {v0 + bs.x, v1 + bs.y};
                    #pragma unroll
                    for (int j = 0; j < 2; j++) {
                        float v = vv[j];
                        float u = 0.7978845608028654f * (v + 0.044715f * v * v * v);
                        vv[j] = 0.5f * v * (1.f + tanh_fast(u));
                    }
                    *(__half2*)&C16[o] = __floats2half2_rn(vv[0], vv[1]);
                }
            }
        }
    }

    if (isV) {
        __syncthreads();
        const int bb = m0 >> 11, tt0 = m0 & (T_ - 1);
        const int nh = n0 - 2 * E_;
        #pragma unroll
        for (int it = 0; it < 8; it++) {
            const int nl = it * 16 + (tid >> 4);
            const int hx = (nh + nl) >> 6, d = (nh + nl) & 63;
            const uint4 v = *(const uint4*)(sm + nl * VROW + (tid & 15) * 16);
            *(uint4*)&Vto[((size_t)(bb * H_ + hx) * D_ + d) * T_ + tt0 + (tid & 15) * 8] = v;
        }
    }
}

#define GEMM_SMEM128 (2*(TILE_B + 128*ROWB))   // 73728
#define GEMM_SMEM64  (2*(TILE_B + 64*ROWB))    // 55296

// ---------------- flash attention: 64q x 128kv tiles, 128 threads, occ=2 ----------------
#define FROWK 144
#define FROWV 272
#define FQ    0
#define FSTG0 9216
#define FSTGB 35840
#define FA3_SMEM (9216 + 2*FSTGB)   // 80896

__global__ void __launch_bounds__(128, 2)
flash_attn3(const fp16* __restrict__ Q_g, const fp16* __restrict__ K_g,
            const fp16* __restrict__ Vt_g, fp16* __restrict__ ctx)
{
    extern __shared__ char sm[];
    const uint32_t sb = smem_u32(sm);
    const int tid = threadIdx.x, wid = tid >> 5, lid = tid & 31;
    const int bh = blockIdx.y;
    const int qt = (gridDim.x - 1) - blockIdx.x;
    const int q0 = qt * 64;
    const int ktmax = qt >> 1;

    const fp16* Qb = Q_g + (size_t)bh * T_ * D_;
    const fp16* Kb = K_g + (size_t)bh * T_ * D_;
    const fp16* Vb = Vt_g + (size_t)bh * D_ * T_;

    {
        const int row = tid >> 1, half = tid & 1;
        const char* g = (const char*)(Qb + (size_t)(q0 + row) * D_ + half * 32);
        uint32_t d = sb + FQ + row * FROWK + half * 64;
        #pragma unroll
        for (int i = 0; i < 4; i++) cpasync16(d + i * 16, g + i * 16);
    }

    auto issueKV = [&](int stage, int kvt) {
        const int kv0 = kvt * 128;
        const uint32_t s0 = sb + FSTG0 + (uint32_t)stage * FSTGB;
        #pragma unroll
        for (int it = 0; it < 2; it++) {
            const int row = (tid >> 1) + it * 64;
            const int half = tid & 1;
            const char* g = (const char*)(Kb + (size_t)(kv0 + row) * D_ + half * 32);
            uint32_t d = s0 + row * FROWK + half * 64;
            #pragma unroll
            for (int i = 0; i < 4; i++) cpasync16(d + i * 16, g + i * 16);
        }
        #pragma unroll
        for (int it = 0; it < 2; it++) {
            const int row = (tid >> 2) + it * 32;
            const int qtc = tid & 3;
            const char* g = (const char*)(Vb + (size_t)row * T_ + kv0 + qtc * 32);
            uint32_t d = s0 + 18432 + row * FROWV + qtc * 64;
            #pragma unroll
            for (int i = 0; i < 4; i++) cpasync16(d + i * 16, g + i * 16);
        }
        asm volatile("cp.async.commit_group;");
    };

    issueKV(0, 0);

    const int am = lid >> 3;
    uint32_t qf[4][4];
    float m_[2] = {-1e30f, -1e30f}, l_[2] = {0.f, 0.f};
    float oacc[8][4] = {};

    const int r0g = q0 + wid * 16 + (lid >> 2);
    const int c0l = (lid & 3) * 2;

    for (int kt = 0; kt <= ktmax; kt++) {
        if (kt + 1 <= ktmax) { issueKV((kt + 1) & 1, kt + 1); asm volatile("cp.async.wait_group 1;"); }
        else                 { asm volatile("cp.async.wait_group 0;"); }
        __syncthreads();

        if (kt == 0) {
            const uint32_t rowq = wid * 16 + (am & 1) * 8 + (lid & 7);
            #pragma unroll
            for (int ks = 0; ks < 4; ks++) {
                uint32_t off = rowq * FROWK + ks * 32 + (am >> 1) * 16;
                ldsm4(qf[ks], sb + FQ + off);
            }
        }

        const uint32_t stg = sb + FSTG0 + (uint32_t)(kt & 1) * FSTGB;

        float sacc[16][4] = {};
        #pragma unroll
        for (int ks = 0; ks < 4; ks++) {
            #pragma unroll
            for (int ntp = 0; ntp < 8; ntp++) {
                uint32_t kh4[4];
                uint32_t off = (uint32_t)(ntp * 16 + ((lid >> 4) * 8) + (lid & 7)) * FROWK
                             + ks * 32 + ((lid >> 3) & 1) * 16;
                ldsm4(kh4, stg + off);
                mma_f16(sacc[2 * ntp],     qf[ks], kh4[0], kh4[1]);
                mma_f16(sacc[2 * ntp + 1], qf[ks], kh4[2], kh4[3]);
            }
        }

        const bool diag = (kt == ktmax);
        float mx0 = -1e30f, mx1 = -1e30f;
        #pragma unroll
        for (int nt = 0; nt < 16; nt++) {
            #pragma unroll
            for (int j = 0; j < 2; j++) {
                float s = sacc[nt][j] * 0.125f;
                if (diag && (kt * 128 + nt * 8 + c0l + j) > r0g) s = -1e30f;
                sacc[nt][j] = s; mx0 = fmaxf(mx0, s);
            }
            #pragma unroll
            for (int j = 2; j < 4; j++) {
                float s = sacc[nt][j] * 0.125f;
                if (diag && (kt * 128 + nt * 8 + c0l + j - 2) > r0g + 8) s = -1e30f;
                sacc[nt][j] = s; mx1 = fmaxf(mx1, s);
            }
        }
        #pragma unroll
        for (int o = 1; o < 4; o <<= 1) {
            mx0 = fmaxf(mx0, __shfl_xor_sync(0xffffffffu, mx0, o));
            mx1 = fmaxf(mx1, __shfl_xor_sync(0xffffffffu, mx1, o));
        }
        float mn0 = fmaxf(m_[0], mx0), mn1 = fmaxf(m_[1], mx1);
        float cr0 = __expf(m_[0] - mn0), cr1 = __expf(m_[1] - mn1);
        float sum0 = 0.f, sum1 = 0.f;
        #pragma unroll
        for (int nt = 0; nt < 16; nt++) {
            float p0 = __expf(sacc[nt][0] - mn0), p1 = __expf(sacc[nt][1] - mn0);
            float p2 = __expf(sacc[nt][2] - mn1), p3 = __expf(sacc[nt][3] - mn1);
            sacc[nt][0] = p0; sacc[nt][1] = p1; sacc[nt][2] = p2; sacc[nt][3] = p3;
            sum0 += p0 + p1; sum1 += p2 + p3;
        }
        #pragma unroll
        for (int o = 1; o < 4; o <<= 1) {
            sum0 += __shfl_xor_sync(0xffffffffu, sum0, o);
            sum1 += __shfl_xor_sync(0xffffffffu, sum1, o);
        }
        l_[0] = l_[0] * cr0 + sum0; l_[1] = l_[1] * cr1 + sum1;
        m_[0] = mn0; m_[1] = mn1;
        #pragma unroll
        for (int d = 0; d < 8; d++) {
            oacc[d][0] *= cr0; oacc[d][1] *= cr0;
            oacc[d][2] *= cr1; oacc[d][3] *= cr1;
        }

        #pragma unroll
        for (int kvt = 0; kvt < 8; kvt++) {
            uint32_t pa[4];
            pa[0] = packh(sacc[2 * kvt][0],     sacc[2 * kvt][1]);
            pa[1] = packh(sacc[2 * kvt][2],     sacc[2 * kvt][3]);
            pa[2] = packh(sacc[2 * kvt + 1][0], sacc[2 * kvt + 1][1]);
            pa[3] = packh(sacc[2 * kvt + 1][2], sacc[2 * kvt + 1][3]);

            #pragma unroll
            for (int ntp = 0; ntp < 4; ntp++) {
                uint32_t vh4[4];
                uint32_t off = (uint32_t)(ntp * 16 + ((lid >> 4) * 8) + (lid & 7)) * FROWV
                             + kvt * 32 + ((lid >> 3) & 1) * 16;
                ldsm4(vh4, stg + 18432 + off);
                mma_f16(oacc[2 * ntp],     pa, vh4[0], vh4[1]);
                mma_f16(oacc[2 * ntp + 1], pa, vh4[2], vh4[3]);
            }
        }
        __syncthreads();
    }

    const int b = bh / H_, h = bh - b * H_;
    float inv0 = 1.f / l_[0], inv1 = 1.f / l_[1];
    #pragma unroll
    for (int nt = 0; nt < 8; nt++) {
        const int d = nt * 8 + c0l;
        {
            size_t o = ((size_t)(b * T_ + r0g)) * E_ + h * D_ + d;
            *(__half2*)&ctx[o] = __floats2half2_rn(oacc[nt][0] * inv0, oacc[nt][1] * inv0);
        }
        {
            size_t o = ((size_t)(b * T_ + r0g + 8)) * E_ + h * D_ + d;
            *(__half2*)&ctx[o] = __floats2half2_rn(oacc[nt][2] * inv1, oacc[nt][3] * inv1);
        }
    }
}

// ---------------- launch ----------------
extern "C" void kernel_launch(void* const* d_in, const int* in_sizes, int n_in,
                              void* d_out, int out_size)
{
    const float* x    = (const float*)d_in[0];
    const float* wq   = (const float*)d_in[1];
    const float* wk   = (const float*)d_in[2];
    const float* wv   = (const float*)d_in[3];
    const float* wo   = (const float*)d_in[4];
    const float* bo   = (const float*)d_in[5];
    const float* ln1s = (const float*)d_in[6];
    const float* ln1b = (const float*)d_in[7];
    const float* ln2s = (const float*)d_in[8];
    const float* ln2b = (const float*)d_in[9];
    const float* w1   = (const float*)d_in[10];
    const float* b1   = (const float*)d_in[11];
    const float* w2   = (const float*)d_in[12];
    const float* b2   = (const float*)d_in[13];
    float* out = (float*)d_out;

    float *x2;
    fp16 *h1, *q, *k, *vt, *ctx, *h2, *mid;
    fp16 *wqkvT, *woT, *w1T, *w2T;
    cudaGetSymbolAddress((void**)&x2,  g_x2);
    cudaGetSymbolAddress((void**)&h1,  g_h1);
    cudaGetSymbolAddress((void**)&q,   g_q);
    cudaGetSymbolAddress((void**)&k,   g_k);
    cudaGetSymbolAddress((void**)&vt,  g_vt);
    cudaGetSymbolAddress((void**)&ctx, g_ctx);
    cudaGetSymbolAddress((void**)&h2,  g_h2);
    cudaGetSymbolAddress((void**)&mid, g_mid);
    cudaGetSymbolAddress((void**)&wqkvT, g_wqkvT);
    cudaGetSymbolAddress((void**)&woT, g_woT);
    cudaGetSymbolAddress((void**)&w1T, g_w1T);
    cudaGetSymbolAddress((void**)&w2T, g_w2T);

    cudaFuncSetAttribute(flash_attn3, cudaFuncAttributeMaxDynamicSharedMemorySize, FA3_SMEM);
    cudaFuncSetAttribute(mma_gemm<EPI_QKV, 128>,       cudaFuncAttributeMaxDynamicSharedMemorySize, GEMM_SMEM128);
    cudaFuncSetAttribute(mma_gemm<EPI_BIAS_RESID, 64>, cudaFuncAttributeMaxDynamicSharedMemorySize, GEMM_SMEM64);
    cudaFuncSetAttribute(mma_gemm<EPI_BIAS_GELU, 128>, cudaFuncAttributeMaxDynamicSharedMemorySize, GEMM_SMEM128);

    // fused preamble: all weight conversions + LN1
    prep_kernel<<<NB_PREP, 256>>>(x, ln1s, ln1b, wq, wk, wv, wo, w1, w2,
                                  h1, wqkvT, woT, w1T, w2T);

    // fused QKV -> Q, K, Vt (fp16; V staged via smem transpose)
    mma_gemm<EPI_QKV, 128><<<dim3(QKVN/128, M_/128), 256, GEMM_SMEM128>>>(
        h1, wqkvT, nullptr, nullptr, nullptr, q, k, vt, nullptr, QKVN, E_);

    // flash attention (64q tiles, occ=2) -> ctx fp16
    flash_attn3<<<dim3(T_/64, BH_), 128, FA3_SMEM>>>(q, k, vt, ctx);

    // proj + bias + resid -> x2 (TN=64: 384 CTAs, occ=3)
    mma_gemm<EPI_BIAS_RESID, 64><<<dim3(E_/64, M_/128), 256, GEMM_SMEM64>>>(
        ctx, woT, bo, x, x2, nullptr, nullptr, nullptr, nullptr, E_, E_);

    // LN2 -> h2 (fp16)
    ln_kernel<<<M_/8, 256>>>(x2, ln2s, ln2b, h2);

    // MLP1 (gelu) -> mid fp16
    mma_gemm<EPI_BIAS_GELU, 128><<<dim3(FF_/128, M_/128), 256, GEMM_SMEM128>>>(
        h2, w1T, b1, nullptr, nullptr, nullptr, nullptr, nullptr, mid, FF_, E_);

    // MLP2 + bias + resid -> out (TN=64: 384 CTAs, occ=3)
    mma_gemm<EPI_BIAS_RESID, 64><<<dim3(E_/64, M_/128), 256, GEMM_SMEM64>>>(
        mid, w2T, b2, x2, out, nullptr, nullptr, nullptr, nullptr, E_, FF_);
}